// round 2
// baseline (speedup 1.0000x reference)
#include <cuda_runtime.h>
#include <math.h>

#define NB   4
#define NTOK 4096
#define NC   192
#define NHD  64
#define MAXM 3969

static const float ATT_SCALE = 0.07216878364870323f; // 192^-0.5

// ---------------- scratch (__device__ globals: allocation-free rule) ----------
__device__ float g_ximg[NB * NC * NTOK + 128];          // (B,C,4096) + OOB pad
__device__ float g_q[NB * NTOK * NC];                   // q projection
__device__ float g_wr[64 * NC * NC];                    // reordered conv weights
__device__ float g_t[2 * NB * MAXM * NC];               // conv partials / t
__device__ float g_kv[NB * MAXM * 128];                 // k (0:64) v (64:128)
__device__ float g_vp[NB * MAXM * 64];                  // v + depthwise conv
__device__ float g_S[(size_t)NB * NTOK * MAXM];         // attention logits/probs
__device__ float g_xcat[NB * NTOK * NC];                // concat of branch outputs

// ---------------- helpers ------------------------------------------------------
__device__ __forceinline__ float warpSum(float v) {
#pragma unroll
    for (int o = 16; o; o >>= 1) v += __shfl_xor_sync(0xffffffffu, v, o);
    return v;
}
__device__ __forceinline__ float warpMax(float v) {
#pragma unroll
    for (int o = 16; o; o >>= 1) v = fmaxf(v, __shfl_xor_sync(0xffffffffu, v, o));
    return v;
}

// ---------------- transpose x (B,N,C) -> (B,C,N) -------------------------------
__global__ void transpose_kernel(const float* __restrict__ x, float* __restrict__ ximg) {
    __shared__ float tile[32][33];
    int b = blockIdx.z;
    int p0 = blockIdx.x << 5, c0 = blockIdx.y << 5;
    int tx = threadIdx.x, ty = threadIdx.y;
#pragma unroll
    for (int i = ty; i < 32; i += 8)
        tile[i][tx] = x[((size_t)b * NTOK + p0 + i) * NC + c0 + tx];
    __syncthreads();
#pragma unroll
    for (int i = ty; i < 32; i += 8)
        ximg[((size_t)b * NC + c0 + i) * NTOK + p0 + tx] = tile[tx][i];
}

// ---------------- reorder sr weights (co,ci,ky,kx) -> [tap][ci][co] ------------
__global__ void reorder_w_kernel(const float* __restrict__ w, float* __restrict__ wr, int k2) {
    int idx = blockIdx.x * 256 + threadIdx.x;
    int total = k2 * NC * NC;
    if (idx >= total) return;
    int co = idx % NC;
    int ci = (idx / NC) % NC;
    int tap = idx / (NC * NC);
    wr[idx] = w[((size_t)co * NC + ci) * k2 + tap];
}

// ---------------- stride-1 VALID conv 192->192 as shifted rank-updates ---------
// grid: (side, B, 2 ci-halves); block 256. Output tile: 192 co x 64 px (one oy row).
__global__ void __launch_bounds__(256) sr_conv_kernel(
    const float* __restrict__ ximg, const float* __restrict__ wr,
    const float* __restrict__ bias, float* __restrict__ out,
    int k, int side, int m)
{
    __shared__ float Wsm[16][192];
    __shared__ float Xsm[16][64];
    const size_t PART = (size_t)NB * MAXM * NC;
    int tid = threadIdx.x;
    int pxg = tid & 7;    // 8 px-groups of 8 px
    int cog = tid >> 3;   // 32 co-groups of 6 co
    int oy = blockIdx.x;
    int b  = blockIdx.y;
    int ci0 = blockIdx.z * 96;
    out += (size_t)blockIdx.z * PART;

    float acc[6][8];
#pragma unroll
    for (int i = 0; i < 6; i++)
#pragma unroll
        for (int j = 0; j < 8; j++) acc[i][j] = 0.f;

    const float* xb = ximg + (size_t)b * NC * NTOK;
    int k2 = k * k;
    for (int tap = 0; tap < k2; tap++) {
        int dy = tap / k, dx = tap - dy * k;
        const float* xrow = xb + (oy + dy) * 64 + dx;
        const float* wtap = wr + (size_t)tap * NC * NC;
        for (int cc = 0; cc < 96; cc += 16) {
            int cbase = ci0 + cc;
            __syncthreads();
#pragma unroll
            for (int j = 0; j < 12; j++) {
                int idx = tid + j * 256;
                int co = idx % 192, ci = idx / 192;
                Wsm[ci][co] = wtap[(size_t)(cbase + ci) * 192 + co];
            }
#pragma unroll
            for (int j = 0; j < 4; j++) {
                int idx = tid + j * 256;
                int px = idx & 63, ci = idx >> 6;
                Xsm[ci][px] = xrow[(size_t)(cbase + ci) * NTOK + px];
            }
            __syncthreads();
#pragma unroll
            for (int ci = 0; ci < 16; ci++) {
                float xr[8];
#pragma unroll
                for (int j = 0; j < 8; j++) xr[j] = Xsm[ci][pxg * 8 + j];
#pragma unroll
                for (int i = 0; i < 6; i++) {
                    float wv = Wsm[ci][cog * 6 + i];
#pragma unroll
                    for (int j = 0; j < 8; j++) acc[i][j] = fmaf(wv, xr[j], acc[i][j]);
                }
            }
        }
    }
    size_t base = ((size_t)b * m + (size_t)oy * side) * NC;
#pragma unroll
    for (int j = 0; j < 8; j++) {
        int ox = pxg * 8 + j;
        if (ox < side) {
            float* op = out + base + (size_t)ox * NC + cog * 6;
#pragma unroll
            for (int i = 0; i < 6; i++) {
                float bb = (ci0 == 0) ? bias[cog * 6 + i] : 0.f;
                op[i] = acc[i][j] + bb;
            }
        }
    }
}

// ---------------- LayerNorm + exact GELU over C=192 (sums conv partials) -------
__global__ void ln_gelu_kernel(float* __restrict__ t, const float* __restrict__ g,
                               const float* __restrict__ bb) {
    const size_t PART = (size_t)NB * MAXM * NC;
    size_t row = blockIdx.x;
    int tid = threadIdx.x;
    float v = t[row * NC + tid] + t[PART + row * NC + tid];
    __shared__ float sm[6];
    int lane = tid & 31, w = tid >> 5;
    float s = warpSum(v);
    if (lane == 0) sm[w] = s;
    __syncthreads();
    float mean = 0.f;
#pragma unroll
    for (int i = 0; i < 6; i++) mean += sm[i];
    mean *= (1.0f / 192.0f);
    float d = v - mean;
    __syncthreads();
    s = warpSum(d * d);
    if (lane == 0) sm[w] = s;
    __syncthreads();
    float var = 0.f;
#pragma unroll
    for (int i = 0; i < 6; i++) var += sm[i];
    var *= (1.0f / 192.0f);
    float y = d * rsqrtf(var + 1e-5f) * g[tid] + bb[tid];
    t[row * NC + tid] = y * normcdff(y);
}

// ---------------- generic NT GEMM: C = scale*(A @ W^T) + bias ------------------
// A: MxK row-major (lda), W: NxK row-major (ldw). Tile 128x64xBK16, 256 thr.
__global__ void __launch_bounds__(256) gemm_nt(
    const float* __restrict__ A, long long sA, int lda,
    const float* __restrict__ W, long long sW, int ldw,
    const float* __restrict__ bias,
    float* __restrict__ C, long long sC, int ldc,
    int M, int Nn, int K, float scale)
{
    __shared__ float As[16][132];
    __shared__ float Ws[16][68];
    int bz = blockIdx.z;
    const float* Ab = A + sA * bz;
    const float* Wb = W + sW * bz;
    float* Cb = C + sC * bz;
    int n0 = blockIdx.x * 64, m0 = blockIdx.y * 128;
    int tid = threadIdx.x;
    int tx = tid & 15, ty = tid >> 4;
    float acc[8][4];
#pragma unroll
    for (int i = 0; i < 8; i++)
#pragma unroll
        for (int j = 0; j < 4; j++) acc[i][j] = 0.f;

    for (int k0 = 0; k0 < K; k0 += 16) {
#pragma unroll
        for (int j = 0; j < 8; j++) {
            int idx = tid + j * 256;
            int kk = idx & 15, mm = idx >> 4;
            int gm = m0 + mm, gk = k0 + kk;
            As[kk][mm] = (gm < M && gk < K) ? Ab[(size_t)gm * lda + gk] : 0.f;
        }
#pragma unroll
        for (int j = 0; j < 4; j++) {
            int idx = tid + j * 256;
            int kk = idx & 15, nn = idx >> 4;
            int gn = n0 + nn, gk = k0 + kk;
            Ws[kk][nn] = (gn < Nn && gk < K) ? Wb[(size_t)gn * ldw + gk] : 0.f;
        }
        __syncthreads();
#pragma unroll
        for (int kk = 0; kk < 16; kk++) {
            float a[8], w[4];
#pragma unroll
            for (int i = 0; i < 8; i++) a[i] = As[kk][ty * 8 + i];
#pragma unroll
            for (int j = 0; j < 4; j++) w[j] = Ws[kk][tx * 4 + j];
#pragma unroll
            for (int i = 0; i < 8; i++)
#pragma unroll
                for (int j = 0; j < 4; j++) acc[i][j] = fmaf(a[i], w[j], acc[i][j]);
        }
        __syncthreads();
    }
#pragma unroll
    for (int i = 0; i < 8; i++) {
        int gm = m0 + ty * 8 + i;
        if (gm >= M) continue;
#pragma unroll
        for (int j = 0; j < 4; j++) {
            int gn = n0 + tx * 4 + j;
            if (gn < Nn) {
                float v = acc[i][j] * scale;
                if (bias) v += bias[gn];
                Cb[(size_t)gm * ldc + gn] = v;
            }
        }
    }
}

// ---------------- generic NN GEMM: C = A(MxK) @ Bm(KxN) ------------------------
__global__ void __launch_bounds__(256) gemm_nn(
    const float* __restrict__ A, long long sA, int lda,
    const float* __restrict__ Bm, long long sB, int ldb,
    float* __restrict__ C, long long sC, int ldc,
    int M, int Nn, int K)
{
    __shared__ float As[16][132];
    __shared__ float Ws[16][68];
    int bz = blockIdx.z;
    const float* Ab = A + sA * bz;
    const float* Bb = Bm + sB * bz;
    float* Cb = C + sC * bz;
    int n0 = blockIdx.x * 64, m0 = blockIdx.y * 128;
    int tid = threadIdx.x;
    int tx = tid & 15, ty = tid >> 4;
    float acc[8][4];
#pragma unroll
    for (int i = 0; i < 8; i++)
#pragma unroll
        for (int j = 0; j < 4; j++) acc[i][j] = 0.f;

    for (int k0 = 0; k0 < K; k0 += 16) {
#pragma unroll
        for (int j = 0; j < 8; j++) {
            int idx = tid + j * 256;
            int kk = idx & 15, mm = idx >> 4;
            int gm = m0 + mm, gk = k0 + kk;
            As[kk][mm] = (gm < M && gk < K) ? Ab[(size_t)gm * lda + gk] : 0.f;
        }
#pragma unroll
        for (int j = 0; j < 4; j++) {
            int idx = tid + j * 256;
            int nn = idx & 63, kk = idx >> 6;
            int gn = n0 + nn, gk = k0 + kk;
            Ws[kk][nn] = (gk < K && gn < Nn) ? Bb[(size_t)gk * ldb + gn] : 0.f;
        }
        __syncthreads();
#pragma unroll
        for (int kk = 0; kk < 16; kk++) {
            float a[8], w[4];
#pragma unroll
            for (int i = 0; i < 8; i++) a[i] = As[kk][ty * 8 + i];
#pragma unroll
            for (int j = 0; j < 4; j++) w[j] = Ws[kk][tx * 4 + j];
#pragma unroll
            for (int i = 0; i < 8; i++)
#pragma unroll
                for (int j = 0; j < 4; j++) acc[i][j] = fmaf(a[i], w[j], acc[i][j]);
        }
        __syncthreads();
    }
#pragma unroll
    for (int i = 0; i < 8; i++) {
        int gm = m0 + ty * 8 + i;
        if (gm >= M) continue;
#pragma unroll
        for (int j = 0; j < 4; j++) {
            int gn = n0 + tx * 4 + j;
            if (gn < Nn) Cb[(size_t)gm * ldc + gn] = acc[i][j];
        }
    }
}

// ---------------- depthwise 3x3 (same pad) on v, residual add ------------------
__global__ void dwconv_kernel(const float* __restrict__ kv, const float* __restrict__ lw,
                              const float* __restrict__ lb, float* __restrict__ vp,
                              int side, int m)
{
    long long idx = (long long)blockIdx.x * 256 + threadIdx.x;
    long long total = (long long)NB * m * 64;
    if (idx >= total) return;
    int hd = (int)(idx & 63);
    long long pm = idx >> 6;
    int p = (int)(pm % m);
    int b = (int)(pm / m);
    int y = p / side, x = p % side;
    const float* vbase = kv + (size_t)b * m * 128 + 64 + hd;
    float s = lb[hd];
#pragma unroll
    for (int dy = 0; dy < 3; dy++) {
        int yy = y + dy - 1;
        if (yy < 0 || yy >= side) continue;
#pragma unroll
        for (int dx = 0; dx < 3; dx++) {
            int xx = x + dx - 1;
            if (xx < 0 || xx >= side) continue;
            s += lw[hd * 9 + dy * 3 + dx] * vbase[(size_t)(yy * side + xx) * 128];
        }
    }
    vp[idx] = vbase[(size_t)p * 128] + s;
}

// ---------------- row softmax over m -------------------------------------------
__global__ void softmax_kernel(float* __restrict__ S, int mcols) {
    size_t row = blockIdx.x;
    float* r = S + row * (size_t)mcols;
    int tid = threadIdx.x;
    float lv[16];
    int cnt = 0;
    float mx = -1e30f;
    for (int j = tid; j < mcols; j += 256) {
        float v = r[j];
        lv[cnt++] = v;
        if (v > mx) mx = v;
    }
    __shared__ float sm[8];
    int lane = tid & 31, w = tid >> 5;
    float tmp = warpMax(mx);
    if (lane == 0) sm[w] = tmp;
    __syncthreads();
    mx = -1e30f;
#pragma unroll
    for (int i = 0; i < 8; i++) mx = fmaxf(mx, sm[i]);
    float sum = 0.f;
    for (int i = 0; i < cnt; i++) {
        float e = __expf(lv[i] - mx);
        lv[i] = e;
        sum += e;
    }
    __syncthreads();
    tmp = warpSum(sum);
    if (lane == 0) sm[w] = tmp;
    __syncthreads();
    sum = 0.f;
#pragma unroll
    for (int i = 0; i < 8; i++) sum += sm[i];
    float inv = 1.f / sum;
    cnt = 0;
    for (int j = tid; j < mcols; j += 256) r[j] = lv[cnt++] * inv;
}

// ---------------- host orchestration -------------------------------------------
extern "C" void kernel_launch(void* const* d_in, const int* in_sizes, int n_in,
                              void* d_out, int out_size)
{
    (void)in_sizes; (void)n_in; (void)out_size;
    const float* x    = (const float*)d_in[0];
    const float* q_w  = (const float*)d_in[1];
    const float* q_b  = (const float*)d_in[2];
    const float* kv_w = (const float*)d_in[3];
    const float* kv_b = (const float*)d_in[4];
    const float* sr_w[3] = {(const float*)d_in[5], (const float*)d_in[7], (const float*)d_in[9]};
    const float* sr_b[3] = {(const float*)d_in[6], (const float*)d_in[8], (const float*)d_in[10]};
    const float* ln_g[3] = {(const float*)d_in[11], (const float*)d_in[13], (const float*)d_in[15]};
    const float* ln_b[3] = {(const float*)d_in[12], (const float*)d_in[14], (const float*)d_in[16]};
    const float* lc_w[3] = {(const float*)d_in[17], (const float*)d_in[19], (const float*)d_in[21]};
    const float* lc_b[3] = {(const float*)d_in[18], (const float*)d_in[20], (const float*)d_in[22]};
    const float* nn1_w = (const float*)d_in[23];
    const float* nn1_b = (const float*)d_in[24];
    float* out = (float*)d_out;

    float *p_ximg, *p_q, *p_wr, *p_t, *p_kv, *p_vp, *p_S, *p_xcat;
    cudaGetSymbolAddress((void**)&p_ximg, g_ximg);
    cudaGetSymbolAddress((void**)&p_q,    g_q);
    cudaGetSymbolAddress((void**)&p_wr,   g_wr);
    cudaGetSymbolAddress((void**)&p_t,    g_t);
    cudaGetSymbolAddress((void**)&p_kv,   g_kv);
    cudaGetSymbolAddress((void**)&p_vp,   g_vp);
    cudaGetSymbolAddress((void**)&p_S,    g_S);
    cudaGetSymbolAddress((void**)&p_xcat, g_xcat);

    // x -> (B, C, 4096)
    transpose_kernel<<<dim3(128, 6, NB), dim3(32, 8)>>>(x, p_ximg);

    // q projection: (16384,192) = x @ q_w^T + q_b
    gemm_nt<<<dim3(3, 128, 1), 256>>>(x, 0, NC, q_w, 0, NC, q_b,
                                      p_q, 0, NC, NB * NTOK, NC, NC, 1.f);

    const int KS[3] = {8, 4, 2};
    for (int h = 0; h < 3; h++) {
        int k = KS[h];
        int side = 64 - k + 1;
        int m = side * side;
        int k2 = k * k;

        reorder_w_kernel<<<(k2 * NC * NC + 255) / 256, 256>>>(sr_w[h], p_wr, k2);
        sr_conv_kernel<<<dim3(side, NB, 2), 256>>>(p_ximg, p_wr, sr_b[h], p_t, k, side, m);
        ln_gelu_kernel<<<NB * m, 192>>>(p_t, ln_g[h], ln_b[h]);

        // kv = t @ kv_w^T + kv_b (first 128 output cols: k then v)
        gemm_nt<<<dim3(2, (NB * m + 127) / 128, 1), 256>>>(
            p_t, 0, NC, kv_w, 0, NC, kv_b, p_kv, 0, 128, NB * m, 128, NC, 1.f);

        // v' = v + depthwise3x3(v)
        dwconv_kernel<<<(int)(((long long)NB * m * 64 + 255) / 256), 256>>>(
            p_kv, lc_w[h], lc_b[h], p_vp, side, m);

        // S = SCALE * q_h @ k^T  (batched over B)
        gemm_nt<<<dim3((m + 63) / 64, NTOK / 128, NB), 256>>>(
            p_q + h * 64, (long long)NTOK * NC, NC,
            p_kv, (long long)m * 128, 128, nullptr,
            p_S, (long long)NTOK * m, m, NTOK, m, 64, ATT_SCALE);

        softmax_kernel<<<NB * NTOK, 256>>>(p_S, m);

        // xcat[:, h*64:(h+1)*64] = P @ v'
        gemm_nn<<<dim3(1, NTOK / 128, NB), 256>>>(
            p_S, (long long)NTOK * m, m,
            p_vp, (long long)m * 64, 64,
            p_xcat + h * 64, (long long)NTOK * NC, NC, NTOK, 64, m);
    }

    // final projection
    gemm_nt<<<dim3(3, 128, 1), 256>>>(p_xcat, 0, NC, nn1_w, 0, NC, nn1_b,
                                      out, 0, NC, NB * NTOK, NC, NC, 1.f);
}

// round 4
// speedup vs baseline: 1.2883x; 1.2883x over previous
#include <cuda_runtime.h>
#include <cuda_bf16.h>
#include <math.h>
#include <stdint.h>

#define NB   4
#define NTOK 4096
#define NC   192
#define MAXM 3969
#define PN   104                         // B smem word pitch (conflict-free)

static const float ATT_SCALE = 0.07216878364870323f; // 192^-0.5

// ---------------- scratch -------------------------------------------------------
__device__ float g_q[NB * NTOK * NC];
__device__ float g_t[(size_t)NB * MAXM * NC];
__device__ float g_kv[NB * MAXM * 128];
__device__ float g_vp[NB * MAXM * 64];
__device__ float g_S[(size_t)NB * NTOK * MAXM];
__device__ float g_xcat[NB * NTOK * NC];
__device__ __nv_bfloat16 g_xh[NB * NTOK * NC];
__device__ __nv_bfloat16 g_xl[NB * NTOK * NC];
__device__ uint32_t g_wpack[768 * 32 * PN];     // 64 taps * 12 images * 3328 words

// ---------------- warp helpers ---------------------------------------------------
__device__ __forceinline__ float warpSum(float v) {
#pragma unroll
    for (int o = 16; o; o >>= 1) v += __shfl_xor_sync(0xffffffffu, v, o);
    return v;
}
__device__ __forceinline__ float warpMax(float v) {
#pragma unroll
    for (int o = 16; o; o >>= 1) v = fmaxf(v, __shfl_xor_sync(0xffffffffu, v, o));
    return v;
}

// ---------------- prep: split x into bf16 hi/lo -----------------------------------
__global__ void prep_x_kernel(const float* __restrict__ x, __nv_bfloat16* __restrict__ xh,
                              __nv_bfloat16* __restrict__ xl) {
    int i = blockIdx.x * 256 + threadIdx.x;
    if (i >= NB * NTOK * NC) return;
    float f = x[i];
    __nv_bfloat16 h = __float2bfloat16(f);
    xh[i] = h;
    xl[i] = __float2bfloat16(f - __bfloat162float(h));
}

// ---------------- prep: W -> packed word images ------------------------------------
// img = ((tap*3 + cb)*2 + cohalf)*2 + split ; image = 32 k-pair rows x PN words.
// word(c2, n) = {bf16 W[ci=cb*64+2c2+1, co], bf16 W[ci=cb*64+2c2, co]} for co=cohalf*96+n.
__global__ void prep_w_kernel(const float* __restrict__ w, uint32_t* __restrict__ wp,
                              int k2) {
    int idx = blockIdx.x * 256 + threadIdx.x;
    int total = k2 * 12 * 32 * PN;
    if (idx >= total) return;
    int img = idx / (32 * PN), rem = idx % (32 * PN);
    int c2 = rem / PN, n = rem % PN;
    if (n >= 96) { wp[idx] = 0u; return; }
    int tap = img / 12, r = img % 12;
    int cb = r >> 2, r2 = r & 3;
    int cohalf = r2 >> 1, split = r2 & 1;
    int ci = cb * 64 + 2 * c2;
    int co = cohalf * 96 + n;
    float fe = w[((size_t)co * NC + ci) * k2 + tap];
    float fo = w[((size_t)co * NC + ci + 1) * k2 + tap];
    __nv_bfloat16 he = __float2bfloat16(fe), ho = __float2bfloat16(fo);
    __nv_bfloat16 ve = split ? __float2bfloat16(fe - __bfloat162float(he)) : he;
    __nv_bfloat16 vo = split ? __float2bfloat16(fo - __bfloat162float(ho)) : ho;
    uint32_t we, wo;
    we = *(const unsigned short*)&ve;
    wo = *(const unsigned short*)&vo;
    wp[idx] = (wo << 16) | we;
}

// ---------------- conv as implicit GEMM on HMMA (mma.sync bf16) --------------------
// CTA: 128 px x 96 co (grid.y = co-half). 8 warps: 64x24 each, 4x3 m16n8k16 atoms.
__global__ void __launch_bounds__(256) conv_hmma_kernel(
    const __nv_bfloat16* __restrict__ xh, const __nv_bfloat16* __restrict__ xl,
    const uint4* __restrict__ wp, const float* __restrict__ bias,
    float* __restrict__ out, int k, int side, int m)
{
    __shared__ alignas(16) uint32_t sAw[128 * 36];    // 128 px x 64 ci bf16 (pitch 72)
    __shared__ alignas(16) uint32_t sBw[2][32 * PN];  // two W images (hi, lo)

    int tid = threadIdx.x;
    int lane = tid & 31, wid = tid >> 5;
    int wm = wid & 1, wn = wid >> 1;                  // M off 64*wm, N off 24*wn
    long long Bm = (long long)NB * m;

    // A gather setup: thread fills half a pixel row (32 bf16)
    int arow = tid >> 1, ahalf = tid & 1;
    long long apx = (long long)blockIdx.x * 128 + arow;
    long long apxc = apx < Bm - 1 ? apx : Bm - 1;
    int ab = (int)(apxc / m), app = (int)(apxc % m);
    int aoy = app / side, aox = app % side;
    size_t axbase = (size_t)ab * NTOK * NC;
    int adst = arow * 36 + ahalf * 16;                // word offset in sAw

    int half = blockIdx.y;

    float acc[4][3][4];
#pragma unroll
    for (int i = 0; i < 4; i++)
#pragma unroll
        for (int j = 0; j < 3; j++)
#pragma unroll
            for (int q = 0; q < 4; q++) acc[i][j][q] = 0.f;

    int rA = lane >> 2, cA = lane & 3;

    int k2 = k * k;
    for (int g = 0; g < k2 * 3; g++) {
        int tap = g / 3, cb = g - tap * 3;
        int dy = tap / k, dx = tap - dy * k;
        size_t aoff = axbase + (size_t)((aoy + dy) * 64 + aox + dx) * NC + cb * 64 + ahalf * 32;
        int imgb = (tap * 3 + cb) * 4 + half * 2;

        __syncthreads();
        {   // A = xh
            const uint4* s = (const uint4*)(xh + aoff);
#pragma unroll
            for (int j = 0; j < 4; j++) *(uint4*)&sAw[adst + j * 4] = s[j];
            // B hi / lo images
            const uint4* s0 = wp + (size_t)(imgb + 0) * (32 * PN / 4);
            const uint4* s1 = wp + (size_t)(imgb + 1) * (32 * PN / 4);
            uint4* d0 = (uint4*)sBw[0];
            uint4* d1 = (uint4*)sBw[1];
            for (int i = tid; i < 32 * PN / 4; i += 256) { d0[i] = s0[i]; d1[i] = s1[i]; }
        }
        __syncthreads();

        // terms xh*wh (buf 0) and xh*wl (buf 1)
#pragma unroll
        for (int buf = 0; buf < 2; buf++) {
#pragma unroll
            for (int ks = 0; ks < 4; ks++) {
                uint32_t a[4][4];
#pragma unroll
                for (int i = 0; i < 4; i++) {
                    int r = wm * 64 + i * 16 + rA;
                    int c = 8 * ks + cA;
                    a[i][0] = sAw[r * 36 + c];
                    a[i][1] = sAw[(r + 8) * 36 + c];
                    a[i][2] = sAw[r * 36 + c + 4];
                    a[i][3] = sAw[(r + 8) * 36 + c + 4];
                }
#pragma unroll
                for (int j = 0; j < 3; j++) {
                    int n = wn * 24 + j * 8 + rA;
                    uint32_t b0 = sBw[buf][(8 * ks + cA) * PN + n];
                    uint32_t b1 = sBw[buf][(8 * ks + 4 + cA) * PN + n];
#pragma unroll
                    for (int i = 0; i < 4; i++) {
                        asm volatile(
                            "mma.sync.aligned.m16n8k16.row.col.f32.bf16.bf16.f32 "
                            "{%0,%1,%2,%3}, {%4,%5,%6,%7}, {%8,%9}, {%0,%1,%2,%3};"
                            : "+f"(acc[i][j][0]), "+f"(acc[i][j][1]),
                              "+f"(acc[i][j][2]), "+f"(acc[i][j][3])
                            : "r"(a[i][0]), "r"(a[i][1]), "r"(a[i][2]), "r"(a[i][3]),
                              "r"(b0), "r"(b1));
                    }
                }
            }
        }

        __syncthreads();
        {   // A = xl
            const uint4* s = (const uint4*)(xl + aoff);
#pragma unroll
            for (int j = 0; j < 4; j++) *(uint4*)&sAw[adst + j * 4] = s[j];
        }
        __syncthreads();

        // term xl*wh (buf 0)
#pragma unroll
        for (int ks = 0; ks < 4; ks++) {
            uint32_t a[4][4];
#pragma unroll
            for (int i = 0; i < 4; i++) {
                int r = wm * 64 + i * 16 + rA;
                int c = 8 * ks + cA;
                a[i][0] = sAw[r * 36 + c];
                a[i][1] = sAw[(r + 8) * 36 + c];
                a[i][2] = sAw[r * 36 + c + 4];
                a[i][3] = sAw[(r + 8) * 36 + c + 4];
            }
#pragma unroll
            for (int j = 0; j < 3; j++) {
                int n = wn * 24 + j * 8 + rA;
                uint32_t b0 = sBw[0][(8 * ks + cA) * PN + n];
                uint32_t b1 = sBw[0][(8 * ks + 4 + cA) * PN + n];
#pragma unroll
                for (int i = 0; i < 4; i++) {
                    asm volatile(
                        "mma.sync.aligned.m16n8k16.row.col.f32.bf16.bf16.f32 "
                        "{%0,%1,%2,%3}, {%4,%5,%6,%7}, {%8,%9}, {%0,%1,%2,%3};"
                        : "+f"(acc[i][j][0]), "+f"(acc[i][j][1]),
                          "+f"(acc[i][j][2]), "+f"(acc[i][j][3])
                        : "r"(a[i][0]), "r"(a[i][1]), "r"(a[i][2]), "r"(a[i][3]),
                          "r"(b0), "r"(b1));
                }
            }
        }
    }

    // epilogue: acc -> out (+bias)
#pragma unroll
    for (int i = 0; i < 4; i++) {
        long long row0 = (long long)blockIdx.x * 128 + wm * 64 + i * 16 + rA;
#pragma unroll
        for (int j = 0; j < 3; j++) {
            int col = half * 96 + wn * 24 + j * 8 + 2 * cA;
            float b0 = bias[col], b1 = bias[col + 1];
            if (row0 < Bm) {
                float2 v = make_float2(acc[i][j][0] + b0, acc[i][j][1] + b1);
                *(float2*)&out[row0 * NC + col] = v;
            }
            if (row0 + 8 < Bm) {
                float2 v = make_float2(acc[i][j][2] + b0, acc[i][j][3] + b1);
                *(float2*)&out[(row0 + 8) * NC + col] = v;
            }
        }
    }
}

// ---------------- LayerNorm + exact GELU over C=192 --------------------------------
__global__ void ln_gelu_kernel(float* __restrict__ t, const float* __restrict__ g,
                               const float* __restrict__ bb) {
    size_t row = blockIdx.x;
    int tid = threadIdx.x;
    float v = t[row * NC + tid];
    __shared__ float sm[6];
    int lane = tid & 31, w = tid >> 5;
    float s = warpSum(v);
    if (lane == 0) sm[w] = s;
    __syncthreads();
    float mean = 0.f;
#pragma unroll
    for (int i = 0; i < 6; i++) mean += sm[i];
    mean *= (1.0f / 192.0f);
    float d = v - mean;
    __syncthreads();
    s = warpSum(d * d);
    if (lane == 0) sm[w] = s;
    __syncthreads();
    float var = 0.f;
#pragma unroll
    for (int i = 0; i < 6; i++) var += sm[i];
    var *= (1.0f / 192.0f);
    float y = d * rsqrtf(var + 1e-5f) * g[tid] + bb[tid];
    t[row * NC + tid] = y * normcdff(y);
}

// ---------------- generic NT GEMM: C = scale*(A @ W^T) + bias ----------------------
__global__ void __launch_bounds__(256) gemm_nt(
    const float* __restrict__ A, long long sA, int lda,
    const float* __restrict__ W, long long sW, int ldw,
    const float* __restrict__ bias,
    float* __restrict__ C, long long sC, int ldc,
    int M, int Nn, int K, float scale)
{
    __shared__ float As[16][132];
    __shared__ float Ws[16][68];
    int bz = blockIdx.z;
    const float* Ab = A + sA * bz;
    const float* Wb = W + sW * bz;
    float* Cb = C + sC * bz;
    int n0 = blockIdx.x * 64, m0 = blockIdx.y * 128;
    int tid = threadIdx.x;
    int tx = tid & 15, ty = tid >> 4;
    float acc[8][4];
#pragma unroll
    for (int i = 0; i < 8; i++)
#pragma unroll
        for (int j = 0; j < 4; j++) acc[i][j] = 0.f;

    for (int k0 = 0; k0 < K; k0 += 16) {
#pragma unroll
        for (int j = 0; j < 8; j++) {
            int idx = tid + j * 256;
            int kk = idx & 15, mm = idx >> 4;
            int gm = m0 + mm, gk = k0 + kk;
            As[kk][mm] = (gm < M && gk < K) ? Ab[(size_t)gm * lda + gk] : 0.f;
        }
#pragma unroll
        for (int j = 0; j < 4; j++) {
            int idx = tid + j * 256;
            int kk = idx & 15, nn = idx >> 4;
            int gn = n0 + nn, gk = k0 + kk;
            Ws[kk][nn] = (gn < Nn && gk < K) ? Wb[(size_t)gn * ldw + gk] : 0.f;
        }
        __syncthreads();
#pragma unroll
        for (int kk = 0; kk < 16; kk++) {
            float a[8], w[4];
#pragma unroll
            for (int i = 0; i < 8; i++) a[i] = As[kk][ty * 8 + i];
#pragma unroll
            for (int j = 0; j < 4; j++) w[j] = Ws[kk][tx * 4 + j];
#pragma unroll
            for (int i = 0; i < 8; i++)
#pragma unroll
                for (int j = 0; j < 4; j++) acc[i][j] = fmaf(a[i], w[j], acc[i][j]);
        }
        __syncthreads();
    }
#pragma unroll
    for (int i = 0; i < 8; i++) {
        int gm = m0 + ty * 8 + i;
        if (gm >= M) continue;
#pragma unroll
        for (int j = 0; j < 4; j++) {
            int gn = n0 + tx * 4 + j;
            if (gn < Nn) {
                float v = acc[i][j] * scale;
                if (bias) v += bias[gn];
                Cb[(size_t)gm * ldc + gn] = v;
            }
        }
    }
}

// ---------------- generic NN GEMM: C = A(MxK) @ Bm(KxN) ----------------------------
__global__ void __launch_bounds__(256) gemm_nn(
    const float* __restrict__ A, long long sA, int lda,
    const float* __restrict__ Bm, long long sB, int ldb,
    float* __restrict__ C, long long sC, int ldc,
    int M, int Nn, int K)
{
    __shared__ float As[16][132];
    __shared__ float Ws[16][68];
    int bz = blockIdx.z;
    const float* Ab = A + sA * bz;
    const float* Bb = Bm + sB * bz;
    float* Cb = C + sC * bz;
    int n0 = blockIdx.x * 64, m0 = blockIdx.y * 128;
    int tid = threadIdx.x;
    int tx = tid & 15, ty = tid >> 4;
    float acc[8][4];
#pragma unroll
    for (int i = 0; i < 8; i++)
#pragma unroll
        for (int j = 0; j < 4; j++) acc[i][j] = 0.f;

    for (int k0 = 0; k0 < K; k0 += 16) {
#pragma unroll
        for (int j = 0; j < 8; j++) {
            int idx = tid + j * 256;
            int kk = idx & 15, mm = idx >> 4;
            int gm = m0 + mm, gk = k0 + kk;
            As[kk][mm] = (gm < M && gk < K) ? Ab[(size_t)gm * lda + gk] : 0.f;
        }
#pragma unroll
        for (int j = 0; j < 4; j++) {
            int idx = tid + j * 256;
            int nn = idx & 63, kk = idx >> 6;
            int gn = n0 + nn, gk = k0 + kk;
            Ws[kk][nn] = (gk < K && gn < Nn) ? Bb[(size_t)gk * ldb + gn] : 0.f;
        }
        __syncthreads();
#pragma unroll
        for (int kk = 0; kk < 16; kk++) {
            float a[8], w[4];
#pragma unroll
            for (int i = 0; i < 8; i++) a[i] = As[kk][ty * 8 + i];
#pragma unroll
            for (int j = 0; j < 4; j++) w[j] = Ws[kk][tx * 4 + j];
#pragma unroll
            for (int i = 0; i < 8; i++)
#pragma unroll
                for (int j = 0; j < 4; j++) acc[i][j] = fmaf(a[i], w[j], acc[i][j]);
        }
        __syncthreads();
    }
#pragma unroll
    for (int i = 0; i < 8; i++) {
        int gm = m0 + ty * 8 + i;
        if (gm >= M) continue;
#pragma unroll
        for (int j = 0; j < 4; j++) {
            int gn = n0 + tx * 4 + j;
            if (gn < Nn) Cb[(size_t)gm * ldc + gn] = acc[i][j];
        }
    }
}

// ---------------- depthwise 3x3 (same pad) on v, residual add ----------------------
__global__ void dwconv_kernel(const float* __restrict__ kv, const float* __restrict__ lw,
                              const float* __restrict__ lb, float* __restrict__ vp,
                              int side, int m)
{
    long long idx = (long long)blockIdx.x * 256 + threadIdx.x;
    long long total = (long long)NB * m * 64;
    if (idx >= total) return;
    int hd = (int)(idx & 63);
    long long pm = idx >> 6;
    int p = (int)(pm % m);
    int b = (int)(pm / m);
    int y = p / side, x = p % side;
    const float* vbase = kv + (size_t)b * m * 128 + 64 + hd;
    float s = lb[hd];
#pragma unroll
    for (int dy = 0; dy < 3; dy++) {
        int yy = y + dy - 1;
        if (yy < 0 || yy >= side) continue;
#pragma unroll
        for (int dx = 0; dx < 3; dx++) {
            int xx = x + dx - 1;
            if (xx < 0 || xx >= side) continue;
            s += lw[hd * 9 + dy * 3 + dx] * vbase[(size_t)(yy * side + xx) * 128];
        }
    }
    vp[idx] = vbase[(size_t)p * 128] + s;
}

// ---------------- row softmax over m -----------------------------------------------
__global__ void softmax_kernel(float* __restrict__ S, int mcols) {
    size_t row = blockIdx.x;
    float* r = S + row * (size_t)mcols;
    int tid = threadIdx.x;
    float lv[16];
    int cnt = 0;
    float mx = -1e30f;
    for (int j = tid; j < mcols; j += 256) {
        float v = r[j];
        lv[cnt++] = v;
        if (v > mx) mx = v;
    }
    __shared__ float sm[8];
    int lane = tid & 31, w = tid >> 5;
    float tmp = warpMax(mx);
    if (lane == 0) sm[w] = tmp;
    __syncthreads();
    mx = -1e30f;
#pragma unroll
    for (int i = 0; i < 8; i++) mx = fmaxf(mx, sm[i]);
    float sum = 0.f;
    for (int i = 0; i < cnt; i++) {
        float e = __expf(lv[i] - mx);
        lv[i] = e;
        sum += e;
    }
    __syncthreads();
    tmp = warpSum(sum);
    if (lane == 0) sm[w] = tmp;
    __syncthreads();
    sum = 0.f;
#pragma unroll
    for (int i = 0; i < 8; i++) sum += sm[i];
    float inv = 1.f / sum;
    cnt = 0;
    for (int j = tid; j < mcols; j += 256) r[j] = lv[cnt++] * inv;
}

// ---------------- host orchestration ------------------------------------------------
extern "C" void kernel_launch(void* const* d_in, const int* in_sizes, int n_in,
                              void* d_out, int out_size)
{
    (void)in_sizes; (void)n_in; (void)out_size;
    const float* x    = (const float*)d_in[0];
    const float* q_w  = (const float*)d_in[1];
    const float* q_b  = (const float*)d_in[2];
    const float* kv_w = (const float*)d_in[3];
    const float* kv_b = (const float*)d_in[4];
    const float* sr_w[3] = {(const float*)d_in[5], (const float*)d_in[7], (const float*)d_in[9]};
    const float* sr_b[3] = {(const float*)d_in[6], (const float*)d_in[8], (const float*)d_in[10]};
    const float* ln_g[3] = {(const float*)d_in[11], (const float*)d_in[13], (const float*)d_in[15]};
    const float* ln_b[3] = {(const float*)d_in[12], (const float*)d_in[14], (const float*)d_in[16]};
    const float* lc_w[3] = {(const float*)d_in[17], (const float*)d_in[19], (const float*)d_in[21]};
    const float* lc_b[3] = {(const float*)d_in[18], (const float*)d_in[20], (const float*)d_in[22]};
    const float* nn1_w = (const float*)d_in[23];
    const float* nn1_b = (const float*)d_in[24];
    float* out = (float*)d_out;

    float *p_q, *p_t, *p_kv, *p_vp, *p_S, *p_xcat;
    __nv_bfloat16 *p_xh, *p_xl;
    uint32_t* p_wp;
    cudaGetSymbolAddress((void**)&p_q,    g_q);
    cudaGetSymbolAddress((void**)&p_t,    g_t);
    cudaGetSymbolAddress((void**)&p_kv,   g_kv);
    cudaGetSymbolAddress((void**)&p_vp,   g_vp);
    cudaGetSymbolAddress((void**)&p_S,    g_S);
    cudaGetSymbolAddress((void**)&p_xcat, g_xcat);
    cudaGetSymbolAddress((void**)&p_xh,   g_xh);
    cudaGetSymbolAddress((void**)&p_xl,   g_xl);
    cudaGetSymbolAddress((void**)&p_wp,   g_wpack);

    prep_x_kernel<<<(NB * NTOK * NC + 255) / 256, 256>>>(x, p_xh, p_xl);

    gemm_nt<<<dim3(3, 128, 1), 256>>>(x, 0, NC, q_w, 0, NC, q_b,
                                      p_q, 0, NC, NB * NTOK, NC, NC, 1.f);

    const int KS[3] = {8, 4, 2};
    for (int h = 0; h < 3; h++) {
        int k = KS[h];
        int side = 64 - k + 1;
        int m = side * side;
        int k2 = k * k;
        long long Bm = (long long)NB * m;

        prep_w_kernel<<<(k2 * 12 * 32 * PN + 255) / 256, 256>>>(sr_w[h], p_wp, k2);
        conv_hmma_kernel<<<dim3((int)((Bm + 127) / 128), 2), 256>>>(
            p_xh, p_xl, (const uint4*)p_wp, sr_b[h], p_t, k, side, m);
        ln_gelu_kernel<<<NB * m, 192>>>(p_t, ln_g[h], ln_b[h]);

        gemm_nt<<<dim3(2, (NB * m + 127) / 128, 1), 256>>>(
            p_t, 0, NC, kv_w, 0, NC, kv_b, p_kv, 0, 128, NB * m, 128, NC, 1.f);

        dwconv_kernel<<<(int)(((long long)NB * m * 64 + 255) / 256), 256>>>(
            p_kv, lc_w[h], lc_b[h], p_vp, side, m);

        gemm_nt<<<dim3((m + 63) / 64, NTOK / 128, NB), 256>>>(
            p_q + h * 64, (long long)NTOK * NC, NC,
            p_kv, (long long)m * 128, 128, nullptr,
            p_S, (long long)NTOK * m, m, NTOK, m, 64, ATT_SCALE);

        softmax_kernel<<<NB * NTOK, 256>>>(p_S, m);

        gemm_nn<<<dim3(1, NTOK / 128, NB), 256>>>(
            p_S, (long long)NTOK * m, m,
            p_vp, (long long)m * 64, 64,
            p_xcat + h * 64, (long long)NTOK * NC, NC, NTOK, 64, m);
    }

    gemm_nt<<<dim3(3, 128, 1), 256>>>(p_xcat, 0, NC, nn1_w, 0, NC, nn1_b,
                                      out, 0, NC, NB * NTOK, NC, NC, 1.f);
}

// round 7
// speedup vs baseline: 2.0902x; 1.6224x over previous
#include <cuda_runtime.h>
#include <cuda_bf16.h>
#include <math.h>
#include <stdint.h>

#define NB   4
#define NTOK 4096
#define NC   192
#define MAXM 3969
#define MAXMP 4032                       // max padded m (63*64)
#define PN   104                         // conv B smem word pitch

static const float ATT_SCALE = 0.07216878364870323f; // 192^-0.5

// ---------------- scratch -------------------------------------------------------
__device__ float g_q[NB * NTOK * NC];
__device__ float g_t[(size_t)NB * MAXM * NC];
__device__ float g_kv[NB * MAXM * 128];
__device__ float g_vp[NB * MAXM * 64];
__device__ float g_S[(size_t)NB * NTOK * MAXMP];
__device__ float g_xcat[NB * NTOK * NC];
__device__ __nv_bfloat16 g_xh[NB * NTOK * NC];
__device__ __nv_bfloat16 g_xl[NB * NTOK * NC];
__device__ uint32_t g_wpack[768 * 32 * PN];
__device__ __nv_bfloat16 g_qh[NB * NTOK * 64];
__device__ __nv_bfloat16 g_ql[NB * NTOK * 64];
__device__ __nv_bfloat16 g_kh[NB * MAXM * 64];
__device__ __nv_bfloat16 g_kl[NB * MAXM * 64];
__device__ __nv_bfloat16 g_Ph[(size_t)NB * NTOK * MAXMP];
__device__ __nv_bfloat16 g_Pl[(size_t)NB * NTOK * MAXMP];
__device__ uint32_t g_vpkh[NB * 63 * 32 * 64];
__device__ uint32_t g_vpkl[NB * 63 * 32 * 64];

// ---------------- warp helpers ---------------------------------------------------
__device__ __forceinline__ float warpSum(float v) {
#pragma unroll
    for (int o = 16; o; o >>= 1) v += __shfl_xor_sync(0xffffffffu, v, o);
    return v;
}
__device__ __forceinline__ float warpMax(float v) {
#pragma unroll
    for (int o = 16; o; o >>= 1) v = fmaxf(v, __shfl_xor_sync(0xffffffffu, v, o));
    return v;
}
#define MMA16816(acc, a, b0, b1)                                                    \
    asm volatile("mma.sync.aligned.m16n8k16.row.col.f32.bf16.bf16.f32 "             \
        "{%0,%1,%2,%3}, {%4,%5,%6,%7}, {%8,%9}, {%0,%1,%2,%3};"                     \
        : "+f"((acc)[0]), "+f"((acc)[1]), "+f"((acc)[2]), "+f"((acc)[3])            \
        : "r"((a)[0]), "r"((a)[1]), "r"((a)[2]), "r"((a)[3]), "r"(b0), "r"(b1))

// ---------------- prep: split x into bf16 hi/lo -----------------------------------
__global__ void prep_x_kernel(const float* __restrict__ x, __nv_bfloat16* __restrict__ xh,
                              __nv_bfloat16* __restrict__ xl) {
    int i = blockIdx.x * 256 + threadIdx.x;
    if (i >= NB * NTOK * NC) return;
    float f = x[i];
    __nv_bfloat16 h = __float2bfloat16(f);
    xh[i] = h;
    xl[i] = __float2bfloat16(f - __bfloat162float(h));
}

// ---------------- prep: W -> packed word images ------------------------------------
__global__ void prep_w_kernel(const float* __restrict__ w, uint32_t* __restrict__ wp,
                              int k2) {
    int idx = blockIdx.x * 256 + threadIdx.x;
    int total = k2 * 12 * 32 * PN;
    if (idx >= total) return;
    int img = idx / (32 * PN), rem = idx % (32 * PN);
    int c2 = rem / PN, n = rem % PN;
    if (n >= 96) { wp[idx] = 0u; return; }
    int tap = img / 12, r = img % 12;
    int cb = r >> 2, r2 = r & 3;
    int cohalf = r2 >> 1, split = r2 & 1;
    int ci = cb * 64 + 2 * c2;
    int co = cohalf * 96 + n;
    float fe = w[((size_t)co * NC + ci) * k2 + tap];
    float fo = w[((size_t)co * NC + ci + 1) * k2 + tap];
    __nv_bfloat16 he = __float2bfloat16(fe), ho = __float2bfloat16(fo);
    __nv_bfloat16 ve = split ? __float2bfloat16(fe - __bfloat162float(he)) : he;
    __nv_bfloat16 vo = split ? __float2bfloat16(fo - __bfloat162float(ho)) : ho;
    uint32_t we = *(const unsigned short*)&ve;
    uint32_t wo = *(const unsigned short*)&vo;
    wp[idx] = (wo << 16) | we;
}

// ---------------- conv as implicit GEMM on HMMA (unchanged from R4) ----------------
__global__ void __launch_bounds__(256) conv_hmma_kernel(
    const __nv_bfloat16* __restrict__ xh, const __nv_bfloat16* __restrict__ xl,
    const uint4* __restrict__ wp, const float* __restrict__ bias,
    float* __restrict__ out, int k, int side, int m)
{
    __shared__ alignas(16) uint32_t sAw[128 * 36];
    __shared__ alignas(16) uint32_t sBw[2][32 * PN];

    int tid = threadIdx.x;
    int lane = tid & 31, wid = tid >> 5;
    int wm = wid & 1, wn = wid >> 1;
    long long Bm = (long long)NB * m;

    int arow = tid >> 1, ahalf = tid & 1;
    long long apx = (long long)blockIdx.x * 128 + arow;
    long long apxc = apx < Bm - 1 ? apx : Bm - 1;
    int ab = (int)(apxc / m), app = (int)(apxc % m);
    int aoy = app / side, aox = app % side;
    size_t axbase = (size_t)ab * NTOK * NC;
    int adst = arow * 36 + ahalf * 16;

    int half = blockIdx.y;

    float acc[4][3][4];
#pragma unroll
    for (int i = 0; i < 4; i++)
#pragma unroll
        for (int j = 0; j < 3; j++)
#pragma unroll
            for (int q = 0; q < 4; q++) acc[i][j][q] = 0.f;

    int rA = lane >> 2, cA = lane & 3;

    int k2 = k * k;
    for (int g = 0; g < k2 * 3; g++) {
        int tap = g / 3, cb = g - tap * 3;
        int dy = tap / k, dx = tap - dy * k;
        size_t aoff = axbase + (size_t)((aoy + dy) * 64 + aox + dx) * NC + cb * 64 + ahalf * 32;
        int imgb = (tap * 3 + cb) * 4 + half * 2;

        __syncthreads();
        {
            const uint4* s = (const uint4*)(xh + aoff);
#pragma unroll
            for (int j = 0; j < 4; j++) *(uint4*)&sAw[adst + j * 4] = s[j];
            const uint4* s0 = wp + (size_t)(imgb + 0) * (32 * PN / 4);
            const uint4* s1 = wp + (size_t)(imgb + 1) * (32 * PN / 4);
            uint4* d0 = (uint4*)sBw[0];
            uint4* d1 = (uint4*)sBw[1];
            for (int i = tid; i < 32 * PN / 4; i += 256) { d0[i] = s0[i]; d1[i] = s1[i]; }
        }
        __syncthreads();

#pragma unroll
        for (int buf = 0; buf < 2; buf++) {
#pragma unroll
            for (int ks = 0; ks < 4; ks++) {
                uint32_t a[4][4];
#pragma unroll
                for (int i = 0; i < 4; i++) {
                    int r = wm * 64 + i * 16 + rA;
                    int c = 8 * ks + cA;
                    a[i][0] = sAw[r * 36 + c];
                    a[i][1] = sAw[(r + 8) * 36 + c];
                    a[i][2] = sAw[r * 36 + c + 4];
                    a[i][3] = sAw[(r + 8) * 36 + c + 4];
                }
#pragma unroll
                for (int j = 0; j < 3; j++) {
                    int n = wn * 24 + j * 8 + rA;
                    uint32_t b0 = sBw[buf][(8 * ks + cA) * PN + n];
                    uint32_t b1 = sBw[buf][(8 * ks + 4 + cA) * PN + n];
#pragma unroll
                    for (int i = 0; i < 4; i++) MMA16816(acc[i][j], a[i], b0, b1);
                }
            }
        }

        __syncthreads();
        {
            const uint4* s = (const uint4*)(xl + aoff);
#pragma unroll
            for (int j = 0; j < 4; j++) *(uint4*)&sAw[adst + j * 4] = s[j];
        }
        __syncthreads();

#pragma unroll
        for (int ks = 0; ks < 4; ks++) {
            uint32_t a[4][4];
#pragma unroll
            for (int i = 0; i < 4; i++) {
                int r = wm * 64 + i * 16 + rA;
                int c = 8 * ks + cA;
                a[i][0] = sAw[r * 36 + c];
                a[i][1] = sAw[(r + 8) * 36 + c];
                a[i][2] = sAw[r * 36 + c + 4];
                a[i][3] = sAw[(r + 8) * 36 + c + 4];
            }
#pragma unroll
            for (int j = 0; j < 3; j++) {
                int n = wn * 24 + j * 8 + rA;
                uint32_t b0 = sBw[0][(8 * ks + cA) * PN + n];
                uint32_t b1 = sBw[0][(8 * ks + 4 + cA) * PN + n];
#pragma unroll
                for (int i = 0; i < 4; i++) MMA16816(acc[i][j], a[i], b0, b1);
            }
        }
    }

#pragma unroll
    for (int i = 0; i < 4; i++) {
        long long row0 = (long long)blockIdx.x * 128 + wm * 64 + i * 16 + rA;
#pragma unroll
        for (int j = 0; j < 3; j++) {
            int col = half * 96 + wn * 24 + j * 8 + 2 * cA;
            float b0 = bias[col], b1 = bias[col + 1];
            if (row0 < Bm) {
                float2 v = make_float2(acc[i][j][0] + b0, acc[i][j][1] + b1);
                *(float2*)&out[row0 * NC + col] = v;
            }
            if (row0 + 8 < Bm) {
                float2 v = make_float2(acc[i][j][2] + b0, acc[i][j][3] + b1);
                *(float2*)&out[(row0 + 8) * NC + col] = v;
            }
        }
    }
}

// ---------------- prep q / k splits -----------------------------------------------
__global__ void prep_q_kernel(const float* __restrict__ q, __nv_bfloat16* __restrict__ qh,
                              __nv_bfloat16* __restrict__ ql, int h) {
    int i = blockIdx.x * 256 + threadIdx.x;
    if (i >= NB * NTOK * 64) return;
    int c = i & 63;
    int row = i >> 6;
    float f = q[(size_t)row * NC + h * 64 + c];
    __nv_bfloat16 hi = __float2bfloat16(f);
    qh[i] = hi;
    ql[i] = __float2bfloat16(f - __bfloat162float(hi));
}
__global__ void prep_k_kernel(const float* __restrict__ kv, __nv_bfloat16* __restrict__ kh,
                              __nv_bfloat16* __restrict__ kl, int m) {
    int i = blockIdx.x * 256 + threadIdx.x;
    if (i >= NB * m * 64) return;
    int c = i & 63;
    int row = i >> 6;
    float f = kv[(size_t)row * 128 + c];
    __nv_bfloat16 hi = __float2bfloat16(f);
    kh[i] = hi;
    kl[i] = __float2bfloat16(f - __bfloat162float(hi));
}

// ---------------- pack v' into MMA word images --------------------------------------
__global__ void pack_v_kernel(const float* __restrict__ vp, uint32_t* __restrict__ pkh,
                              uint32_t* __restrict__ pkl, int m, int nchunk) {
    int idx = blockIdx.x * 256 + threadIdx.x;
    int total = NB * nchunk * 32 * 64;
    if (idx >= total) return;
    int n = idx & 63;
    int c2 = (idx >> 6) & 31;
    int c = (idx >> 11) % nchunk;
    int b = idx / (nchunk * 2048);
    int k0 = c * 64 + 2 * c2;
    float v0 = (k0 < m) ? vp[((size_t)b * m + k0) * 64 + n] : 0.f;
    float v1 = (k0 + 1 < m) ? vp[((size_t)b * m + k0 + 1) * 64 + n] : 0.f;
    __nv_bfloat16 h0 = __float2bfloat16(v0), h1 = __float2bfloat16(v1);
    __nv_bfloat16 l0 = __float2bfloat16(v0 - __bfloat162float(h0));
    __nv_bfloat16 l1 = __float2bfloat16(v1 - __bfloat162float(h1));
    uint32_t wh = ((uint32_t)*(unsigned short*)&h1 << 16) | *(unsigned short*)&h0;
    uint32_t wl = ((uint32_t)*(unsigned short*)&l1 << 16) | *(unsigned short*)&l0;
    pkh[idx] = wh;
    pkl[idx] = wl;
}

// ---------------- S = scale * q @ k^T via HMMA (row stride mpad, even) ---------------
__global__ void __launch_bounds__(256) attn_s_kernel(
    const __nv_bfloat16* __restrict__ qh, const __nv_bfloat16* __restrict__ ql,
    const __nv_bfloat16* __restrict__ kh, const __nv_bfloat16* __restrict__ kl,
    float* __restrict__ S, int m, int mpad)
{
    extern __shared__ uint32_t dynsm[];
    uint32_t* sQ = dynsm;                 // 2 * 128 * 36
    uint32_t* sK = dynsm + 2 * 128 * 36;  // 2 * 32 * 136

    int tid = threadIdx.x, lane = tid & 31, wid = tid >> 5;
    int wm = wid & 1, wn = wid >> 1;
    int rA = lane >> 2, cA = lane & 3;
    int b = blockIdx.z;
    int mq0 = blockIdx.y * 128;
    int n0 = blockIdx.x * 128;

    {   // q fill (both splits)
        int arow = tid >> 1, ahalf = tid & 1;
        size_t off = ((size_t)b * NTOK + mq0 + arow) * 64 + ahalf * 32;
        const uint4* sh = (const uint4*)(qh + off);
        const uint4* sl = (const uint4*)(ql + off);
        uint32_t* dh = sQ + arow * 36 + ahalf * 16;
        uint32_t* dl = sQ + 128 * 36 + arow * 36 + ahalf * 16;
#pragma unroll
        for (int j = 0; j < 4; j++) { *(uint4*)&dh[j * 4] = sh[j]; *(uint4*)&dl[j * 4] = sl[j]; }
    }
    {   // k fill with transpose into [c2][n] images
        int n = tid >> 1, half = tid & 1;
        int ng = n0 + n;
        int ok = ng < m;
        size_t roff = ((size_t)b * m + (ok ? ng : 0)) * 64;
        const uint4* rh = (const uint4*)(kh + roff);
        const uint4* rl = (const uint4*)(kl + roff);
#pragma unroll
        for (int jj = 0; jj < 4; jj++) {
            uint4 vh = rh[half * 4 + jj];
            uint4 vl = rl[half * 4 + jj];
            if (!ok) { vh = make_uint4(0, 0, 0, 0); vl = vh; }
            int c2 = half * 16 + jj * 4;
            sK[(c2 + 0) * 136 + n] = vh.x;
            sK[(c2 + 1) * 136 + n] = vh.y;
            sK[(c2 + 2) * 136 + n] = vh.z;
            sK[(c2 + 3) * 136 + n] = vh.w;
            sK[32 * 136 + (c2 + 0) * 136 + n] = vl.x;
            sK[32 * 136 + (c2 + 1) * 136 + n] = vl.y;
            sK[32 * 136 + (c2 + 2) * 136 + n] = vl.z;
            sK[32 * 136 + (c2 + 3) * 136 + n] = vl.w;
        }
    }
    __syncthreads();

    float acc[4][4][4];
#pragma unroll
    for (int i = 0; i < 4; i++)
#pragma unroll
        for (int j = 0; j < 4; j++)
#pragma unroll
            for (int q = 0; q < 4; q++) acc[i][j][q] = 0.f;

    // terms: (qh,kh), (qh,kl), (ql,kh)
#pragma unroll
    for (int t = 0; t < 3; t++) {
        const uint32_t* A = sQ + (t == 2 ? 128 * 36 : 0);
        const uint32_t* Bk = sK + (t == 1 ? 32 * 136 : 0);
#pragma unroll
        for (int ks = 0; ks < 4; ks++) {
            uint32_t a[4][4];
#pragma unroll
            for (int i = 0; i < 4; i++) {
                int r = wm * 64 + i * 16 + rA;
                int c = 8 * ks + cA;
                a[i][0] = A[r * 36 + c];
                a[i][1] = A[(r + 8) * 36 + c];
                a[i][2] = A[r * 36 + c + 4];
                a[i][3] = A[(r + 8) * 36 + c + 4];
            }
#pragma unroll
            for (int j = 0; j < 4; j++) {
                int n = wn * 32 + j * 8 + rA;
                uint32_t b0 = Bk[(8 * ks + cA) * 136 + n];
                uint32_t b1 = Bk[(8 * ks + 4 + cA) * 136 + n];
#pragma unroll
                for (int i = 0; i < 4; i++) MMA16816(acc[i][j], a[i], b0, b1);
            }
        }
    }

    // epilogue: S (fp32, padded row stride mpad — float2 always 8B-aligned)
#pragma unroll
    for (int i = 0; i < 4; i++) {
        size_t row0 = (size_t)b * NTOK + mq0 + wm * 64 + i * 16 + rA;
#pragma unroll
        for (int j = 0; j < 4; j++) {
            int col = n0 + wn * 32 + j * 8 + 2 * cA;
            if (col + 1 < m) {
                *(float2*)&S[row0 * mpad + col] =
                    make_float2(acc[i][j][0] * ATT_SCALE, acc[i][j][1] * ATT_SCALE);
                *(float2*)&S[(row0 + 8) * mpad + col] =
                    make_float2(acc[i][j][2] * ATT_SCALE, acc[i][j][3] * ATT_SCALE);
            } else if (col < m) {
                S[row0 * mpad + col] = acc[i][j][0] * ATT_SCALE;
                S[(row0 + 8) * mpad + col] = acc[i][j][2] * ATT_SCALE;
            }
        }
    }
}

// ---------------- row softmax (stride mpad) -> split bf16 P (padded) -----------------
__global__ void softmax_kernel(const float* __restrict__ S, __nv_bfloat16* __restrict__ Ph,
                               __nv_bfloat16* __restrict__ Pl, int m, int mpad) {
    size_t row = blockIdx.x;
    const float* r = S + row * (size_t)mpad;
    int tid = threadIdx.x;
    float lv[16];
    int cnt = 0;
    float mx = -1e30f;
    for (int j = tid; j < m; j += 256) {
        float v = r[j];
        lv[cnt++] = v;
        if (v > mx) mx = v;
    }
    __shared__ float sm[8];
    int lane = tid & 31, w = tid >> 5;
    float tmp = warpMax(mx);
    if (lane == 0) sm[w] = tmp;
    __syncthreads();
    mx = -1e30f;
#pragma unroll
    for (int i = 0; i < 8; i++) mx = fmaxf(mx, sm[i]);
    float sum = 0.f;
    for (int i = 0; i < cnt; i++) {
        float e = __expf(lv[i] - mx);
        lv[i] = e;
        sum += e;
    }
    __syncthreads();
    tmp = warpSum(sum);
    if (lane == 0) sm[w] = tmp;
    __syncthreads();
    sum = 0.f;
#pragma unroll
    for (int i = 0; i < 8; i++) sum += sm[i];
    float inv = 1.f / sum;
    __nv_bfloat16* ph = Ph + row * (size_t)mpad;
    __nv_bfloat16* pl = Pl + row * (size_t)mpad;
    cnt = 0;
    for (int j = tid; j < mpad; j += 256) {
        if (j < m) {
            float p = lv[cnt++] * inv;
            __nv_bfloat16 hp = __float2bfloat16(p);
            ph[j] = hp;
            pl[j] = __float2bfloat16(p - __bfloat162float(hp));
        } else {
            ph[j] = __float2bfloat16(0.f);
            pl[j] = __float2bfloat16(0.f);
        }
    }
}

// ---------------- PV: out_h = P @ v' via HMMA (FIXED N coverage) ---------------------
// CTA 64(rows) x 64(v cols); warps 4(M)x2(N), each warp 16 rows x 32 cols.
__global__ void __launch_bounds__(256) attn_pv_kernel(
    const __nv_bfloat16* __restrict__ Ph, const __nv_bfloat16* __restrict__ Pl,
    const uint32_t* __restrict__ pkh, const uint32_t* __restrict__ pkl,
    float* __restrict__ out, int mpad, int nchunk)
{
    __shared__ alignas(16) uint32_t sP[2 * 64 * 36];
    __shared__ alignas(16) uint32_t sV[2 * 32 * 72];

    int tid = threadIdx.x, lane = tid & 31, wid = tid >> 5;
    int wm = wid & 3, wn = wid >> 2;
    int rA = lane >> 2, cA = lane & 3;
    int b = blockIdx.y;
    int m0 = blockIdx.x * 64;

    int arow = tid >> 2, aq = tid & 3;
    size_t abase = ((size_t)b * NTOK + m0 + arow) * mpad;

    float acc[4][4];
#pragma unroll
    for (int j = 0; j < 4; j++)
#pragma unroll
        for (int q = 0; q < 4; q++) acc[j][q] = 0.f;

    for (int c = 0; c < nchunk; c++) {
        __syncthreads();
        {
            size_t off = abase + c * 64 + aq * 16;
            const uint4* sh = (const uint4*)(Ph + off);
            const uint4* sl = (const uint4*)(Pl + off);
            uint32_t* dh = sP + arow * 36 + aq * 8;
            uint32_t* dl = sP + 64 * 36 + arow * 36 + aq * 8;
            *(uint4*)&dh[0] = sh[0]; *(uint4*)&dh[4] = sh[1];
            *(uint4*)&dl[0] = sl[0]; *(uint4*)&dl[4] = sl[1];
        }
        {
            size_t gb = ((size_t)b * nchunk + c) * 2048;
#pragma unroll
            for (int t = 0; t < 8; t++) {
                int idx = tid + t * 256;
                int c2 = idx >> 6, n = idx & 63;
                sV[c2 * 72 + n] = pkh[gb + idx];
                sV[32 * 72 + c2 * 72 + n] = pkl[gb + idx];
            }
        }
        __syncthreads();

#pragma unroll
        for (int t = 0; t < 3; t++) {
            const uint32_t* A = sP + (t == 2 ? 64 * 36 : 0);
            const uint32_t* Bv = sV + (t == 1 ? 32 * 72 : 0);
#pragma unroll
            for (int ks = 0; ks < 4; ks++) {
                uint32_t a[4];
                int r = wm * 16 + rA;
                int cc = 8 * ks + cA;
                a[0] = A[r * 36 + cc];
                a[1] = A[(r + 8) * 36 + cc];
                a[2] = A[r * 36 + cc + 4];
                a[3] = A[(r + 8) * 36 + cc + 4];
#pragma unroll
                for (int j = 0; j < 4; j++) {
                    int n = wn * 32 + j * 8 + rA;
                    uint32_t b0 = Bv[(8 * ks + cA) * 72 + n];
                    uint32_t b1 = Bv[(8 * ks + 4 + cA) * 72 + n];
                    MMA16816(acc[j], a, b0, b1);
                }
            }
        }
    }

    size_t row0 = (size_t)b * NTOK + m0 + wm * 16 + rA;
#pragma unroll
    for (int j = 0; j < 4; j++) {
        int col = wn * 32 + j * 8 + 2 * cA;
        *(float2*)&out[row0 * NC + col] = make_float2(acc[j][0], acc[j][1]);
        *(float2*)&out[(row0 + 8) * NC + col] = make_float2(acc[j][2], acc[j][3]);
    }
}

// ---------------- LayerNorm + exact GELU --------------------------------------------
__global__ void ln_gelu_kernel(float* __restrict__ t, const float* __restrict__ g,
                               const float* __restrict__ bb) {
    size_t row = blockIdx.x;
    int tid = threadIdx.x;
    float v = t[row * NC + tid];
    __shared__ float sm[6];
    int lane = tid & 31, w = tid >> 5;
    float s = warpSum(v);
    if (lane == 0) sm[w] = s;
    __syncthreads();
    float mean = 0.f;
#pragma unroll
    for (int i = 0; i < 6; i++) mean += sm[i];
    mean *= (1.0f / 192.0f);
    float d = v - mean;
    __syncthreads();
    s = warpSum(d * d);
    if (lane == 0) sm[w] = s;
    __syncthreads();
    float var = 0.f;
#pragma unroll
    for (int i = 0; i < 6; i++) var += sm[i];
    var *= (1.0f / 192.0f);
    float y = d * rsqrtf(var + 1e-5f) * g[tid] + bb[tid];
    t[row * NC + tid] = y * normcdff(y);
}

// ---------------- generic NT GEMM (projections) --------------------------------------
__global__ void __launch_bounds__(256) gemm_nt(
    const float* __restrict__ A, long long sA, int lda,
    const float* __restrict__ W, long long sW, int ldw,
    const float* __restrict__ bias,
    float* __restrict__ C, long long sC, int ldc,
    int M, int Nn, int K, float scale)
{
    __shared__ float As[16][132];
    __shared__ float Ws[16][68];
    int bz = blockIdx.z;
    const float* Ab = A + sA * bz;
    const float* Wb = W + sW * bz;
    float* Cb = C + sC * bz;
    int n0 = blockIdx.x * 64, m0 = blockIdx.y * 128;
    int tid = threadIdx.x;
    int tx = tid & 15, ty = tid >> 4;
    float acc[8][4];
#pragma unroll
    for (int i = 0; i < 8; i++)
#pragma unroll
        for (int j = 0; j < 4; j++) acc[i][j] = 0.f;

    for (int k0 = 0; k0 < K; k0 += 16) {
#pragma unroll
        for (int j = 0; j < 8; j++) {
            int idx = tid + j * 256;
            int kk = idx & 15, mm = idx >> 4;
            int gm = m0 + mm, gk = k0 + kk;
            As[kk][mm] = (gm < M && gk < K) ? Ab[(size_t)gm * lda + gk] : 0.f;
        }
#pragma unroll
        for (int j = 0; j < 4; j++) {
            int idx = tid + j * 256;
            int kk = idx & 15, nn = idx >> 4;
            int gn = n0 + nn, gk = k0 + kk;
            Ws[kk][nn] = (gn < Nn && gk < K) ? Wb[(size_t)gn * ldw + gk] : 0.f;
        }
        __syncthreads();
#pragma unroll
        for (int kk = 0; kk < 16; kk++) {
            float a[8], w[4];
#pragma unroll
            for (int i = 0; i < 8; i++) a[i] = As[kk][ty * 8 + i];
#pragma unroll
            for (int j = 0; j < 4; j++) w[j] = Ws[kk][tx * 4 + j];
#pragma unroll
            for (int i = 0; i < 8; i++)
#pragma unroll
                for (int j = 0; j < 4; j++) acc[i][j] = fmaf(a[i], w[j], acc[i][j]);
        }
        __syncthreads();
    }
#pragma unroll
    for (int i = 0; i < 8; i++) {
        int gm = m0 + ty * 8 + i;
        if (gm >= M) continue;
#pragma unroll
        for (int j = 0; j < 4; j++) {
            int gn = n0 + tx * 4 + j;
            if (gn < Nn) {
                float v = acc[i][j] * scale;
                if (bias) v += bias[gn];
                Cb[(size_t)gm * ldc + gn] = v;
            }
        }
    }
}

// ---------------- depthwise 3x3 on v, residual add -----------------------------------
__global__ void dwconv_kernel(const float* __restrict__ kv, const float* __restrict__ lw,
                              const float* __restrict__ lb, float* __restrict__ vp,
                              int side, int m)
{
    long long idx = (long long)blockIdx.x * 256 + threadIdx.x;
    long long total = (long long)NB * m * 64;
    if (idx >= total) return;
    int hd = (int)(idx & 63);
    long long pm = idx >> 6;
    int p = (int)(pm % m);
    int b = (int)(pm / m);
    int y = p / side, x = p % side;
    const float* vbase = kv + (size_t)b * m * 128 + 64 + hd;
    float s = lb[hd];
#pragma unroll
    for (int dy = 0; dy < 3; dy++) {
        int yy = y + dy - 1;
        if (yy < 0 || yy >= side) continue;
#pragma unroll
        for (int dx = 0; dx < 3; dx++) {
            int xx = x + dx - 1;
            if (xx < 0 || xx >= side) continue;
            s += lw[hd * 9 + dy * 3 + dx] * vbase[(size_t)(yy * side + xx) * 128];
        }
    }
    vp[idx] = vbase[(size_t)p * 128] + s;
}

// ---------------- host orchestration ---------------------------------------------------
extern "C" void kernel_launch(void* const* d_in, const int* in_sizes, int n_in,
                              void* d_out, int out_size)
{
    (void)in_sizes; (void)n_in; (void)out_size;
    const float* x    = (const float*)d_in[0];
    const float* q_w  = (const float*)d_in[1];
    const float* q_b  = (const float*)d_in[2];
    const float* kv_w = (const float*)d_in[3];
    const float* kv_b = (const float*)d_in[4];
    const float* sr_w[3] = {(const float*)d_in[5], (const float*)d_in[7], (const float*)d_in[9]};
    const float* sr_b[3] = {(const float*)d_in[6], (const float*)d_in[8], (const float*)d_in[10]};
    const float* ln_g[3] = {(const float*)d_in[11], (const float*)d_in[13], (const float*)d_in[15]};
    const float* ln_b[3] = {(const float*)d_in[12], (const float*)d_in[14], (const float*)d_in[16]};
    const float* lc_w[3] = {(const float*)d_in[17], (const float*)d_in[19], (const float*)d_in[21]};
    const float* lc_b[3] = {(const float*)d_in[18], (const float*)d_in[20], (const float*)d_in[22]};
    const float* nn1_w = (const float*)d_in[23];
    const float* nn1_b = (const float*)d_in[24];
    float* out = (float*)d_out;

    float *p_q, *p_t, *p_kv, *p_vp, *p_S, *p_xcat;
    __nv_bfloat16 *p_xh, *p_xl, *p_qh, *p_ql, *p_kh, *p_kl, *p_Ph, *p_Pl;
    uint32_t *p_wp, *p_vkh, *p_vkl;
    cudaGetSymbolAddress((void**)&p_q,    g_q);
    cudaGetSymbolAddress((void**)&p_t,    g_t);
    cudaGetSymbolAddress((void**)&p_kv,   g_kv);
    cudaGetSymbolAddress((void**)&p_vp,   g_vp);
    cudaGetSymbolAddress((void**)&p_S,    g_S);
    cudaGetSymbolAddress((void**)&p_xcat, g_xcat);
    cudaGetSymbolAddress((void**)&p_xh,   g_xh);
    cudaGetSymbolAddress((void**)&p_xl,   g_xl);
    cudaGetSymbolAddress((void**)&p_wp,   g_wpack);
    cudaGetSymbolAddress((void**)&p_qh,   g_qh);
    cudaGetSymbolAddress((void**)&p_ql,   g_ql);
    cudaGetSymbolAddress((void**)&p_kh,   g_kh);
    cudaGetSymbolAddress((void**)&p_kl,   g_kl);
    cudaGetSymbolAddress((void**)&p_Ph,   g_Ph);
    cudaGetSymbolAddress((void**)&p_Pl,   g_Pl);
    cudaGetSymbolAddress((void**)&p_vkh,  g_vpkh);
    cudaGetSymbolAddress((void**)&p_vkl,  g_vpkl);

    cudaFuncSetAttribute(attn_s_kernel, cudaFuncAttributeMaxDynamicSharedMemorySize, 71680);

    prep_x_kernel<<<(NB * NTOK * NC + 255) / 256, 256>>>(x, p_xh, p_xl);

    gemm_nt<<<dim3(3, 128, 1), 256>>>(x, 0, NC, q_w, 0, NC, q_b,
                                      p_q, 0, NC, NB * NTOK, NC, NC, 1.f);

    const int KS[3] = {8, 4, 2};
    for (int h = 0; h < 3; h++) {
        int k = KS[h];
        int side = 64 - k + 1;
        int m = side * side;
        int k2 = k * k;
        int nchunk = (m + 63) / 64;
        int mpad = nchunk * 64;
        long long Bm = (long long)NB * m;

        prep_w_kernel<<<(k2 * 12 * 32 * PN + 255) / 256, 256>>>(sr_w[h], p_wp, k2);
        conv_hmma_kernel<<<dim3((int)((Bm + 127) / 128), 2), 256>>>(
            p_xh, p_xl, (const uint4*)p_wp, sr_b[h], p_t, k, side, m);
        ln_gelu_kernel<<<NB * m, 192>>>(p_t, ln_g[h], ln_b[h]);

        gemm_nt<<<dim3(2, (NB * m + 127) / 128, 1), 256>>>(
            p_t, 0, NC, kv_w, 0, NC, kv_b, p_kv, 0, 128, NB * m, 128, NC, 1.f);

        prep_q_kernel<<<(NB * NTOK * 64 + 255) / 256, 256>>>(p_q, p_qh, p_ql, h);
        prep_k_kernel<<<(NB * m * 64 + 255) / 256, 256>>>(p_kv, p_kh, p_kl, m);

        dwconv_kernel<<<(int)(((long long)NB * m * 64 + 255) / 256), 256>>>(
            p_kv, lc_w[h], lc_b[h], p_vp, side, m);
        pack_v_kernel<<<(NB * nchunk * 2048 + 255) / 256, 256>>>(p_vp, p_vkh, p_vkl, m, nchunk);

        attn_s_kernel<<<dim3((m + 127) / 128, NTOK / 128, NB), 256, 71680>>>(
            p_qh, p_ql, p_kh, p_kl, p_S, m, mpad);

        softmax_kernel<<<NB * NTOK, 256>>>(p_S, p_Ph, p_Pl, m, mpad);

        attn_pv_kernel<<<dim3(NTOK / 64, NB), 256>>>(
            p_Ph, p_Pl, p_vkh, p_vkl, p_xcat + h * 64, mpad, nchunk);
    }

    gemm_nt<<<dim3(3, 128, 1), 256>>>(p_xcat, 0, NC, nn1_w, 0, NC, nn1_b,
                                      out, 0, NC, NB * NTOK, NC, NC, 1.f);
}

// round 8
// speedup vs baseline: 2.3536x; 1.1261x over previous
#include <cuda_runtime.h>
#include <cuda_bf16.h>
#include <math.h>
#include <stdint.h>

#define NB   4
#define NTOK 4096
#define NC   192
#define MAXM 3969
#define MAXMP 4032                       // max padded m (63*64)
#define PN   104                         // conv B smem word pitch
#define STGW 15872                       // conv stage size in words (Ah4608+Al4608+B6656)

static const float ATT_SCALE = 0.07216878364870323f; // 192^-0.5

// ---------------- scratch -------------------------------------------------------
__device__ float g_q[NB * NTOK * NC];
__device__ float g_t[(size_t)NB * MAXM * NC];
__device__ float g_kv[NB * MAXM * 128];
__device__ float g_vp[NB * MAXM * 64];
__device__ float g_S[(size_t)NB * NTOK * MAXMP];
__device__ float g_xcat[NB * NTOK * NC];
__device__ __nv_bfloat16 g_xh[NB * NTOK * NC];
__device__ __nv_bfloat16 g_xl[NB * NTOK * NC];
__device__ uint32_t g_wpack[768 * 32 * PN];
__device__ __nv_bfloat16 g_qh[NB * NTOK * 64];
__device__ __nv_bfloat16 g_ql[NB * NTOK * 64];
__device__ __nv_bfloat16 g_kh[NB * MAXM * 64];
__device__ __nv_bfloat16 g_kl[NB * MAXM * 64];
__device__ __nv_bfloat16 g_Ph[(size_t)NB * NTOK * MAXMP];
__device__ __nv_bfloat16 g_Pl[(size_t)NB * NTOK * MAXMP];
__device__ uint32_t g_vpkh[NB * 63 * 32 * 64];
__device__ uint32_t g_vpkl[NB * 63 * 32 * 64];

// ---------------- warp helpers ---------------------------------------------------
__device__ __forceinline__ float warpSum(float v) {
#pragma unroll
    for (int o = 16; o; o >>= 1) v += __shfl_xor_sync(0xffffffffu, v, o);
    return v;
}
__device__ __forceinline__ float warpMax(float v) {
#pragma unroll
    for (int o = 16; o; o >>= 1) v = fmaxf(v, __shfl_xor_sync(0xffffffffu, v, o));
    return v;
}
__device__ __forceinline__ uint32_t smem_u32(const void* p) {
    uint32_t a;
    asm("{ .reg .u64 t; cvta.to.shared.u64 t, %1; cvt.u32.u64 %0, t; }" : "=r"(a) : "l"(p));
    return a;
}
#define MMA16816(acc, a, b0, b1)                                                    \
    asm volatile("mma.sync.aligned.m16n8k16.row.col.f32.bf16.bf16.f32 "             \
        "{%0,%1,%2,%3}, {%4,%5,%6,%7}, {%8,%9}, {%0,%1,%2,%3};"                     \
        : "+f"((acc)[0]), "+f"((acc)[1]), "+f"((acc)[2]), "+f"((acc)[3])            \
        : "r"((a)[0]), "r"((a)[1]), "r"((a)[2]), "r"((a)[3]), "r"(b0), "r"(b1))
#define CPA16(dst, src)                                                             \
    asm volatile("cp.async.cg.shared.global [%0], [%1], 16;"                        \
        :: "r"(dst), "l"(src))
#define CPA_COMMIT() asm volatile("cp.async.commit_group;" ::: "memory")
#define CPA_WAIT1()  asm volatile("cp.async.wait_group 1;" ::: "memory")

// ---------------- prep: split x into bf16 hi/lo -----------------------------------
__global__ void prep_x_kernel(const float* __restrict__ x, __nv_bfloat16* __restrict__ xh,
                              __nv_bfloat16* __restrict__ xl) {
    int i = blockIdx.x * 256 + threadIdx.x;
    if (i >= NB * NTOK * NC) return;
    float f = x[i];
    __nv_bfloat16 h = __float2bfloat16(f);
    xh[i] = h;
    xl[i] = __float2bfloat16(f - __bfloat162float(h));
}

// ---------------- prep: W -> packed word images ------------------------------------
__global__ void prep_w_kernel(const float* __restrict__ w, uint32_t* __restrict__ wp,
                              int k2) {
    int idx = blockIdx.x * 256 + threadIdx.x;
    int total = k2 * 12 * 32 * PN;
    if (idx >= total) return;
    int img = idx / (32 * PN), rem = idx % (32 * PN);
    int c2 = rem / PN, n = rem % PN;
    if (n >= 96) { wp[idx] = 0u; return; }
    int tap = img / 12, r = img % 12;
    int cb = r >> 2, r2 = r & 3;
    int cohalf = r2 >> 1, split = r2 & 1;
    int ci = cb * 64 + 2 * c2;
    int co = cohalf * 96 + n;
    float fe = w[((size_t)co * NC + ci) * k2 + tap];
    float fo = w[((size_t)co * NC + ci + 1) * k2 + tap];
    __nv_bfloat16 he = __float2bfloat16(fe), ho = __float2bfloat16(fo);
    __nv_bfloat16 ve = split ? __float2bfloat16(fe - __bfloat162float(he)) : he;
    __nv_bfloat16 vo = split ? __float2bfloat16(fo - __bfloat162float(ho)) : ho;
    uint32_t we = *(const unsigned short*)&ve;
    uint32_t wo = *(const unsigned short*)&vo;
    wp[idx] = (wo << 16) | we;
}

// ---------------- conv as implicit GEMM on HMMA + cp.async double buffer ------------
// CTA: 128 px x 96 co (grid.y = co-half). Dyn smem: 2 stages x (Ah,Al,B0,B1).
__global__ void __launch_bounds__(256) conv_hmma_kernel(
    const __nv_bfloat16* __restrict__ xh, const __nv_bfloat16* __restrict__ xl,
    const uint4* __restrict__ wp, const float* __restrict__ bias,
    float* __restrict__ out, int k, int side, int m)
{
    extern __shared__ uint32_t dsm[];     // 2 * STGW words

    int tid = threadIdx.x;
    int lane = tid & 31, wid = tid >> 5;
    int wm = wid & 1, wn = wid >> 1;
    long long Bm = (long long)NB * m;

    int arow = tid >> 1, ahalf = tid & 1;
    long long apx = (long long)blockIdx.x * 128 + arow;
    long long apxc = apx < Bm - 1 ? apx : Bm - 1;
    int ab = (int)(apxc / m), app = (int)(apxc % m);
    int aoy = app / side, aox = app % side;
    size_t axbase = (size_t)ab * NTOK * NC;
    int half = blockIdx.y;
    int rA = lane >> 2, cA = lane & 3;

    uint32_t smbase = smem_u32(dsm);
    uint32_t aw0 = smbase + (uint32_t)(arow * 36 + ahalf * 16) * 4;  // Ah dst
    uint32_t bw0 = smbase + 9216u * 4;                               // B dst base

    float acc[4][3][4];
#pragma unroll
    for (int i = 0; i < 4; i++)
#pragma unroll
        for (int j = 0; j < 3; j++)
#pragma unroll
            for (int q = 0; q < 4; q++) acc[i][j][q] = 0.f;

    int k2 = k * k;
    int ng = k2 * 3;

    // fill issue for group g into stage s
#define CONV_ISSUE(g, s) do {                                                        \
        int _tap = (g) / 3, _cb = (g) - _tap * 3;                                    \
        int _dy = _tap / k, _dx = _tap - _dy * k;                                    \
        size_t _aoff = axbase + (size_t)((aoy + _dy) * 64 + aox + _dx) * NC          \
                     + _cb * 64 + ahalf * 32;                                        \
        uint32_t _soff = (uint32_t)(s) * (STGW * 4);                                 \
        const char* _gh = (const char*)(xh + _aoff);                                 \
        const char* _gl = (const char*)(xl + _aoff);                                 \
        _Pragma("unroll")                                                            \
        for (int _j = 0; _j < 4; _j++) {                                             \
            CPA16(aw0 + _soff + _j * 16, _gh + _j * 16);                             \
            CPA16(aw0 + _soff + 4608u * 4 + _j * 16, _gl + _j * 16);                 \
        }                                                                            \
        int _imgb = (_tap * 3 + _cb) * 4 + half * 2;                                 \
        const char* _gb = (const char*)(wp + (size_t)_imgb * (32 * PN / 4));         \
        _Pragma("unroll")                                                            \
        for (int _i = 0; _i < 7; _i++) {                                             \
            int _idx = tid + _i * 256;                                               \
            if (_idx < 1664) CPA16(bw0 + _soff + _idx * 16, _gb + (size_t)_idx * 16);\
        }                                                                            \
    } while (0)

    CONV_ISSUE(0, 0);
    CPA_COMMIT();

    for (int g = 0; g < ng; g++) {
        if (g + 1 < ng) CONV_ISSUE(g + 1, (g + 1) & 1);
        CPA_COMMIT();            // always commit (empty group on last iter)
        CPA_WAIT1();             // stage g complete; g+1 may still be in flight
        __syncthreads();

        const uint32_t* stg = dsm + (g & 1) * STGW;
#pragma unroll
        for (int t = 0; t < 3; t++) {
            const uint32_t* A = stg + (t == 2 ? 4608 : 0);
            const uint32_t* Bw = stg + 9216 + (t == 1 ? 3328 : 0);
#pragma unroll
            for (int ks = 0; ks < 4; ks++) {
                uint32_t a[4][4];
#pragma unroll
                for (int i = 0; i < 4; i++) {
                    int r = wm * 64 + i * 16 + rA;
                    int c = 8 * ks + cA;
                    a[i][0] = A[r * 36 + c];
                    a[i][1] = A[(r + 8) * 36 + c];
                    a[i][2] = A[r * 36 + c + 4];
                    a[i][3] = A[(r + 8) * 36 + c + 4];
                }
#pragma unroll
                for (int j = 0; j < 3; j++) {
                    int n = wn * 24 + j * 8 + rA;
                    uint32_t b0 = Bw[(8 * ks + cA) * PN + n];
                    uint32_t b1 = Bw[(8 * ks + 4 + cA) * PN + n];
#pragma unroll
                    for (int i = 0; i < 4; i++) MMA16816(acc[i][j], a[i], b0, b1);
                }
            }
        }
        __syncthreads();         // protect stage (g&1) before iter g+1 overwrites it
    }

#pragma unroll
    for (int i = 0; i < 4; i++) {
        long long row0 = (long long)blockIdx.x * 128 + wm * 64 + i * 16 + rA;
#pragma unroll
        for (int j = 0; j < 3; j++) {
            int col = half * 96 + wn * 24 + j * 8 + 2 * cA;
            float b0 = bias[col], b1 = bias[col + 1];
            if (row0 < Bm) {
                float2 v = make_float2(acc[i][j][0] + b0, acc[i][j][1] + b1);
                *(float2*)&out[row0 * NC + col] = v;
            }
            if (row0 + 8 < Bm) {
                float2 v = make_float2(acc[i][j][2] + b0, acc[i][j][3] + b1);
                *(float2*)&out[(row0 + 8) * NC + col] = v;
            }
        }
    }
#undef CONV_ISSUE
}

// ---------------- prep q / k splits -----------------------------------------------
__global__ void prep_q_kernel(const float* __restrict__ q, __nv_bfloat16* __restrict__ qh,
                              __nv_bfloat16* __restrict__ ql, int h) {
    int i = blockIdx.x * 256 + threadIdx.x;
    if (i >= NB * NTOK * 64) return;
    int c = i & 63;
    int row = i >> 6;
    float f = q[(size_t)row * NC + h * 64 + c];
    __nv_bfloat16 hi = __float2bfloat16(f);
    qh[i] = hi;
    ql[i] = __float2bfloat16(f - __bfloat162float(hi));
}
__global__ void prep_k_kernel(const float* __restrict__ kv, __nv_bfloat16* __restrict__ kh,
                              __nv_bfloat16* __restrict__ kl, int m) {
    int i = blockIdx.x * 256 + threadIdx.x;
    if (i >= NB * m * 64) return;
    int c = i & 63;
    int row = i >> 6;
    float f = kv[(size_t)row * 128 + c];
    __nv_bfloat16 hi = __float2bfloat16(f);
    kh[i] = hi;
    kl[i] = __float2bfloat16(f - __bfloat162float(hi));
}

// ---------------- pack v' into MMA word images --------------------------------------
__global__ void pack_v_kernel(const float* __restrict__ vp, uint32_t* __restrict__ pkh,
                              uint32_t* __restrict__ pkl, int m, int nchunk) {
    int idx = blockIdx.x * 256 + threadIdx.x;
    int total = NB * nchunk * 32 * 64;
    if (idx >= total) return;
    int n = idx & 63;
    int c2 = (idx >> 6) & 31;
    int c = (idx >> 11) % nchunk;
    int b = idx / (nchunk * 2048);
    int k0 = c * 64 + 2 * c2;
    float v0 = (k0 < m) ? vp[((size_t)b * m + k0) * 64 + n] : 0.f;
    float v1 = (k0 + 1 < m) ? vp[((size_t)b * m + k0 + 1) * 64 + n] : 0.f;
    __nv_bfloat16 h0 = __float2bfloat16(v0), h1 = __float2bfloat16(v1);
    __nv_bfloat16 l0 = __float2bfloat16(v0 - __bfloat162float(h0));
    __nv_bfloat16 l1 = __float2bfloat16(v1 - __bfloat162float(h1));
    uint32_t wh = ((uint32_t)*(unsigned short*)&h1 << 16) | *(unsigned short*)&h0;
    uint32_t wl = ((uint32_t)*(unsigned short*)&l1 << 16) | *(unsigned short*)&l0;
    pkh[idx] = wh;
    pkl[idx] = wl;
}

// ---------------- S = scale * q @ k^T via HMMA (row stride mpad, even) ---------------
__global__ void __launch_bounds__(256) attn_s_kernel(
    const __nv_bfloat16* __restrict__ qh, const __nv_bfloat16* __restrict__ ql,
    const __nv_bfloat16* __restrict__ kh, const __nv_bfloat16* __restrict__ kl,
    float* __restrict__ S, int m, int mpad)
{
    extern __shared__ uint32_t dynsm[];
    uint32_t* sQ = dynsm;                 // 2 * 128 * 36
    uint32_t* sK = dynsm + 2 * 128 * 36;  // 2 * 32 * 136

    int tid = threadIdx.x, lane = tid & 31, wid = tid >> 5;
    int wm = wid & 1, wn = wid >> 1;
    int rA = lane >> 2, cA = lane & 3;
    int b = blockIdx.z;
    int mq0 = blockIdx.y * 128;
    int n0 = blockIdx.x * 128;

    {   // q fill (both splits)
        int arow = tid >> 1, ahalf = tid & 1;
        size_t off = ((size_t)b * NTOK + mq0 + arow) * 64 + ahalf * 32;
        const uint4* sh = (const uint4*)(qh + off);
        const uint4* sl = (const uint4*)(ql + off);
        uint32_t* dh = sQ + arow * 36 + ahalf * 16;
        uint32_t* dl = sQ + 128 * 36 + arow * 36 + ahalf * 16;
#pragma unroll
        for (int j = 0; j < 4; j++) { *(uint4*)&dh[j * 4] = sh[j]; *(uint4*)&dl[j * 4] = sl[j]; }
    }
    {   // k fill with transpose into [c2][n] images
        int n = tid >> 1, half = tid & 1;
        int ng = n0 + n;
        int ok = ng < m;
        size_t roff = ((size_t)b * m + (ok ? ng : 0)) * 64;
        const uint4* rh = (const uint4*)(kh + roff);
        const uint4* rl = (const uint4*)(kl + roff);
#pragma unroll
        for (int jj = 0; jj < 4; jj++) {
            uint4 vh = rh[half * 4 + jj];
            uint4 vl = rl[half * 4 + jj];
            if (!ok) { vh = make_uint4(0, 0, 0, 0); vl = vh; }
            int c2 = half * 16 + jj * 4;
            sK[(c2 + 0) * 136 + n] = vh.x;
            sK[(c2 + 1) * 136 + n] = vh.y;
            sK[(c2 + 2) * 136 + n] = vh.z;
            sK[(c2 + 3) * 136 + n] = vh.w;
            sK[32 * 136 + (c2 + 0) * 136 + n] = vl.x;
            sK[32 * 136 + (c2 + 1) * 136 + n] = vl.y;
            sK[32 * 136 + (c2 + 2) * 136 + n] = vl.z;
            sK[32 * 136 + (c2 + 3) * 136 + n] = vl.w;
        }
    }
    __syncthreads();

    float acc[4][4][4];
#pragma unroll
    for (int i = 0; i < 4; i++)
#pragma unroll
        for (int j = 0; j < 4; j++)
#pragma unroll
            for (int q = 0; q < 4; q++) acc[i][j][q] = 0.f;

    // terms: (qh,kh), (qh,kl), (ql,kh)
#pragma unroll
    for (int t = 0; t < 3; t++) {
        const uint32_t* A = sQ + (t == 2 ? 128 * 36 : 0);
        const uint32_t* Bk = sK + (t == 1 ? 32 * 136 : 0);
#pragma unroll
        for (int ks = 0; ks < 4; ks++) {
            uint32_t a[4][4];
#pragma unroll
            for (int i = 0; i < 4; i++) {
                int r = wm * 64 + i * 16 + rA;
                int c = 8 * ks + cA;
                a[i][0] = A[r * 36 + c];
                a[i][1] = A[(r + 8) * 36 + c];
                a[i][2] = A[r * 36 + c + 4];
                a[i][3] = A[(r + 8) * 36 + c + 4];
            }
#pragma unroll
            for (int j = 0; j < 4; j++) {
                int n = wn * 32 + j * 8 + rA;
                uint32_t b0 = Bk[(8 * ks + cA) * 136 + n];
                uint32_t b1 = Bk[(8 * ks + 4 + cA) * 136 + n];
#pragma unroll
                for (int i = 0; i < 4; i++) MMA16816(acc[i][j], a[i], b0, b1);
            }
        }
    }

    // epilogue: S (fp32, padded row stride mpad — float2 always 8B-aligned)
#pragma unroll
    for (int i = 0; i < 4; i++) {
        size_t row0 = (size_t)b * NTOK + mq0 + wm * 64 + i * 16 + rA;
#pragma unroll
        for (int j = 0; j < 4; j++) {
            int col = n0 + wn * 32 + j * 8 + 2 * cA;
            if (col + 1 < m) {
                *(float2*)&S[row0 * mpad + col] =
                    make_float2(acc[i][j][0] * ATT_SCALE, acc[i][j][1] * ATT_SCALE);
                *(float2*)&S[(row0 + 8) * mpad + col] =
                    make_float2(acc[i][j][2] * ATT_SCALE, acc[i][j][3] * ATT_SCALE);
            } else if (col < m) {
                S[row0 * mpad + col] = acc[i][j][0] * ATT_SCALE;
                S[(row0 + 8) * mpad + col] = acc[i][j][2] * ATT_SCALE;
            }
        }
    }
}

// ---------------- row softmax (stride mpad) -> split bf16 P (padded) -----------------
__global__ void softmax_kernel(const float* __restrict__ S, __nv_bfloat16* __restrict__ Ph,
                               __nv_bfloat16* __restrict__ Pl, int m, int mpad) {
    size_t row = blockIdx.x;
    const float* r = S + row * (size_t)mpad;
    int tid = threadIdx.x;
    float lv[16];
    int cnt = 0;
    float mx = -1e30f;
    for (int j = tid; j < m; j += 256) {
        float v = r[j];
        lv[cnt++] = v;
        if (v > mx) mx = v;
    }
    __shared__ float sm[8];
    int lane = tid & 31, w = tid >> 5;
    float tmp = warpMax(mx);
    if (lane == 0) sm[w] = tmp;
    __syncthreads();
    mx = -1e30f;
#pragma unroll
    for (int i = 0; i < 8; i++) mx = fmaxf(mx, sm[i]);
    float sum = 0.f;
    for (int i = 0; i < cnt; i++) {
        float e = __expf(lv[i] - mx);
        lv[i] = e;
        sum += e;
    }
    __syncthreads();
    tmp = warpSum(sum);
    if (lane == 0) sm[w] = tmp;
    __syncthreads();
    sum = 0.f;
#pragma unroll
    for (int i = 0; i < 8; i++) sum += sm[i];
    float inv = 1.f / sum;
    __nv_bfloat16* ph = Ph + row * (size_t)mpad;
    __nv_bfloat16* pl = Pl + row * (size_t)mpad;
    cnt = 0;
    for (int j = tid; j < mpad; j += 256) {
        if (j < m) {
            float p = lv[cnt++] * inv;
            __nv_bfloat16 hp = __float2bfloat16(p);
            ph[j] = hp;
            pl[j] = __float2bfloat16(p - __bfloat162float(hp));
        } else {
            ph[j] = __float2bfloat16(0.f);
            pl[j] = __float2bfloat16(0.f);
        }
    }
}

// ---------------- PV: out_h = P @ v' via HMMA ----------------------------------------
// CTA 64(rows) x 64(v cols); warps 4(M)x2(N), each warp 16 rows x 32 cols.
__global__ void __launch_bounds__(256) attn_pv_kernel(
    const __nv_bfloat16* __restrict__ Ph, const __nv_bfloat16* __restrict__ Pl,
    const uint32_t* __restrict__ pkh, const uint32_t* __restrict__ pkl,
    float* __restrict__ out, int mpad, int nchunk)
{
    __shared__ alignas(16) uint32_t sP[2 * 64 * 36];
    __shared__ alignas(16) uint32_t sV[2 * 32 * 72];

    int tid = threadIdx.x, lane = tid & 31, wid = tid >> 5;
    int wm = wid & 3, wn = wid >> 2;
    int rA = lane >> 2, cA = lane & 3;
    int b = blockIdx.y;
    int m0 = blockIdx.x * 64;

    int arow = tid >> 2, aq = tid & 3;
    size_t abase = ((size_t)b * NTOK + m0 + arow) * mpad;

    float acc[4][4];
#pragma unroll
    for (int j = 0; j < 4; j++)
#pragma unroll
        for (int q = 0; q < 4; q++) acc[j][q] = 0.f;

    for (int c = 0; c < nchunk; c++) {
        __syncthreads();
        {
            size_t off = abase + c * 64 + aq * 16;
            const uint4* sh = (const uint4*)(Ph + off);
            const uint4* sl = (const uint4*)(Pl + off);
            uint32_t* dh = sP + arow * 36 + aq * 8;
            uint32_t* dl = sP + 64 * 36 + arow * 36 + aq * 8;
            *(uint4*)&dh[0] = sh[0]; *(uint4*)&dh[4] = sh[1];
            *(uint4*)&dl[0] = sl[0]; *(uint4*)&dl[4] = sl[1];
        }
        {
            size_t gb = ((size_t)b * nchunk + c) * 2048;
#pragma unroll
            for (int t = 0; t < 8; t++) {
                int idx = tid + t * 256;
                int c2 = idx >> 6, n = idx & 63;
                sV[c2 * 72 + n] = pkh[gb + idx];
                sV[32 * 72 + c2 * 72 + n] = pkl[gb + idx];
            }
        }
        __syncthreads();

#pragma unroll
        for (int t = 0; t < 3; t++) {
            const uint32_t* A = sP + (t == 2 ? 64 * 36 : 0);
            const uint32_t* Bv = sV + (t == 1 ? 32 * 72 : 0);
#pragma unroll
            for (int ks = 0; ks < 4; ks++) {
                uint32_t a[4];
                int r = wm * 16 + rA;
                int cc = 8 * ks + cA;
                a[0] = A[r * 36 + cc];
                a[1] = A[(r + 8) * 36 + cc];
                a[2] = A[r * 36 + cc + 4];
                a[3] = A[(r + 8) * 36 + cc + 4];
#pragma unroll
                for (int j = 0; j < 4; j++) {
                    int n = wn * 32 + j * 8 + rA;
                    uint32_t b0 = Bv[(8 * ks + cA) * 72 + n];
                    uint32_t b1 = Bv[(8 * ks + 4 + cA) * 72 + n];
                    MMA16816(acc[j], a, b0, b1);
                }
            }
        }
    }

    size_t row0 = (size_t)b * NTOK + m0 + wm * 16 + rA;
#pragma unroll
    for (int j = 0; j < 4; j++) {
        int col = wn * 32 + j * 8 + 2 * cA;
        *(float2*)&out[row0 * NC + col] = make_float2(acc[j][0], acc[j][1]);
        *(float2*)&out[(row0 + 8) * NC + col] = make_float2(acc[j][2], acc[j][3]);
    }
}

// ---------------- LayerNorm + exact GELU --------------------------------------------
__global__ void ln_gelu_kernel(float* __restrict__ t, const float* __restrict__ g,
                               const float* __restrict__ bb) {
    size_t row = blockIdx.x;
    int tid = threadIdx.x;
    float v = t[row * NC + tid];
    __shared__ float sm[6];
    int lane = tid & 31, w = tid >> 5;
    float s = warpSum(v);
    if (lane == 0) sm[w] = s;
    __syncthreads();
    float mean = 0.f;
#pragma unroll
    for (int i = 0; i < 6; i++) mean += sm[i];
    mean *= (1.0f / 192.0f);
    float d = v - mean;
    __syncthreads();
    s = warpSum(d * d);
    if (lane == 0) sm[w] = s;
    __syncthreads();
    float var = 0.f;
#pragma unroll
    for (int i = 0; i < 6; i++) var += sm[i];
    var *= (1.0f / 192.0f);
    float y = d * rsqrtf(var + 1e-5f) * g[tid] + bb[tid];
    t[row * NC + tid] = y * normcdff(y);
}

// ---------------- generic NT GEMM (projections) --------------------------------------
__global__ void __launch_bounds__(256) gemm_nt(
    const float* __restrict__ A, long long sA, int lda,
    const float* __restrict__ W, long long sW, int ldw,
    const float* __restrict__ bias,
    float* __restrict__ C, long long sC, int ldc,
    int M, int Nn, int K, float scale)
{
    __shared__ float As[16][132];
    __shared__ float Ws[16][68];
    int bz = blockIdx.z;
    const float* Ab = A + sA * bz;
    const float* Wb = W + sW * bz;
    float* Cb = C + sC * bz;
    int n0 = blockIdx.x * 64, m0 = blockIdx.y * 128;
    int tid = threadIdx.x;
    int tx = tid & 15, ty = tid >> 4;
    float acc[8][4];
#pragma unroll
    for (int i = 0; i < 8; i++)
#pragma unroll
        for (int j = 0; j < 4; j++) acc[i][j] = 0.f;

    for (int k0 = 0; k0 < K; k0 += 16) {
#pragma unroll
        for (int j = 0; j < 8; j++) {
            int idx = tid + j * 256;
            int kk = idx & 15, mm = idx >> 4;
            int gm = m0 + mm, gk = k0 + kk;
            As[kk][mm] = (gm < M && gk < K) ? Ab[(size_t)gm * lda + gk] : 0.f;
        }
#pragma unroll
        for (int j = 0; j < 4; j++) {
            int idx = tid + j * 256;
            int kk = idx & 15, nn = idx >> 4;
            int gn = n0 + nn, gk = k0 + kk;
            Ws[kk][nn] = (gn < Nn && gk < K) ? Wb[(size_t)gn * ldw + gk] : 0.f;
        }
        __syncthreads();
#pragma unroll
        for (int kk = 0; kk < 16; kk++) {
            float a[8], w[4];
#pragma unroll
            for (int i = 0; i < 8; i++) a[i] = As[kk][ty * 8 + i];
#pragma unroll
            for (int j = 0; j < 4; j++) w[j] = Ws[kk][tx * 4 + j];
#pragma unroll
            for (int i = 0; i < 8; i++)
#pragma unroll
                for (int j = 0; j < 4; j++) acc[i][j] = fmaf(a[i], w[j], acc[i][j]);
        }
        __syncthreads();
    }
#pragma unroll
    for (int i = 0; i < 8; i++) {
        int gm = m0 + ty * 8 + i;
        if (gm >= M) continue;
#pragma unroll
        for (int j = 0; j < 4; j++) {
            int gn = n0 + tx * 4 + j;
            if (gn < Nn) {
                float v = acc[i][j] * scale;
                if (bias) v += bias[gn];
                Cb[(size_t)gm * ldc + gn] = v;
            }
        }
    }
}

// ---------------- depthwise 3x3 on v, residual add -----------------------------------
__global__ void dwconv_kernel(const float* __restrict__ kv, const float* __restrict__ lw,
                              const float* __restrict__ lb, float* __restrict__ vp,
                              int side, int m)
{
    long long idx = (long long)blockIdx.x * 256 + threadIdx.x;
    long long total = (long long)NB * m * 64;
    if (idx >= total) return;
    int hd = (int)(idx & 63);
    long long pm = idx >> 6;
    int p = (int)(pm % m);
    int b = (int)(pm / m);
    int y = p / side, x = p % side;
    const float* vbase = kv + (size_t)b * m * 128 + 64 + hd;
    float s = lb[hd];
#pragma unroll
    for (int dy = 0; dy < 3; dy++) {
        int yy = y + dy - 1;
        if (yy < 0 || yy >= side) continue;
#pragma unroll
        for (int dx = 0; dx < 3; dx++) {
            int xx = x + dx - 1;
            if (xx < 0 || xx >= side) continue;
            s += lw[hd * 9 + dy * 3 + dx] * vbase[(size_t)(yy * side + xx) * 128];
        }
    }
    vp[idx] = vbase[(size_t)p * 128] + s;
}

// ---------------- host orchestration ---------------------------------------------------
extern "C" void kernel_launch(void* const* d_in, const int* in_sizes, int n_in,
                              void* d_out, int out_size)
{
    (void)in_sizes; (void)n_in; (void)out_size;
    const float* x    = (const float*)d_in[0];
    const float* q_w  = (const float*)d_in[1];
    const float* q_b  = (const float*)d_in[2];
    const float* kv_w = (const float*)d_in[3];
    const float* kv_b = (const float*)d_in[4];
    const float* sr_w[3] = {(const float*)d_in[5], (const float*)d_in[7], (const float*)d_in[9]};
    const float* sr_b[3] = {(const float*)d_in[6], (const float*)d_in[8], (const float*)d_in[10]};
    const float* ln_g[3] = {(const float*)d_in[11], (const float*)d_in[13], (const float*)d_in[15]};
    const float* ln_b[3] = {(const float*)d_in[12], (const float*)d_in[14], (const float*)d_in[16]};
    const float* lc_w[3] = {(const float*)d_in[17], (const float*)d_in[19], (const float*)d_in[21]};
    const float* lc_b[3] = {(const float*)d_in[18], (const float*)d_in[20], (const float*)d_in[22]};
    const float* nn1_w = (const float*)d_in[23];
    const float* nn1_b = (const float*)d_in[24];
    float* out = (float*)d_out;

    float *p_q, *p_t, *p_kv, *p_vp, *p_S, *p_xcat;
    __nv_bfloat16 *p_xh, *p_xl, *p_qh, *p_ql, *p_kh, *p_kl, *p_Ph, *p_Pl;
    uint32_t *p_wp, *p_vkh, *p_vkl;
    cudaGetSymbolAddress((void**)&p_q,    g_q);
    cudaGetSymbolAddress((void**)&p_t,    g_t);
    cudaGetSymbolAddress((void**)&p_kv,   g_kv);
    cudaGetSymbolAddress((void**)&p_vp,   g_vp);
    cudaGetSymbolAddress((void**)&p_S,    g_S);
    cudaGetSymbolAddress((void**)&p_xcat, g_xcat);
    cudaGetSymbolAddress((void**)&p_xh,   g_xh);
    cudaGetSymbolAddress((void**)&p_xl,   g_xl);
    cudaGetSymbolAddress((void**)&p_wp,   g_wpack);
    cudaGetSymbolAddress((void**)&p_qh,   g_qh);
    cudaGetSymbolAddress((void**)&p_ql,   g_ql);
    cudaGetSymbolAddress((void**)&p_kh,   g_kh);
    cudaGetSymbolAddress((void**)&p_kl,   g_kl);
    cudaGetSymbolAddress((void**)&p_Ph,   g_Ph);
    cudaGetSymbolAddress((void**)&p_Pl,   g_Pl);
    cudaGetSymbolAddress((void**)&p_vkh,  g_vpkh);
    cudaGetSymbolAddress((void**)&p_vkl,  g_vpkl);

    cudaFuncSetAttribute(attn_s_kernel, cudaFuncAttributeMaxDynamicSharedMemorySize, 71680);
    cudaFuncSetAttribute(conv_hmma_kernel, cudaFuncAttributeMaxDynamicSharedMemorySize,
                         2 * STGW * 4);

    prep_x_kernel<<<(NB * NTOK * NC + 255) / 256, 256>>>(x, p_xh, p_xl);

    gemm_nt<<<dim3(3, 128, 1), 256>>>(x, 0, NC, q_w, 0, NC, q_b,
                                      p_q, 0, NC, NB * NTOK, NC, NC, 1.f);

    const int KS[3] = {8, 4, 2};
    for (int h = 0; h < 3; h++) {
        int k = KS[h];
        int side = 64 - k + 1;
        int m = side * side;
        int k2 = k * k;
        int nchunk = (m + 63) / 64;
        int mpad = nchunk * 64;
        long long Bm = (long long)NB * m;

        prep_w_kernel<<<(k2 * 12 * 32 * PN + 255) / 256, 256>>>(sr_w[h], p_wp, k2);
        conv_hmma_kernel<<<dim3((int)((Bm + 127) / 128), 2), 256, 2 * STGW * 4>>>(
            p_xh, p_xl, (const uint4*)p_wp, sr_b[h], p_t, k, side, m);
        ln_gelu_kernel<<<NB * m, 192>>>(p_t, ln_g[h], ln_b[h]);

        gemm_nt<<<dim3(2, (NB * m + 127) / 128, 1), 256>>>(
            p_t, 0, NC, kv_w, 0, NC, kv_b, p_kv, 0, 128, NB * m, 128, NC, 1.f);

        prep_q_kernel<<<(NB * NTOK * 64 + 255) / 256, 256>>>(p_q, p_qh, p_ql, h);
        prep_k_kernel<<<(NB * m * 64 + 255) / 256, 256>>>(p_kv, p_kh, p_kl, m);

        dwconv_kernel<<<(int)(((long long)NB * m * 64 + 255) / 256), 256>>>(
            p_kv, lc_w[h], lc_b[h], p_vp, side, m);
        pack_v_kernel<<<(NB * nchunk * 2048 + 255) / 256, 256>>>(p_vp, p_vkh, p_vkl, m, nchunk);

        attn_s_kernel<<<dim3((m + 127) / 128, NTOK / 128, NB), 256, 71680>>>(
            p_qh, p_ql, p_kh, p_kl, p_S, m, mpad);

        softmax_kernel<<<NB * NTOK, 256>>>(p_S, p_Ph, p_Pl, m, mpad);

        attn_pv_kernel<<<dim3(NTOK / 64, NB), 256>>>(
            p_Ph, p_Pl, p_vkh, p_vkl, p_xcat + h * 64, mpad, nchunk);
    }

    gemm_nt<<<dim3(3, 128, 1), 256>>>(p_xcat, 0, NC, nn1_w, 0, NC, nn1_b,
                                      out, 0, NC, NB * NTOK, NC, NC, 1.f);
}

// round 9
// speedup vs baseline: 2.7224x; 1.1567x over previous
#include <cuda_runtime.h>
#include <cuda_bf16.h>
#include <math.h>
#include <stdint.h>

#define NB   4
#define NTOK 4096
#define NC   192
#define MAXM 3969
#define MAXMP 4032                       // max padded m (63*64)
#define PN   104                         // conv B smem word pitch
#define CSTGW 11264                      // conv stage words: Ah2304+Al2304+B6656

static const float ATT_SCALE = 0.07216878364870323f; // 192^-0.5

// ---------------- scratch -------------------------------------------------------
__device__ float g_q[NB * NTOK * NC];
__device__ float g_t[(size_t)NB * MAXM * NC];
__device__ float g_kv[NB * MAXM * 128];
__device__ float g_vp[NB * MAXM * 64];
__device__ float g_S[(size_t)NB * NTOK * MAXMP];
__device__ float g_xcat[NB * NTOK * NC];
__device__ __nv_bfloat16 g_xh[NB * NTOK * NC];
__device__ __nv_bfloat16 g_xl[NB * NTOK * NC];
__device__ uint32_t g_wpack[768 * 32 * PN];
__device__ __nv_bfloat16 g_qh[NB * NTOK * 64];
__device__ __nv_bfloat16 g_ql[NB * NTOK * 64];
__device__ __nv_bfloat16 g_kh[NB * MAXM * 64];
__device__ __nv_bfloat16 g_kl[NB * MAXM * 64];
__device__ __nv_bfloat16 g_Ph[(size_t)NB * NTOK * MAXMP];
__device__ __nv_bfloat16 g_Pl[(size_t)NB * NTOK * MAXMP];
__device__ uint32_t g_vpkh[NB * 63 * 32 * 64];
__device__ uint32_t g_vpkl[NB * 63 * 32 * 64];

// ---------------- warp helpers ---------------------------------------------------
__device__ __forceinline__ float warpSum(float v) {
#pragma unroll
    for (int o = 16; o; o >>= 1) v += __shfl_xor_sync(0xffffffffu, v, o);
    return v;
}
__device__ __forceinline__ float warpMax(float v) {
#pragma unroll
    for (int o = 16; o; o >>= 1) v = fmaxf(v, __shfl_xor_sync(0xffffffffu, v, o));
    return v;
}
__device__ __forceinline__ uint32_t smem_u32(const void* p) {
    uint32_t a;
    asm("{ .reg .u64 t; cvta.to.shared.u64 t, %1; cvt.u32.u64 %0, t; }" : "=r"(a) : "l"(p));
    return a;
}
#define MMA16816(acc, a, b0, b1)                                                    \
    asm volatile("mma.sync.aligned.m16n8k16.row.col.f32.bf16.bf16.f32 "             \
        "{%0,%1,%2,%3}, {%4,%5,%6,%7}, {%8,%9}, {%0,%1,%2,%3};"                     \
        : "+f"((acc)[0]), "+f"((acc)[1]), "+f"((acc)[2]), "+f"((acc)[3])            \
        : "r"((a)[0]), "r"((a)[1]), "r"((a)[2]), "r"((a)[3]), "r"(b0), "r"(b1))
#define CPA16(dst, src)                                                             \
    asm volatile("cp.async.cg.shared.global [%0], [%1], 16;"                        \
        :: "r"(dst), "l"(src))
#define CPA_COMMIT() asm volatile("cp.async.commit_group;" ::: "memory")
#define CPA_WAIT1()  asm volatile("cp.async.wait_group 1;" ::: "memory")

// ---------------- prep: split x into bf16 hi/lo -----------------------------------
__global__ void prep_x_kernel(const float* __restrict__ x, __nv_bfloat16* __restrict__ xh,
                              __nv_bfloat16* __restrict__ xl) {
    int i = blockIdx.x * 256 + threadIdx.x;
    if (i >= NB * NTOK * NC) return;
    float f = x[i];
    __nv_bfloat16 h = __float2bfloat16(f);
    xh[i] = h;
    xl[i] = __float2bfloat16(f - __bfloat162float(h));
}

// ---------------- prep: W -> packed word images ------------------------------------
__global__ void prep_w_kernel(const float* __restrict__ w, uint32_t* __restrict__ wp,
                              int k2) {
    int idx = blockIdx.x * 256 + threadIdx.x;
    int total = k2 * 12 * 32 * PN;
    if (idx >= total) return;
    int img = idx / (32 * PN), rem = idx % (32 * PN);
    int c2 = rem / PN, n = rem % PN;
    if (n >= 96) { wp[idx] = 0u; return; }
    int tap = img / 12, r = img % 12;
    int cb = r >> 2, r2 = r & 3;
    int cohalf = r2 >> 1, split = r2 & 1;
    int ci = cb * 64 + 2 * c2;
    int co = cohalf * 96 + n;
    float fe = w[((size_t)co * NC + ci) * k2 + tap];
    float fo = w[((size_t)co * NC + ci + 1) * k2 + tap];
    __nv_bfloat16 he = __float2bfloat16(fe), ho = __float2bfloat16(fo);
    __nv_bfloat16 ve = split ? __float2bfloat16(fe - __bfloat162float(he)) : he;
    __nv_bfloat16 vo = split ? __float2bfloat16(fo - __bfloat162float(ho)) : ho;
    uint32_t we = *(const unsigned short*)&ve;
    uint32_t wo = *(const unsigned short*)&vo;
    wp[idx] = (wo << 16) | we;
}

// ---------------- conv: implicit GEMM, HMMA, cp.async x2, 64px tile, frag reuse -----
// CTA: 64 px x 96 co (grid.y = co-half). 8 warps: wm in {0,1} (32px), wn in {0..3} (24co).
__global__ void __launch_bounds__(256, 2) conv_hmma_kernel(
    const __nv_bfloat16* __restrict__ xh, const __nv_bfloat16* __restrict__ xl,
    const uint4* __restrict__ wp, const float* __restrict__ bias,
    float* __restrict__ out, int k, int side, int m)
{
    extern __shared__ uint32_t dsm[];     // 2 * CSTGW words

    int tid = threadIdx.x;
    int lane = tid & 31, wid = tid >> 5;
    int wm = wid & 1, wn = wid >> 1;
    long long Bm = (long long)NB * m;

    int arow = tid >> 2, aq = tid & 3;   // 64 rows x 4 threads, 16 elems (32B) each
    long long apx = (long long)blockIdx.x * 64 + arow;
    long long apxc = apx < Bm - 1 ? apx : Bm - 1;
    int ab = (int)(apxc / m), app = (int)(apxc % m);
    int aoy = app / side, aox = app % side;
    size_t axbase = (size_t)ab * NTOK * NC;
    int half = blockIdx.y;
    int rA = lane >> 2, cA = lane & 3;

    uint32_t smbase = smem_u32(dsm);
    uint32_t awd = smbase + (uint32_t)(arow * 36 + aq * 8) * 4;   // A dst (hi)
    uint32_t bwd = smbase + 4608u * 4;                            // B dst base

    float acc[2][3][4];
#pragma unroll
    for (int i = 0; i < 2; i++)
#pragma unroll
        for (int j = 0; j < 3; j++)
#pragma unroll
            for (int q = 0; q < 4; q++) acc[i][j][q] = 0.f;

    int k2 = k * k;
    int ng = k2 * 3;

#define CONV_ISSUE(g, s) do {                                                        \
        int _tap = (g) / 3, _cb = (g) - _tap * 3;                                    \
        int _dy = _tap / k, _dx = _tap - _dy * k;                                    \
        size_t _aoff = axbase + (size_t)((aoy + _dy) * 64 + aox + _dx) * NC          \
                     + _cb * 64 + aq * 16;                                           \
        uint32_t _soff = (uint32_t)(s) * (CSTGW * 4);                                \
        const char* _gh = (const char*)(xh + _aoff);                                 \
        const char* _gl = (const char*)(xl + _aoff);                                 \
        CPA16(awd + _soff,      _gh);                                                \
        CPA16(awd + _soff + 16, _gh + 16);                                           \
        CPA16(awd + _soff + 2304u * 4,      _gl);                                    \
        CPA16(awd + _soff + 2304u * 4 + 16, _gl + 16);                               \
        int _imgb = (_tap * 3 + _cb) * 4 + half * 2;                                 \
        const char* _gb = (const char*)(wp + (size_t)_imgb * (32 * PN / 4));         \
        _Pragma("unroll")                                                            \
        for (int _i = 0; _i < 7; _i++) {                                             \
            int _idx = tid + _i * 256;                                               \
            if (_idx < 1664) CPA16(bwd + _soff + _idx * 16, _gb + (size_t)_idx * 16);\
        }                                                                            \
    } while (0)

    CONV_ISSUE(0, 0);
    CPA_COMMIT();

    for (int g = 0; g < ng; g++) {
        if (g + 1 < ng) CONV_ISSUE(g + 1, (g + 1) & 1);
        CPA_COMMIT();
        CPA_WAIT1();
        __syncthreads();

        const uint32_t* stg = dsm + (g & 1) * CSTGW;
        const uint32_t* Ah = stg;
        const uint32_t* Al = stg + 2304;
        const uint32_t* B0 = stg + 4608;
        const uint32_t* B1 = stg + 7936;

#pragma unroll
        for (int ks = 0; ks < 4; ks++) {
            uint32_t ah[2][4], al[2][4];
#pragma unroll
            for (int i = 0; i < 2; i++) {
                int r = wm * 32 + i * 16 + rA;
                int c = 8 * ks + cA;
                ah[i][0] = Ah[r * 36 + c];
                ah[i][1] = Ah[(r + 8) * 36 + c];
                ah[i][2] = Ah[r * 36 + c + 4];
                ah[i][3] = Ah[(r + 8) * 36 + c + 4];
                al[i][0] = Al[r * 36 + c];
                al[i][1] = Al[(r + 8) * 36 + c];
                al[i][2] = Al[r * 36 + c + 4];
                al[i][3] = Al[(r + 8) * 36 + c + 4];
            }
            uint32_t b0[3][2], b1[3][2];
#pragma unroll
            for (int j = 0; j < 3; j++) {
                int n = wn * 24 + j * 8 + rA;
                b0[j][0] = B0[(8 * ks + cA) * PN + n];
                b0[j][1] = B0[(8 * ks + 4 + cA) * PN + n];
                b1[j][0] = B1[(8 * ks + cA) * PN + n];
                b1[j][1] = B1[(8 * ks + 4 + cA) * PN + n];
            }
#pragma unroll
            for (int i = 0; i < 2; i++)
#pragma unroll
                for (int j = 0; j < 3; j++) {
                    MMA16816(acc[i][j], ah[i], b0[j][0], b0[j][1]);
                    MMA16816(acc[i][j], ah[i], b1[j][0], b1[j][1]);
                    MMA16816(acc[i][j], al[i], b0[j][0], b0[j][1]);
                }
        }
        __syncthreads();
    }

#pragma unroll
    for (int i = 0; i < 2; i++) {
        long long row0 = (long long)blockIdx.x * 64 + wm * 32 + i * 16 + rA;
#pragma unroll
        for (int j = 0; j < 3; j++) {
            int col = half * 96 + wn * 24 + j * 8 + 2 * cA;
            float b0 = bias[col], b1 = bias[col + 1];
            if (row0 < Bm) {
                float2 v = make_float2(acc[i][j][0] + b0, acc[i][j][1] + b1);
                *(float2*)&out[row0 * NC + col] = v;
            }
            if (row0 + 8 < Bm) {
                float2 v = make_float2(acc[i][j][2] + b0, acc[i][j][3] + b1);
                *(float2*)&out[(row0 + 8) * NC + col] = v;
            }
        }
    }
#undef CONV_ISSUE
}

// ---------------- prep q / k splits -----------------------------------------------
__global__ void prep_q_kernel(const float* __restrict__ q, __nv_bfloat16* __restrict__ qh,
                              __nv_bfloat16* __restrict__ ql, int h) {
    int i = blockIdx.x * 256 + threadIdx.x;
    if (i >= NB * NTOK * 64) return;
    int c = i & 63;
    int row = i >> 6;
    float f = q[(size_t)row * NC + h * 64 + c];
    __nv_bfloat16 hi = __float2bfloat16(f);
    qh[i] = hi;
    ql[i] = __float2bfloat16(f - __bfloat162float(hi));
}
__global__ void prep_k_kernel(const float* __restrict__ kv, __nv_bfloat16* __restrict__ kh,
                              __nv_bfloat16* __restrict__ kl, int m) {
    int i = blockIdx.x * 256 + threadIdx.x;
    if (i >= NB * m * 64) return;
    int c = i & 63;
    int row = i >> 6;
    float f = kv[(size_t)row * 128 + c];
    __nv_bfloat16 hi = __float2bfloat16(f);
    kh[i] = hi;
    kl[i] = __float2bfloat16(f - __bfloat162float(hi));
}

// ---------------- pack v' into MMA word images --------------------------------------
__global__ void pack_v_kernel(const float* __restrict__ vp, uint32_t* __restrict__ pkh,
                              uint32_t* __restrict__ pkl, int m, int nchunk) {
    int idx = blockIdx.x * 256 + threadIdx.x;
    int total = NB * nchunk * 32 * 64;
    if (idx >= total) return;
    int n = idx & 63;
    int c2 = (idx >> 6) & 31;
    int c = (idx >> 11) % nchunk;
    int b = idx / (nchunk * 2048);
    int k0 = c * 64 + 2 * c2;
    float v0 = (k0 < m) ? vp[((size_t)b * m + k0) * 64 + n] : 0.f;
    float v1 = (k0 + 1 < m) ? vp[((size_t)b * m + k0 + 1) * 64 + n] : 0.f;
    __nv_bfloat16 h0 = __float2bfloat16(v0), h1 = __float2bfloat16(v1);
    __nv_bfloat16 l0 = __float2bfloat16(v0 - __bfloat162float(h0));
    __nv_bfloat16 l1 = __float2bfloat16(v1 - __bfloat162float(h1));
    uint32_t wh = ((uint32_t)*(unsigned short*)&h1 << 16) | *(unsigned short*)&h0;
    uint32_t wl = ((uint32_t)*(unsigned short*)&l1 << 16) | *(unsigned short*)&l0;
    pkh[idx] = wh;
    pkl[idx] = wl;
}

// ---------------- S = scale * q @ k^T via HMMA (row stride mpad, even) ---------------
__global__ void __launch_bounds__(256) attn_s_kernel(
    const __nv_bfloat16* __restrict__ qh, const __nv_bfloat16* __restrict__ ql,
    const __nv_bfloat16* __restrict__ kh, const __nv_bfloat16* __restrict__ kl,
    float* __restrict__ S, int m, int mpad)
{
    extern __shared__ uint32_t dynsm[];
    uint32_t* sQ = dynsm;                 // 2 * 128 * 36
    uint32_t* sK = dynsm + 2 * 128 * 36;  // 2 * 32 * 136

    int tid = threadIdx.x, lane = tid & 31, wid = tid >> 5;
    int wm = wid & 1, wn = wid >> 1;
    int rA = lane >> 2, cA = lane & 3;
    int b = blockIdx.z;
    int mq0 = blockIdx.y * 128;
    int n0 = blockIdx.x * 128;

    {   // q fill (both splits)
        int arow = tid >> 1, ahalf = tid & 1;
        size_t off = ((size_t)b * NTOK + mq0 + arow) * 64 + ahalf * 32;
        const uint4* sh = (const uint4*)(qh + off);
        const uint4* sl = (const uint4*)(ql + off);
        uint32_t* dh = sQ + arow * 36 + ahalf * 16;
        uint32_t* dl = sQ + 128 * 36 + arow * 36 + ahalf * 16;
#pragma unroll
        for (int j = 0; j < 4; j++) { *(uint4*)&dh[j * 4] = sh[j]; *(uint4*)&dl[j * 4] = sl[j]; }
    }
    {   // k fill with transpose into [c2][n] images
        int n = tid >> 1, half = tid & 1;
        int ng = n0 + n;
        int ok = ng < m;
        size_t roff = ((size_t)b * m + (ok ? ng : 0)) * 64;
        const uint4* rh = (const uint4*)(kh + roff);
        const uint4* rl = (const uint4*)(kl + roff);
#pragma unroll
        for (int jj = 0; jj < 4; jj++) {
            uint4 vh = rh[half * 4 + jj];
            uint4 vl = rl[half * 4 + jj];
            if (!ok) { vh = make_uint4(0, 0, 0, 0); vl = vh; }
            int c2 = half * 16 + jj * 4;
            sK[(c2 + 0) * 136 + n] = vh.x;
            sK[(c2 + 1) * 136 + n] = vh.y;
            sK[(c2 + 2) * 136 + n] = vh.z;
            sK[(c2 + 3) * 136 + n] = vh.w;
            sK[32 * 136 + (c2 + 0) * 136 + n] = vl.x;
            sK[32 * 136 + (c2 + 1) * 136 + n] = vl.y;
            sK[32 * 136 + (c2 + 2) * 136 + n] = vl.z;
            sK[32 * 136 + (c2 + 3) * 136 + n] = vl.w;
        }
    }
    __syncthreads();

    float acc[4][4][4];
#pragma unroll
    for (int i = 0; i < 4; i++)
#pragma unroll
        for (int j = 0; j < 4; j++)
#pragma unroll
            for (int q = 0; q < 4; q++) acc[i][j][q] = 0.f;

    // terms: (qh,kh), (qh,kl), (ql,kh)
#pragma unroll
    for (int t = 0; t < 3; t++) {
        const uint32_t* A = sQ + (t == 2 ? 128 * 36 : 0);
        const uint32_t* Bk = sK + (t == 1 ? 32 * 136 : 0);
#pragma unroll
        for (int ks = 0; ks < 4; ks++) {
            uint32_t a[4][4];
#pragma unroll
            for (int i = 0; i < 4; i++) {
                int r = wm * 64 + i * 16 + rA;
                int c = 8 * ks + cA;
                a[i][0] = A[r * 36 + c];
                a[i][1] = A[(r + 8) * 36 + c];
                a[i][2] = A[r * 36 + c + 4];
                a[i][3] = A[(r + 8) * 36 + c + 4];
            }
#pragma unroll
            for (int j = 0; j < 4; j++) {
                int n = wn * 32 + j * 8 + rA;
                uint32_t b0 = Bk[(8 * ks + cA) * 136 + n];
                uint32_t b1 = Bk[(8 * ks + 4 + cA) * 136 + n];
#pragma unroll
                for (int i = 0; i < 4; i++) MMA16816(acc[i][j], a[i], b0, b1);
            }
        }
    }

    // epilogue: S (fp32, padded row stride mpad — float2 always 8B-aligned)
#pragma unroll
    for (int i = 0; i < 4; i++) {
        size_t row0 = (size_t)b * NTOK + mq0 + wm * 64 + i * 16 + rA;
#pragma unroll
        for (int j = 0; j < 4; j++) {
            int col = n0 + wn * 32 + j * 8 + 2 * cA;
            if (col + 1 < m) {
                *(float2*)&S[row0 * mpad + col] =
                    make_float2(acc[i][j][0] * ATT_SCALE, acc[i][j][1] * ATT_SCALE);
                *(float2*)&S[(row0 + 8) * mpad + col] =
                    make_float2(acc[i][j][2] * ATT_SCALE, acc[i][j][3] * ATT_SCALE);
            } else if (col < m) {
                S[row0 * mpad + col] = acc[i][j][0] * ATT_SCALE;
                S[(row0 + 8) * mpad + col] = acc[i][j][2] * ATT_SCALE;
            }
        }
    }
}

// ---------------- row softmax (stride mpad) -> split bf16 P (padded) -----------------
__global__ void softmax_kernel(const float* __restrict__ S, __nv_bfloat16* __restrict__ Ph,
                               __nv_bfloat16* __restrict__ Pl, int m, int mpad) {
    size_t row = blockIdx.x;
    const float* r = S + row * (size_t)mpad;
    int tid = threadIdx.x;
    float lv[16];
    int cnt = 0;
    float mx = -1e30f;
    for (int j = tid; j < m; j += 256) {
        float v = r[j];
        lv[cnt++] = v;
        if (v > mx) mx = v;
    }
    __shared__ float sm[8];
    int lane = tid & 31, w = tid >> 5;
    float tmp = warpMax(mx);
    if (lane == 0) sm[w] = tmp;
    __syncthreads();
    mx = -1e30f;
#pragma unroll
    for (int i = 0; i < 8; i++) mx = fmaxf(mx, sm[i]);
    float sum = 0.f;
    for (int i = 0; i < cnt; i++) {
        float e = __expf(lv[i] - mx);
        lv[i] = e;
        sum += e;
    }
    __syncthreads();
    tmp = warpSum(sum);
    if (lane == 0) sm[w] = tmp;
    __syncthreads();
    sum = 0.f;
#pragma unroll
    for (int i = 0; i < 8; i++) sum += sm[i];
    float inv = 1.f / sum;
    __nv_bfloat16* ph = Ph + row * (size_t)mpad;
    __nv_bfloat16* pl = Pl + row * (size_t)mpad;
    cnt = 0;
    for (int j = tid; j < mpad; j += 256) {
        if (j < m) {
            float p = lv[cnt++] * inv;
            __nv_bfloat16 hp = __float2bfloat16(p);
            ph[j] = hp;
            pl[j] = __float2bfloat16(p - __bfloat162float(hp));
        } else {
            ph[j] = __float2bfloat16(0.f);
            pl[j] = __float2bfloat16(0.f);
        }
    }
}

// ---------------- PV: out_h = P @ v' via HMMA ----------------------------------------
// CTA 64(rows) x 64(v cols); warps 4(M)x2(N), each warp 16 rows x 32 cols.
__global__ void __launch_bounds__(256) attn_pv_kernel(
    const __nv_bfloat16* __restrict__ Ph, const __nv_bfloat16* __restrict__ Pl,
    const uint32_t* __restrict__ pkh, const uint32_t* __restrict__ pkl,
    float* __restrict__ out, int mpad, int nchunk)
{
    __shared__ alignas(16) uint32_t sP[2 * 64 * 36];
    __shared__ alignas(16) uint32_t sV[2 * 32 * 72];

    int tid = threadIdx.x, lane = tid & 31, wid = tid >> 5;
    int wm = wid & 3, wn = wid >> 2;
    int rA = lane >> 2, cA = lane & 3;
    int b = blockIdx.y;
    int m0 = blockIdx.x * 64;

    int arow = tid >> 2, aq = tid & 3;
    size_t abase = ((size_t)b * NTOK + m0 + arow) * mpad;

    float acc[4][4];
#pragma unroll
    for (int j = 0; j < 4; j++)
#pragma unroll
        for (int q = 0; q < 4; q++) acc[j][q] = 0.f;

    for (int c = 0; c < nchunk; c++) {
        __syncthreads();
        {
            size_t off = abase + c * 64 + aq * 16;
            const uint4* sh = (const uint4*)(Ph + off);
            const uint4* sl = (const uint4*)(Pl + off);
            uint32_t* dh = sP + arow * 36 + aq * 8;
            uint32_t* dl = sP + 64 * 36 + arow * 36 + aq * 8;
            *(uint4*)&dh[0] = sh[0]; *(uint4*)&dh[4] = sh[1];
            *(uint4*)&dl[0] = sl[0]; *(uint4*)&dl[4] = sl[1];
        }
        {
            size_t gb = ((size_t)b * nchunk + c) * 2048;
#pragma unroll
            for (int t = 0; t < 8; t++) {
                int idx = tid + t * 256;
                int c2 = idx >> 6, n = idx & 63;
                sV[c2 * 72 + n] = pkh[gb + idx];
                sV[32 * 72 + c2 * 72 + n] = pkl[gb + idx];
            }
        }
        __syncthreads();

#pragma unroll
        for (int t = 0; t < 3; t++) {
            const uint32_t* A = sP + (t == 2 ? 64 * 36 : 0);
            const uint32_t* Bv = sV + (t == 1 ? 32 * 72 : 0);
#pragma unroll
            for (int ks = 0; ks < 4; ks++) {
                uint32_t a[4];
                int r = wm * 16 + rA;
                int cc = 8 * ks + cA;
                a[0] = A[r * 36 + cc];
                a[1] = A[(r + 8) * 36 + cc];
                a[2] = A[r * 36 + cc + 4];
                a[3] = A[(r + 8) * 36 + cc + 4];
#pragma unroll
                for (int j = 0; j < 4; j++) {
                    int n = wn * 32 + j * 8 + rA;
                    uint32_t b0 = Bv[(8 * ks + cA) * 72 + n];
                    uint32_t b1 = Bv[(8 * ks + 4 + cA) * 72 + n];
                    MMA16816(acc[j], a, b0, b1);
                }
            }
        }
    }

    size_t row0 = (size_t)b * NTOK + m0 + wm * 16 + rA;
#pragma unroll
    for (int j = 0; j < 4; j++) {
        int col = wn * 32 + j * 8 + 2 * cA;
        *(float2*)&out[row0 * NC + col] = make_float2(acc[j][0], acc[j][1]);
        *(float2*)&out[(row0 + 8) * NC + col] = make_float2(acc[j][2], acc[j][3]);
    }
}

// ---------------- LayerNorm + exact GELU --------------------------------------------
__global__ void ln_gelu_kernel(float* __restrict__ t, const float* __restrict__ g,
                               const float* __restrict__ bb) {
    size_t row = blockIdx.x;
    int tid = threadIdx.x;
    float v = t[row * NC + tid];
    __shared__ float sm[6];
    int lane = tid & 31, w = tid >> 5;
    float s = warpSum(v);
    if (lane == 0) sm[w] = s;
    __syncthreads();
    float mean = 0.f;
#pragma unroll
    for (int i = 0; i < 6; i++) mean += sm[i];
    mean *= (1.0f / 192.0f);
    float d = v - mean;
    __syncthreads();
    s = warpSum(d * d);
    if (lane == 0) sm[w] = s;
    __syncthreads();
    float var = 0.f;
#pragma unroll
    for (int i = 0; i < 6; i++) var += sm[i];
    var *= (1.0f / 192.0f);
    float y = d * rsqrtf(var + 1e-5f) * g[tid] + bb[tid];
    t[row * NC + tid] = y * normcdff(y);
}

// ---------------- generic NT GEMM (projections) --------------------------------------
__global__ void __launch_bounds__(256) gemm_nt(
    const float* __restrict__ A, long long sA, int lda,
    const float* __restrict__ W, long long sW, int ldw,
    const float* __restrict__ bias,
    float* __restrict__ C, long long sC, int ldc,
    int M, int Nn, int K, float scale)
{
    __shared__ float As[16][132];
    __shared__ float Ws[16][68];
    int bz = blockIdx.z;
    const float* Ab = A + sA * bz;
    const float* Wb = W + sW * bz;
    float* Cb = C + sC * bz;
    int n0 = blockIdx.x * 64, m0 = blockIdx.y * 128;
    int tid = threadIdx.x;
    int tx = tid & 15, ty = tid >> 4;
    float acc[8][4];
#pragma unroll
    for (int i = 0; i < 8; i++)
#pragma unroll
        for (int j = 0; j < 4; j++) acc[i][j] = 0.f;

    for (int k0 = 0; k0 < K; k0 += 16) {
#pragma unroll
        for (int j = 0; j < 8; j++) {
            int idx = tid + j * 256;
            int kk = idx & 15, mm = idx >> 4;
            int gm = m0 + mm, gk = k0 + kk;
            As[kk][mm] = (gm < M && gk < K) ? Ab[(size_t)gm * lda + gk] : 0.f;
        }
#pragma unroll
        for (int j = 0; j < 4; j++) {
            int idx = tid + j * 256;
            int kk = idx & 15, nn = idx >> 4;
            int gn = n0 + nn, gk = k0 + kk;
            Ws[kk][nn] = (gn < Nn && gk < K) ? Wb[(size_t)gn * ldw + gk] : 0.f;
        }
        __syncthreads();
#pragma unroll
        for (int kk = 0; kk < 16; kk++) {
            float a[8], w[4];
#pragma unroll
            for (int i = 0; i < 8; i++) a[i] = As[kk][ty * 8 + i];
#pragma unroll
            for (int j = 0; j < 4; j++) w[j] = Ws[kk][tx * 4 + j];
#pragma unroll
            for (int i = 0; i < 8; i++)
#pragma unroll
                for (int j = 0; j < 4; j++) acc[i][j] = fmaf(a[i], w[j], acc[i][j]);
        }
        __syncthreads();
    }
#pragma unroll
    for (int i = 0; i < 8; i++) {
        int gm = m0 + ty * 8 + i;
        if (gm >= M) continue;
#pragma unroll
        for (int j = 0; j < 4; j++) {
            int gn = n0 + tx * 4 + j;
            if (gn < Nn) {
                float v = acc[i][j] * scale;
                if (bias) v += bias[gn];
                Cb[(size_t)gm * ldc + gn] = v;
            }
        }
    }
}

// ---------------- depthwise 3x3 on v, residual add -----------------------------------
__global__ void dwconv_kernel(const float* __restrict__ kv, const float* __restrict__ lw,
                              const float* __restrict__ lb, float* __restrict__ vp,
                              int side, int m)
{
    long long idx = (long long)blockIdx.x * 256 + threadIdx.x;
    long long total = (long long)NB * m * 64;
    if (idx >= total) return;
    int hd = (int)(idx & 63);
    long long pm = idx >> 6;
    int p = (int)(pm % m);
    int b = (int)(pm / m);
    int y = p / side, x = p % side;
    const float* vbase = kv + (size_t)b * m * 128 + 64 + hd;
    float s = lb[hd];
#pragma unroll
    for (int dy = 0; dy < 3; dy++) {
        int yy = y + dy - 1;
        if (yy < 0 || yy >= side) continue;
#pragma unroll
        for (int dx = 0; dx < 3; dx++) {
            int xx = x + dx - 1;
            if (xx < 0 || xx >= side) continue;
            s += lw[hd * 9 + dy * 3 + dx] * vbase[(size_t)(yy * side + xx) * 128];
        }
    }
    vp[idx] = vbase[(size_t)p * 128] + s;
}

// ---------------- host orchestration ---------------------------------------------------
extern "C" void kernel_launch(void* const* d_in, const int* in_sizes, int n_in,
                              void* d_out, int out_size)
{
    (void)in_sizes; (void)n_in; (void)out_size;
    const float* x    = (const float*)d_in[0];
    const float* q_w  = (const float*)d_in[1];
    const float* q_b  = (const float*)d_in[2];
    const float* kv_w = (const float*)d_in[3];
    const float* kv_b = (const float*)d_in[4];
    const float* sr_w[3] = {(const float*)d_in[5], (const float*)d_in[7], (const float*)d_in[9]};
    const float* sr_b[3] = {(const float*)d_in[6], (const float*)d_in[8], (const float*)d_in[10]};
    const float* ln_g[3] = {(const float*)d_in[11], (const float*)d_in[13], (const float*)d_in[15]};
    const float* ln_b[3] = {(const float*)d_in[12], (const float*)d_in[14], (const float*)d_in[16]};
    const float* lc_w[3] = {(const float*)d_in[17], (const float*)d_in[19], (const float*)d_in[21]};
    const float* lc_b[3] = {(const float*)d_in[18], (const float*)d_in[20], (const float*)d_in[22]};
    const float* nn1_w = (const float*)d_in[23];
    const float* nn1_b = (const float*)d_in[24];
    float* out = (float*)d_out;

    float *p_q, *p_t, *p_kv, *p_vp, *p_S, *p_xcat;
    __nv_bfloat16 *p_xh, *p_xl, *p_qh, *p_ql, *p_kh, *p_kl, *p_Ph, *p_Pl;
    uint32_t *p_wp, *p_vkh, *p_vkl;
    cudaGetSymbolAddress((void**)&p_q,    g_q);
    cudaGetSymbolAddress((void**)&p_t,    g_t);
    cudaGetSymbolAddress((void**)&p_kv,   g_kv);
    cudaGetSymbolAddress((void**)&p_vp,   g_vp);
    cudaGetSymbolAddress((void**)&p_S,    g_S);
    cudaGetSymbolAddress((void**)&p_xcat, g_xcat);
    cudaGetSymbolAddress((void**)&p_xh,   g_xh);
    cudaGetSymbolAddress((void**)&p_xl,   g_xl);
    cudaGetSymbolAddress((void**)&p_wp,   g_wpack);
    cudaGetSymbolAddress((void**)&p_qh,   g_qh);
    cudaGetSymbolAddress((void**)&p_ql,   g_ql);
    cudaGetSymbolAddress((void**)&p_kh,   g_kh);
    cudaGetSymbolAddress((void**)&p_kl,   g_kl);
    cudaGetSymbolAddress((void**)&p_Ph,   g_Ph);
    cudaGetSymbolAddress((void**)&p_Pl,   g_Pl);
    cudaGetSymbolAddress((void**)&p_vkh,  g_vpkh);
    cudaGetSymbolAddress((void**)&p_vkl,  g_vpkl);

    cudaFuncSetAttribute(attn_s_kernel, cudaFuncAttributeMaxDynamicSharedMemorySize, 71680);
    cudaFuncSetAttribute(conv_hmma_kernel, cudaFuncAttributeMaxDynamicSharedMemorySize,
                         2 * CSTGW * 4);

    prep_x_kernel<<<(NB * NTOK * NC + 255) / 256, 256>>>(x, p_xh, p_xl);

    gemm_nt<<<dim3(3, 128, 1), 256>>>(x, 0, NC, q_w, 0, NC, q_b,
                                      p_q, 0, NC, NB * NTOK, NC, NC, 1.f);

    const int KS[3] = {8, 4, 2};
    for (int h = 0; h < 3; h++) {
        int k = KS[h];
        int side = 64 - k + 1;
        int m = side * side;
        int k2 = k * k;
        int nchunk = (m + 63) / 64;
        int mpad = nchunk * 64;
        long long Bm = (long long)NB * m;

        prep_w_kernel<<<(k2 * 12 * 32 * PN + 255) / 256, 256>>>(sr_w[h], p_wp, k2);
        conv_hmma_kernel<<<dim3((int)((Bm + 63) / 64), 2), 256, 2 * CSTGW * 4>>>(
            p_xh, p_xl, (const uint4*)p_wp, sr_b[h], p_t, k, side, m);
        ln_gelu_kernel<<<NB * m, 192>>>(p_t, ln_g[h], ln_b[h]);

        gemm_nt<<<dim3(2, (NB * m + 127) / 128, 1), 256>>>(
            p_t, 0, NC, kv_w, 0, NC, kv_b, p_kv, 0, 128, NB * m, 128, NC, 1.f);

        prep_q_kernel<<<(NB * NTOK * 64 + 255) / 256, 256>>>(p_q, p_qh, p_ql, h);
        prep_k_kernel<<<(NB * m * 64 + 255) / 256, 256>>>(p_kv, p_kh, p_kl, m);

        dwconv_kernel<<<(int)(((long long)NB * m * 64 + 255) / 256), 256>>>(
            p_kv, lc_w[h], lc_b[h], p_vp, side, m);
        pack_v_kernel<<<(NB * nchunk * 2048 + 255) / 256, 256>>>(p_vp, p_vkh, p_vkl, m, nchunk);

        attn_s_kernel<<<dim3((m + 127) / 128, NTOK / 128, NB), 256, 71680>>>(
            p_qh, p_ql, p_kh, p_kl, p_S, m, mpad);

        softmax_kernel<<<NB * NTOK, 256>>>(p_S, p_Ph, p_Pl, m, mpad);

        attn_pv_kernel<<<dim3(NTOK / 64, NB), 256>>>(
            p_Ph, p_Pl, p_vkh, p_vkl, p_xcat + h * 64, mpad, nchunk);
    }

    gemm_nt<<<dim3(3, 128, 1), 256>>>(p_xcat, 0, NC, nn1_w, 0, NC, nn1_b,
                                      out, 0, NC, NB * NTOK, NC, NC, 1.f);
}

// round 10
// speedup vs baseline: 3.4360x; 1.2621x over previous
#include <cuda_runtime.h>
#include <cuda_bf16.h>
#include <math.h>
#include <stdint.h>

#define NB   4
#define NTOK 4096
#define NC   192
#define MAXM 3969
#define PN   104                         // conv B smem word pitch
#define CSTGW 11264                      // conv stage words: Ah2304+Al2304+B6656

static const float ATT_SCALE = 0.07216878364870323f; // 192^-0.5

// ---------------- scratch -------------------------------------------------------
__device__ float g_q[NB * NTOK * NC];
__device__ float g_t[(size_t)NB * MAXM * NC];
__device__ float g_kv[NB * MAXM * 128];
__device__ float g_vp[NB * MAXM * 64];
__device__ float g_xcat[NB * NTOK * NC];
__device__ __nv_bfloat16 g_xh[NB * NTOK * NC];
__device__ __nv_bfloat16 g_xl[NB * NTOK * NC];
__device__ uint32_t g_wpack[768 * 32 * PN];
__device__ __nv_bfloat16 g_qh[NB * NTOK * 64];
__device__ __nv_bfloat16 g_ql[NB * NTOK * 64];
__device__ __nv_bfloat16 g_kh[NB * MAXM * 64];
__device__ __nv_bfloat16 g_kl[NB * MAXM * 64];
__device__ uint32_t g_vpkh[NB * 63 * 32 * 64];
__device__ uint32_t g_vpkl[NB * 63 * 32 * 64];

// ---------------- helpers ---------------------------------------------------------
__device__ __forceinline__ uint32_t smem_u32(const void* p) {
    uint32_t a;
    asm("{ .reg .u64 t; cvta.to.shared.u64 t, %1; cvt.u32.u64 %0, t; }" : "=r"(a) : "l"(p));
    return a;
}
#define MMA16816(acc, a, b0, b1)                                                    \
    asm volatile("mma.sync.aligned.m16n8k16.row.col.f32.bf16.bf16.f32 "             \
        "{%0,%1,%2,%3}, {%4,%5,%6,%7}, {%8,%9}, {%0,%1,%2,%3};"                     \
        : "+f"((acc)[0]), "+f"((acc)[1]), "+f"((acc)[2]), "+f"((acc)[3])            \
        : "r"((a)[0]), "r"((a)[1]), "r"((a)[2]), "r"((a)[3]), "r"(b0), "r"(b1))
#define CPA16(dst, src)                                                             \
    asm volatile("cp.async.cg.shared.global [%0], [%1], 16;"                        \
        :: "r"(dst), "l"(src))
#define CPA_COMMIT() asm volatile("cp.async.commit_group;" ::: "memory")
#define CPA_WAIT1()  asm volatile("cp.async.wait_group 1;" ::: "memory")

// split pair of floats into packed bf16 hi/lo words
__device__ __forceinline__ void split2(float a, float b, uint32_t& hi, uint32_t& lo) {
    __nv_bfloat16 ha = __float2bfloat16(a), hb = __float2bfloat16(b);
    float ra = a - __bfloat162float(ha);
    float rb = b - __bfloat162float(hb);
    __nv_bfloat16 la = __float2bfloat16(ra), lb = __float2bfloat16(rb);
    hi = ((uint32_t)*(unsigned short*)&hb << 16) | *(unsigned short*)&ha;
    lo = ((uint32_t)*(unsigned short*)&lb << 16) | *(unsigned short*)&la;
}

// ---------------- prep: split x into bf16 hi/lo -----------------------------------
__global__ void prep_x_kernel(const float* __restrict__ x, __nv_bfloat16* __restrict__ xh,
                              __nv_bfloat16* __restrict__ xl) {
    int i = blockIdx.x * 256 + threadIdx.x;
    if (i >= NB * NTOK * NC) return;
    float f = x[i];
    __nv_bfloat16 h = __float2bfloat16(f);
    xh[i] = h;
    xl[i] = __float2bfloat16(f - __bfloat162float(h));
}

// ---------------- prep: W -> packed word images ------------------------------------
__global__ void prep_w_kernel(const float* __restrict__ w, uint32_t* __restrict__ wp,
                              int k2) {
    int idx = blockIdx.x * 256 + threadIdx.x;
    int total = k2 * 12 * 32 * PN;
    if (idx >= total) return;
    int img = idx / (32 * PN), rem = idx % (32 * PN);
    int c2 = rem / PN, n = rem % PN;
    if (n >= 96) { wp[idx] = 0u; return; }
    int tap = img / 12, r = img % 12;
    int cb = r >> 2, r2 = r & 3;
    int cohalf = r2 >> 1, split = r2 & 1;
    int ci = cb * 64 + 2 * c2;
    int co = cohalf * 96 + n;
    float fe = w[((size_t)co * NC + ci) * k2 + tap];
    float fo = w[((size_t)co * NC + ci + 1) * k2 + tap];
    __nv_bfloat16 he = __float2bfloat16(fe), ho = __float2bfloat16(fo);
    __nv_bfloat16 ve = split ? __float2bfloat16(fe - __bfloat162float(he)) : he;
    __nv_bfloat16 vo = split ? __float2bfloat16(fo - __bfloat162float(ho)) : ho;
    uint32_t we = *(const unsigned short*)&ve;
    uint32_t wo = *(const unsigned short*)&vo;
    wp[idx] = (wo << 16) | we;
}

// ---------------- conv: implicit GEMM, HMMA, cp.async x2 (unchanged from R9) --------
__global__ void __launch_bounds__(256, 2) conv_hmma_kernel(
    const __nv_bfloat16* __restrict__ xh, const __nv_bfloat16* __restrict__ xl,
    const uint4* __restrict__ wp, const float* __restrict__ bias,
    float* __restrict__ out, int k, int side, int m)
{
    extern __shared__ uint32_t dsm[];

    int tid = threadIdx.x;
    int lane = tid & 31, wid = tid >> 5;
    int wm = wid & 1, wn = wid >> 1;
    long long Bm = (long long)NB * m;

    int arow = tid >> 2, aq = tid & 3;
    long long apx = (long long)blockIdx.x * 64 + arow;
    long long apxc = apx < Bm - 1 ? apx : Bm - 1;
    int ab = (int)(apxc / m), app = (int)(apxc % m);
    int aoy = app / side, aox = app % side;
    size_t axbase = (size_t)ab * NTOK * NC;
    int half = blockIdx.y;
    int rA = lane >> 2, cA = lane & 3;

    uint32_t smbase = smem_u32(dsm);
    uint32_t awd = smbase + (uint32_t)(arow * 36 + aq * 8) * 4;
    uint32_t bwd = smbase + 4608u * 4;

    float acc[2][3][4];
#pragma unroll
    for (int i = 0; i < 2; i++)
#pragma unroll
        for (int j = 0; j < 3; j++)
#pragma unroll
            for (int q = 0; q < 4; q++) acc[i][j][q] = 0.f;

    int k2 = k * k;
    int ng = k2 * 3;

#define CONV_ISSUE(g, s) do {                                                        \
        int _tap = (g) / 3, _cb = (g) - _tap * 3;                                    \
        int _dy = _tap / k, _dx = _tap - _dy * k;                                    \
        size_t _aoff = axbase + (size_t)((aoy + _dy) * 64 + aox + _dx) * NC          \
                     + _cb * 64 + aq * 16;                                           \
        uint32_t _soff = (uint32_t)(s) * (CSTGW * 4);                                \
        const char* _gh = (const char*)(xh + _aoff);                                 \
        const char* _gl = (const char*)(xl + _aoff);                                 \
        CPA16(awd + _soff,      _gh);                                                \
        CPA16(awd + _soff + 16, _gh + 16);                                           \
        CPA16(awd + _soff + 2304u * 4,      _gl);                                    \
        CPA16(awd + _soff + 2304u * 4 + 16, _gl + 16);                               \
        int _imgb = (_tap * 3 + _cb) * 4 + half * 2;                                 \
        const char* _gb = (const char*)(wp + (size_t)_imgb * (32 * PN / 4));         \
        _Pragma("unroll")                                                            \
        for (int _i = 0; _i < 7; _i++) {                                             \
            int _idx = tid + _i * 256;                                               \
            if (_idx < 1664) CPA16(bwd + _soff + _idx * 16, _gb + (size_t)_idx * 16);\
        }                                                                            \
    } while (0)

    CONV_ISSUE(0, 0);
    CPA_COMMIT();

    for (int g = 0; g < ng; g++) {
        if (g + 1 < ng) CONV_ISSUE(g + 1, (g + 1) & 1);
        CPA_COMMIT();
        CPA_WAIT1();
        __syncthreads();

        const uint32_t* stg = dsm + (g & 1) * CSTGW;
        const uint32_t* Ah = stg;
        const uint32_t* Al = stg + 2304;
        const uint32_t* B0 = stg + 4608;
        const uint32_t* B1 = stg + 7936;

#pragma unroll
        for (int ks = 0; ks < 4; ks++) {
            uint32_t ah[2][4], al[2][4];
#pragma unroll
            for (int i = 0; i < 2; i++) {
                int r = wm * 32 + i * 16 + rA;
                int c = 8 * ks + cA;
                ah[i][0] = Ah[r * 36 + c];
                ah[i][1] = Ah[(r + 8) * 36 + c];
                ah[i][2] = Ah[r * 36 + c + 4];
                ah[i][3] = Ah[(r + 8) * 36 + c + 4];
                al[i][0] = Al[r * 36 + c];
                al[i][1] = Al[(r + 8) * 36 + c];
                al[i][2] = Al[r * 36 + c + 4];
                al[i][3] = Al[(r + 8) * 36 + c + 4];
            }
            uint32_t b0[3][2], b1[3][2];
#pragma unroll
            for (int j = 0; j < 3; j++) {
                int n = wn * 24 + j * 8 + rA;
                b0[j][0] = B0[(8 * ks + cA) * PN + n];
                b0[j][1] = B0[(8 * ks + 4 + cA) * PN + n];
                b1[j][0] = B1[(8 * ks + cA) * PN + n];
                b1[j][1] = B1[(8 * ks + 4 + cA) * PN + n];
            }
#pragma unroll
            for (int i = 0; i < 2; i++)
#pragma unroll
                for (int j = 0; j < 3; j++) {
                    MMA16816(acc[i][j], ah[i], b0[j][0], b0[j][1]);
                    MMA16816(acc[i][j], ah[i], b1[j][0], b1[j][1]);
                    MMA16816(acc[i][j], al[i], b0[j][0], b0[j][1]);
                }
        }
        __syncthreads();
    }

#pragma unroll
    for (int i = 0; i < 2; i++) {
        long long row0 = (long long)blockIdx.x * 64 + wm * 32 + i * 16 + rA;
#pragma unroll
        for (int j = 0; j < 3; j++) {
            int col = half * 96 + wn * 24 + j * 8 + 2 * cA;
            float b0 = bias[col], b1 = bias[col + 1];
            if (row0 < Bm) {
                float2 v = make_float2(acc[i][j][0] + b0, acc[i][j][1] + b1);
                *(float2*)&out[row0 * NC + col] = v;
            }
            if (row0 + 8 < Bm) {
                float2 v = make_float2(acc[i][j][2] + b0, acc[i][j][3] + b1);
                *(float2*)&out[(row0 + 8) * NC + col] = v;
            }
        }
    }
#undef CONV_ISSUE
}

// ---------------- prep q / k splits -----------------------------------------------
__global__ void prep_q_kernel(const float* __restrict__ q, __nv_bfloat16* __restrict__ qh,
                              __nv_bfloat16* __restrict__ ql, int h) {
    int i = blockIdx.x * 256 + threadIdx.x;
    if (i >= NB * NTOK * 64) return;
    int c = i & 63;
    int row = i >> 6;
    float f = q[(size_t)row * NC + h * 64 + c];
    __nv_bfloat16 hi = __float2bfloat16(f);
    qh[i] = hi;
    ql[i] = __float2bfloat16(f - __bfloat162float(hi));
}
__global__ void prep_k_kernel(const float* __restrict__ kv, __nv_bfloat16* __restrict__ kh,
                              __nv_bfloat16* __restrict__ kl, int m) {
    int i = blockIdx.x * 256 + threadIdx.x;
    if (i >= NB * m * 64) return;
    int c = i & 63;
    int row = i >> 6;
    float f = kv[(size_t)row * 128 + c];
    __nv_bfloat16 hi = __float2bfloat16(f);
    kh[i] = hi;
    kl[i] = __float2bfloat16(f - __bfloat162float(hi));
}

// ---------------- pack v' into MMA word images --------------------------------------
__global__ void pack_v_kernel(const float* __restrict__ vp, uint32_t* __restrict__ pkh,
                              uint32_t* __restrict__ pkl, int m, int nchunk) {
    int idx = blockIdx.x * 256 + threadIdx.x;
    int total = NB * nchunk * 32 * 64;
    if (idx >= total) return;
    int n = idx & 63;
    int c2 = (idx >> 6) & 31;
    int c = (idx >> 11) % nchunk;
    int b = idx / (nchunk * 2048);
    int k0 = c * 64 + 2 * c2;
    float v0 = (k0 < m) ? vp[((size_t)b * m + k0) * 64 + n] : 0.f;
    float v1 = (k0 + 1 < m) ? vp[((size_t)b * m + k0 + 1) * 64 + n] : 0.f;
    uint32_t wh, wl;
    split2(v0, v1, wh, wl);
    pkh[idx] = wh;
    pkl[idx] = wl;
}

// ---------------- fused flash attention: out = softmax(scale*q@k^T) @ v' -------------
// CTA: 128 q rows (grid 32 x NB), 8 warps, warp owns 16 rows x full m loop.
__global__ void __launch_bounds__(256) attn_flash_kernel(
    const __nv_bfloat16* __restrict__ qh, const __nv_bfloat16* __restrict__ ql,
    const __nv_bfloat16* __restrict__ kh, const __nv_bfloat16* __restrict__ kl,
    const uint32_t* __restrict__ pkh, const uint32_t* __restrict__ pkl,
    float* __restrict__ out, int m, int nchunk)
{
    extern __shared__ uint32_t fsm[];
    uint32_t* sQh = fsm;              // 128*36
    uint32_t* sQl = fsm + 4608;       // 128*36
    uint32_t* sKh = fsm + 9216;       // 32*72
    uint32_t* sKl = fsm + 11520;
    uint32_t* sVh = fsm + 13824;
    uint32_t* sVl = fsm + 16128;      // total 18432 words = 73728 B

    int tid = threadIdx.x, lane = tid & 31, w = tid >> 5;
    int rA = lane >> 2, cA = lane & 3;
    int b = blockIdx.y;
    int q0 = blockIdx.x * 128;

    {   // q fill (once)
        int arow = tid >> 1, ahalf = tid & 1;
        size_t off = ((size_t)b * NTOK + q0 + arow) * 64 + ahalf * 32;
        const uint4* sh = (const uint4*)(qh + off);
        const uint4* sl = (const uint4*)(ql + off);
        uint32_t* dh = sQh + arow * 36 + ahalf * 16;
        uint32_t* dl = sQl + arow * 36 + ahalf * 16;
#pragma unroll
        for (int j = 0; j < 4; j++) { *(uint4*)&dh[j * 4] = sh[j]; *(uint4*)&dl[j * 4] = sl[j]; }
    }

    float acc_o[8][4];
#pragma unroll
    for (int nn = 0; nn < 8; nn++)
#pragma unroll
        for (int q = 0; q < 4; q++) acc_o[nn][q] = 0.f;
    float mrun0 = -1e30f, mrun1 = -1e30f, l0 = 0.f, l1 = 0.f;

    int kq = tid >> 2, kquad = tid & 3;   // k-fill: 64 rows x 4 threads

    for (int c = 0; c < nchunk; c++) {
        __syncthreads();                  // protect k/v smem from previous compute
        {   // k fill (transposed images, zero-padded beyond m)
            int ngk = c * 64 + kq;
            int ok = ngk < m;
            size_t roff = ((size_t)b * m + (ok ? ngk : 0)) * 64;
            const uint4* rh = (const uint4*)(kh + roff);
            const uint4* rl = (const uint4*)(kl + roff);
#pragma unroll
            for (int jj = 0; jj < 2; jj++) {
                uint4 vh = rh[kquad * 2 + jj];
                uint4 vl = rl[kquad * 2 + jj];
                if (!ok) { vh = make_uint4(0, 0, 0, 0); vl = vh; }
                int c2 = kquad * 8 + jj * 4;
                sKh[(c2 + 0) * 72 + kq] = vh.x;
                sKh[(c2 + 1) * 72 + kq] = vh.y;
                sKh[(c2 + 2) * 72 + kq] = vh.z;
                sKh[(c2 + 3) * 72 + kq] = vh.w;
                sKl[(c2 + 0) * 72 + kq] = vl.x;
                sKl[(c2 + 1) * 72 + kq] = vl.y;
                sKl[(c2 + 2) * 72 + kq] = vl.z;
                sKl[(c2 + 3) * 72 + kq] = vl.w;
            }
        }
        {   // v fill (straight copy, repitch 64 -> 72)
            size_t gb = ((size_t)b * nchunk + c) * 2048;
#pragma unroll
            for (int t = 0; t < 8; t++) {
                int idx = tid + t * 256;
                int c2 = idx >> 6, n = idx & 63;
                sVh[c2 * 72 + n] = pkh[gb + idx];
                sVl[c2 * 72 + n] = pkl[gb + idx];
            }
        }
        __syncthreads();

        // ---- S = q @ k^T (warp: 16 rows x 64 cols), 3-term split ----
        float s[8][4];
#pragma unroll
        for (int j = 0; j < 8; j++)
#pragma unroll
            for (int q = 0; q < 4; q++) s[j][q] = 0.f;

#pragma unroll
        for (int ks = 0; ks < 4; ks++) {
            uint32_t ah[4], al[4];
            int r = w * 16 + rA;
            int cc = 8 * ks + cA;
            ah[0] = sQh[r * 36 + cc];
            ah[1] = sQh[(r + 8) * 36 + cc];
            ah[2] = sQh[r * 36 + cc + 4];
            ah[3] = sQh[(r + 8) * 36 + cc + 4];
            al[0] = sQl[r * 36 + cc];
            al[1] = sQl[(r + 8) * 36 + cc];
            al[2] = sQl[r * 36 + cc + 4];
            al[3] = sQl[(r + 8) * 36 + cc + 4];
#pragma unroll
            for (int j = 0; j < 8; j++) {
                int n = j * 8 + rA;
                uint32_t bh0 = sKh[(8 * ks + cA) * 72 + n];
                uint32_t bh1 = sKh[(8 * ks + 4 + cA) * 72 + n];
                uint32_t bl0 = sKl[(8 * ks + cA) * 72 + n];
                uint32_t bl1 = sKl[(8 * ks + 4 + cA) * 72 + n];
                MMA16816(s[j], ah, bh0, bh1);
                MMA16816(s[j], ah, bl0, bl1);
                MMA16816(s[j], al, bh0, bh1);
            }
        }

        // ---- scale + mask padded cols (last chunk only) ----
        int cbase = c * 64;
        bool lastc = (cbase + 64 > m);
#pragma unroll
        for (int j = 0; j < 8; j++)
#pragma unroll
            for (int q = 0; q < 4; q++) {
                float v = s[j][q] * ATT_SCALE;
                if (lastc && (cbase + j * 8 + 2 * cA + (q & 1)) >= m) v = -1e30f;
                s[j][q] = v;
            }

        // ---- online softmax (rows rA and rA+8; reduce over quad lanes) ----
        float mx0 = -1e30f, mx1 = -1e30f;
#pragma unroll
        for (int j = 0; j < 8; j++) {
            mx0 = fmaxf(mx0, fmaxf(s[j][0], s[j][1]));
            mx1 = fmaxf(mx1, fmaxf(s[j][2], s[j][3]));
        }
        mx0 = fmaxf(mx0, __shfl_xor_sync(0xffffffffu, mx0, 1));
        mx0 = fmaxf(mx0, __shfl_xor_sync(0xffffffffu, mx0, 2));
        mx1 = fmaxf(mx1, __shfl_xor_sync(0xffffffffu, mx1, 1));
        mx1 = fmaxf(mx1, __shfl_xor_sync(0xffffffffu, mx1, 2));
        float mn0 = fmaxf(mrun0, mx0), mn1 = fmaxf(mrun1, mx1);
        float sc0 = __expf(mrun0 - mn0), sc1 = __expf(mrun1 - mn1);
        mrun0 = mn0; mrun1 = mn1;

        float sum0 = 0.f, sum1 = 0.f;
#pragma unroll
        for (int j = 0; j < 8; j++) {
            s[j][0] = __expf(s[j][0] - mn0);
            s[j][1] = __expf(s[j][1] - mn0);
            s[j][2] = __expf(s[j][2] - mn1);
            s[j][3] = __expf(s[j][3] - mn1);
            sum0 += s[j][0] + s[j][1];
            sum1 += s[j][2] + s[j][3];
        }
        sum0 += __shfl_xor_sync(0xffffffffu, sum0, 1);
        sum0 += __shfl_xor_sync(0xffffffffu, sum0, 2);
        sum1 += __shfl_xor_sync(0xffffffffu, sum1, 1);
        sum1 += __shfl_xor_sync(0xffffffffu, sum1, 2);
        l0 = l0 * sc0 + sum0;
        l1 = l1 * sc1 + sum1;

#pragma unroll
        for (int nn = 0; nn < 8; nn++) {
            acc_o[nn][0] *= sc0; acc_o[nn][1] *= sc0;
            acc_o[nn][2] *= sc1; acc_o[nn][3] *= sc1;
        }

        // ---- pack P into A-fragments (hi/lo split), in registers ----
        uint32_t aph[4][4], apl[4][4];
#pragma unroll
        for (int kk = 0; kk < 4; kk++) {
            split2(s[2 * kk][0],     s[2 * kk][1],     aph[kk][0], apl[kk][0]);
            split2(s[2 * kk][2],     s[2 * kk][3],     aph[kk][1], apl[kk][1]);
            split2(s[2 * kk + 1][0], s[2 * kk + 1][1], aph[kk][2], apl[kk][2]);
            split2(s[2 * kk + 1][2], s[2 * kk + 1][3], aph[kk][3], apl[kk][3]);
        }

        // ---- PV accumulate ----
#pragma unroll
        for (int kk = 0; kk < 4; kk++) {
#pragma unroll
            for (int nn = 0; nn < 8; nn++) {
                int n = nn * 8 + rA;
                uint32_t vh0 = sVh[(8 * kk + cA) * 72 + n];
                uint32_t vh1 = sVh[(8 * kk + 4 + cA) * 72 + n];
                uint32_t vl0 = sVl[(8 * kk + cA) * 72 + n];
                uint32_t vl1 = sVl[(8 * kk + 4 + cA) * 72 + n];
                MMA16816(acc_o[nn], aph[kk], vh0, vh1);
                MMA16816(acc_o[nn], aph[kk], vl0, vl1);
                MMA16816(acc_o[nn], apl[kk], vh0, vh1);
            }
        }
    }

    // ---- epilogue: normalize and store ----
    float inv0 = 1.f / l0, inv1 = 1.f / l1;
    size_t row0 = (size_t)b * NTOK + q0 + w * 16 + rA;
#pragma unroll
    for (int nn = 0; nn < 8; nn++) {
        int col = nn * 8 + 2 * cA;
        *(float2*)&out[row0 * NC + col] =
            make_float2(acc_o[nn][0] * inv0, acc_o[nn][1] * inv0);
        *(float2*)&out[(row0 + 8) * NC + col] =
            make_float2(acc_o[nn][2] * inv1, acc_o[nn][3] * inv1);
    }
}

// ---------------- LayerNorm + exact GELU --------------------------------------------
__device__ __forceinline__ float warpSum(float v) {
#pragma unroll
    for (int o = 16; o; o >>= 1) v += __shfl_xor_sync(0xffffffffu, v, o);
    return v;
}
__global__ void ln_gelu_kernel(float* __restrict__ t, const float* __restrict__ g,
                               const float* __restrict__ bb) {
    size_t row = blockIdx.x;
    int tid = threadIdx.x;
    float v = t[row * NC + tid];
    __shared__ float sm[6];
    int lane = tid & 31, w = tid >> 5;
    float s = warpSum(v);
    if (lane == 0) sm[w] = s;
    __syncthreads();
    float mean = 0.f;
#pragma unroll
    for (int i = 0; i < 6; i++) mean += sm[i];
    mean *= (1.0f / 192.0f);
    float d = v - mean;
    __syncthreads();
    s = warpSum(d * d);
    if (lane == 0) sm[w] = s;
    __syncthreads();
    float var = 0.f;
#pragma unroll
    for (int i = 0; i < 6; i++) var += sm[i];
    var *= (1.0f / 192.0f);
    float y = d * rsqrtf(var + 1e-5f) * g[tid] + bb[tid];
    t[row * NC + tid] = y * normcdff(y);
}

// ---------------- generic NT GEMM (projections) --------------------------------------
__global__ void __launch_bounds__(256) gemm_nt(
    const float* __restrict__ A, long long sA, int lda,
    const float* __restrict__ W, long long sW, int ldw,
    const float* __restrict__ bias,
    float* __restrict__ C, long long sC, int ldc,
    int M, int Nn, int K, float scale)
{
    __shared__ float As[16][132];
    __shared__ float Ws[16][68];
    int bz = blockIdx.z;
    const float* Ab = A + sA * bz;
    const float* Wb = W + sW * bz;
    float* Cb = C + sC * bz;
    int n0 = blockIdx.x * 64, m0 = blockIdx.y * 128;
    int tid = threadIdx.x;
    int tx = tid & 15, ty = tid >> 4;
    float acc[8][4];
#pragma unroll
    for (int i = 0; i < 8; i++)
#pragma unroll
        for (int j = 0; j < 4; j++) acc[i][j] = 0.f;

    for (int k0 = 0; k0 < K; k0 += 16) {
#pragma unroll
        for (int j = 0; j < 8; j++) {
            int idx = tid + j * 256;
            int kk = idx & 15, mm = idx >> 4;
            int gm = m0 + mm, gk = k0 + kk;
            As[kk][mm] = (gm < M && gk < K) ? Ab[(size_t)gm * lda + gk] : 0.f;
        }
#pragma unroll
        for (int j = 0; j < 4; j++) {
            int idx = tid + j * 256;
            int kk = idx & 15, nn = idx >> 4;
            int gn = n0 + nn, gk = k0 + kk;
            Ws[kk][nn] = (gn < Nn && gk < K) ? Wb[(size_t)gn * ldw + gk] : 0.f;
        }
        __syncthreads();
#pragma unroll
        for (int kk = 0; kk < 16; kk++) {
            float a[8], w[4];
#pragma unroll
            for (int i = 0; i < 8; i++) a[i] = As[kk][ty * 8 + i];
#pragma unroll
            for (int j = 0; j < 4; j++) w[j] = Ws[kk][tx * 4 + j];
#pragma unroll
            for (int i = 0; i < 8; i++)
#pragma unroll
                for (int j = 0; j < 4; j++) acc[i][j] = fmaf(a[i], w[j], acc[i][j]);
        }
        __syncthreads();
    }
#pragma unroll
    for (int i = 0; i < 8; i++) {
        int gm = m0 + ty * 8 + i;
        if (gm >= M) continue;
#pragma unroll
        for (int j = 0; j < 4; j++) {
            int gn = n0 + tx * 4 + j;
            if (gn < Nn) {
                float v = acc[i][j] * scale;
                if (bias) v += bias[gn];
                Cb[(size_t)gm * ldc + gn] = v;
            }
        }
    }
}

// ---------------- depthwise 3x3 on v, residual add -----------------------------------
__global__ void dwconv_kernel(const float* __restrict__ kv, const float* __restrict__ lw,
                              const float* __restrict__ lb, float* __restrict__ vp,
                              int side, int m)
{
    long long idx = (long long)blockIdx.x * 256 + threadIdx.x;
    long long total = (long long)NB * m * 64;
    if (idx >= total) return;
    int hd = (int)(idx & 63);
    long long pm = idx >> 6;
    int p = (int)(pm % m);
    int b = (int)(pm / m);
    int y = p / side, x = p % side;
    const float* vbase = kv + (size_t)b * m * 128 + 64 + hd;
    float s = lb[hd];
#pragma unroll
    for (int dy = 0; dy < 3; dy++) {
        int yy = y + dy - 1;
        if (yy < 0 || yy >= side) continue;
#pragma unroll
        for (int dx = 0; dx < 3; dx++) {
            int xx = x + dx - 1;
            if (xx < 0 || xx >= side) continue;
            s += lw[hd * 9 + dy * 3 + dx] * vbase[(size_t)(yy * side + xx) * 128];
        }
    }
    vp[idx] = vbase[(size_t)p * 128] + s;
}

// ---------------- host orchestration ---------------------------------------------------
extern "C" void kernel_launch(void* const* d_in, const int* in_sizes, int n_in,
                              void* d_out, int out_size)
{
    (void)in_sizes; (void)n_in; (void)out_size;
    const float* x    = (const float*)d_in[0];
    const float* q_w  = (const float*)d_in[1];
    const float* q_b  = (const float*)d_in[2];
    const float* kv_w = (const float*)d_in[3];
    const float* kv_b = (const float*)d_in[4];
    const float* sr_w[3] = {(const float*)d_in[5], (const float*)d_in[7], (const float*)d_in[9]};
    const float* sr_b[3] = {(const float*)d_in[6], (const float*)d_in[8], (const float*)d_in[10]};
    const float* ln_g[3] = {(const float*)d_in[11], (const float*)d_in[13], (const float*)d_in[15]};
    const float* ln_b[3] = {(const float*)d_in[12], (const float*)d_in[14], (const float*)d_in[16]};
    const float* lc_w[3] = {(const float*)d_in[17], (const float*)d_in[19], (const float*)d_in[21]};
    const float* lc_b[3] = {(const float*)d_in[18], (const float*)d_in[20], (const float*)d_in[22]};
    const float* nn1_w = (const float*)d_in[23];
    const float* nn1_b = (const float*)d_in[24];
    float* out = (float*)d_out;

    float *p_q, *p_t, *p_kv, *p_vp, *p_xcat;
    __nv_bfloat16 *p_xh, *p_xl, *p_qh, *p_ql, *p_kh, *p_kl;
    uint32_t *p_wp, *p_vkh, *p_vkl;
    cudaGetSymbolAddress((void**)&p_q,    g_q);
    cudaGetSymbolAddress((void**)&p_t,    g_t);
    cudaGetSymbolAddress((void**)&p_kv,   g_kv);
    cudaGetSymbolAddress((void**)&p_vp,   g_vp);
    cudaGetSymbolAddress((void**)&p_xcat, g_xcat);
    cudaGetSymbolAddress((void**)&p_xh,   g_xh);
    cudaGetSymbolAddress((void**)&p_xl,   g_xl);
    cudaGetSymbolAddress((void**)&p_wp,   g_wpack);
    cudaGetSymbolAddress((void**)&p_qh,   g_qh);
    cudaGetSymbolAddress((void**)&p_ql,   g_ql);
    cudaGetSymbolAddress((void**)&p_kh,   g_kh);
    cudaGetSymbolAddress((void**)&p_kl,   g_kl);
    cudaGetSymbolAddress((void**)&p_vkh,  g_vpkh);
    cudaGetSymbolAddress((void**)&p_vkl,  g_vpkl);

    cudaFuncSetAttribute(conv_hmma_kernel, cudaFuncAttributeMaxDynamicSharedMemorySize,
                         2 * CSTGW * 4);
    cudaFuncSetAttribute(attn_flash_kernel, cudaFuncAttributeMaxDynamicSharedMemorySize,
                         73728);

    prep_x_kernel<<<(NB * NTOK * NC + 255) / 256, 256>>>(x, p_xh, p_xl);

    gemm_nt<<<dim3(3, 128, 1), 256>>>(x, 0, NC, q_w, 0, NC, q_b,
                                      p_q, 0, NC, NB * NTOK, NC, NC, 1.f);

    const int KS[3] = {8, 4, 2};
    for (int h = 0; h < 3; h++) {
        int k = KS[h];
        int side = 64 - k + 1;
        int m = side * side;
        int k2 = k * k;
        int nchunk = (m + 63) / 64;
        long long Bm = (long long)NB * m;

        prep_w_kernel<<<(k2 * 12 * 32 * PN + 255) / 256, 256>>>(sr_w[h], p_wp, k2);
        conv_hmma_kernel<<<dim3((int)((Bm + 63) / 64), 2), 256, 2 * CSTGW * 4>>>(
            p_xh, p_xl, (const uint4*)p_wp, sr_b[h], p_t, k, side, m);
        ln_gelu_kernel<<<NB * m, 192>>>(p_t, ln_g[h], ln_b[h]);

        gemm_nt<<<dim3(2, (NB * m + 127) / 128, 1), 256>>>(
            p_t, 0, NC, kv_w, 0, NC, kv_b, p_kv, 0, 128, NB * m, 128, NC, 1.f);

        prep_q_kernel<<<(NB * NTOK * 64 + 255) / 256, 256>>>(p_q, p_qh, p_ql, h);
        prep_k_kernel<<<(NB * m * 64 + 255) / 256, 256>>>(p_kv, p_kh, p_kl, m);

        dwconv_kernel<<<(int)(((long long)NB * m * 64 + 255) / 256), 256>>>(
            p_kv, lc_w[h], lc_b[h], p_vp, side, m);
        pack_v_kernel<<<(NB * nchunk * 2048 + 255) / 256, 256>>>(p_vp, p_vkh, p_vkl, m, nchunk);

        attn_flash_kernel<<<dim3(NTOK / 128, NB), 256, 73728>>>(
            p_qh, p_ql, p_kh, p_kl, p_vkh, p_vkl, p_xcat + h * 64, m, nchunk);
    }

    gemm_nt<<<dim3(3, 128, 1), 256>>>(p_xcat, 0, NC, nn1_w, 0, NC, nn1_b,
                                      out, 0, NC, NB * NTOK, NC, NC, 1.f);
}

// round 11
// speedup vs baseline: 3.5952x; 1.0463x over previous
#include <cuda_runtime.h>
#include <cuda_bf16.h>
#include <math.h>
#include <stdint.h>

#define NB   4
#define NTOK 4096
#define NC   192
#define MAXM 3969
#define PN   104                         // conv B smem word pitch
#define CSTGW 11264                      // conv stage words: Ah2304+Al2304+B6656
#define FSTGW 9216                       // flash stage words: kh/kl/vh/vl x 2304

static const float ATT_SCALE = 0.07216878364870323f; // 192^-0.5

// ---------------- scratch -------------------------------------------------------
__device__ float g_q[NB * NTOK * NC];
__device__ float g_t[(size_t)NB * MAXM * NC];
__device__ float g_kv[NB * MAXM * 128];
__device__ float g_vp[NB * MAXM * 64];
__device__ float g_xcat[NB * NTOK * NC];
__device__ __nv_bfloat16 g_xh[NB * NTOK * NC];
__device__ __nv_bfloat16 g_xl[NB * NTOK * NC];
__device__ uint32_t g_wpack[768 * 32 * PN];
__device__ __nv_bfloat16 g_qh[NB * NTOK * 64];
__device__ __nv_bfloat16 g_ql[NB * NTOK * 64];
__device__ uint32_t g_kvimg[NB * 63 * FSTGW];   // per-chunk [kh|kl|vh|vl] images

// ---------------- helpers ---------------------------------------------------------
__device__ __forceinline__ uint32_t smem_u32(const void* p) {
    uint32_t a;
    asm("{ .reg .u64 t; cvta.to.shared.u64 t, %1; cvt.u32.u64 %0, t; }" : "=r"(a) : "l"(p));
    return a;
}
#define MMA16816(acc, a, b0, b1)                                                    \
    asm volatile("mma.sync.aligned.m16n8k16.row.col.f32.bf16.bf16.f32 "             \
        "{%0,%1,%2,%3}, {%4,%5,%6,%7}, {%8,%9}, {%0,%1,%2,%3};"                     \
        : "+f"((acc)[0]), "+f"((acc)[1]), "+f"((acc)[2]), "+f"((acc)[3])            \
        : "r"((a)[0]), "r"((a)[1]), "r"((a)[2]), "r"((a)[3]), "r"(b0), "r"(b1))
#define CPA16(dst, src)                                                             \
    asm volatile("cp.async.cg.shared.global [%0], [%1], 16;"                        \
        :: "r"(dst), "l"(src))
#define CPA_COMMIT() asm volatile("cp.async.commit_group;" ::: "memory")
#define CPA_WAIT1()  asm volatile("cp.async.wait_group 1;" ::: "memory")

__device__ __forceinline__ void split2(float a, float b, uint32_t& hi, uint32_t& lo) {
    __nv_bfloat16 ha = __float2bfloat16(a), hb = __float2bfloat16(b);
    float ra = a - __bfloat162float(ha);
    float rb = b - __bfloat162float(hb);
    __nv_bfloat16 la = __float2bfloat16(ra), lb = __float2bfloat16(rb);
    hi = ((uint32_t)*(unsigned short*)&hb << 16) | *(unsigned short*)&ha;
    lo = ((uint32_t)*(unsigned short*)&lb << 16) | *(unsigned short*)&la;
}

// ---------------- prep: split x into bf16 hi/lo -----------------------------------
__global__ void prep_x_kernel(const float* __restrict__ x, __nv_bfloat16* __restrict__ xh,
                              __nv_bfloat16* __restrict__ xl) {
    int i = blockIdx.x * 256 + threadIdx.x;
    if (i >= NB * NTOK * NC) return;
    float f = x[i];
    __nv_bfloat16 h = __float2bfloat16(f);
    xh[i] = h;
    xl[i] = __float2bfloat16(f - __bfloat162float(h));
}

// ---------------- prep: W -> packed word images ------------------------------------
__global__ void prep_w_kernel(const float* __restrict__ w, uint32_t* __restrict__ wp,
                              int k2) {
    int idx = blockIdx.x * 256 + threadIdx.x;
    int total = k2 * 12 * 32 * PN;
    if (idx >= total) return;
    int img = idx / (32 * PN), rem = idx % (32 * PN);
    int c2 = rem / PN, n = rem % PN;
    if (n >= 96) { wp[idx] = 0u; return; }
    int tap = img / 12, r = img % 12;
    int cb = r >> 2, r2 = r & 3;
    int cohalf = r2 >> 1, split = r2 & 1;
    int ci = cb * 64 + 2 * c2;
    int co = cohalf * 96 + n;
    float fe = w[((size_t)co * NC + ci) * k2 + tap];
    float fo = w[((size_t)co * NC + ci + 1) * k2 + tap];
    __nv_bfloat16 he = __float2bfloat16(fe), ho = __float2bfloat16(fo);
    __nv_bfloat16 ve = split ? __float2bfloat16(fe - __bfloat162float(he)) : he;
    __nv_bfloat16 vo = split ? __float2bfloat16(fo - __bfloat162float(ho)) : ho;
    uint32_t we = *(const unsigned short*)&ve;
    uint32_t wo = *(const unsigned short*)&vo;
    wp[idx] = (wo << 16) | we;
}

// ---------------- conv: implicit GEMM, HMMA, cp.async x2 (unchanged from R9) --------
__global__ void __launch_bounds__(256, 2) conv_hmma_kernel(
    const __nv_bfloat16* __restrict__ xh, const __nv_bfloat16* __restrict__ xl,
    const uint4* __restrict__ wp, const float* __restrict__ bias,
    float* __restrict__ out, int k, int side, int m)
{
    extern __shared__ uint32_t dsm[];

    int tid = threadIdx.x;
    int lane = tid & 31, wid = tid >> 5;
    int wm = wid & 1, wn = wid >> 1;
    long long Bm = (long long)NB * m;

    int arow = tid >> 2, aq = tid & 3;
    long long apx = (long long)blockIdx.x * 64 + arow;
    long long apxc = apx < Bm - 1 ? apx : Bm - 1;
    int ab = (int)(apxc / m), app = (int)(apxc % m);
    int aoy = app / side, aox = app % side;
    size_t axbase = (size_t)ab * NTOK * NC;
    int half = blockIdx.y;
    int rA = lane >> 2, cA = lane & 3;

    uint32_t smbase = smem_u32(dsm);
    uint32_t awd = smbase + (uint32_t)(arow * 36 + aq * 8) * 4;
    uint32_t bwd = smbase + 4608u * 4;

    float acc[2][3][4];
#pragma unroll
    for (int i = 0; i < 2; i++)
#pragma unroll
        for (int j = 0; j < 3; j++)
#pragma unroll
            for (int q = 0; q < 4; q++) acc[i][j][q] = 0.f;

    int k2 = k * k;
    int ng = k2 * 3;

#define CONV_ISSUE(g, s) do {                                                        \
        int _tap = (g) / 3, _cb = (g) - _tap * 3;                                    \
        int _dy = _tap / k, _dx = _tap - _dy * k;                                    \
        size_t _aoff = axbase + (size_t)((aoy + _dy) * 64 + aox + _dx) * NC          \
                     + _cb * 64 + aq * 16;                                           \
        uint32_t _soff = (uint32_t)(s) * (CSTGW * 4);                                \
        const char* _gh = (const char*)(xh + _aoff);                                 \
        const char* _gl = (const char*)(xl + _aoff);                                 \
        CPA16(awd + _soff,      _gh);                                                \
        CPA16(awd + _soff + 16, _gh + 16);                                           \
        CPA16(awd + _soff + 2304u * 4,      _gl);                                    \
        CPA16(awd + _soff + 2304u * 4 + 16, _gl + 16);                               \
        int _imgb = (_tap * 3 + _cb) * 4 + half * 2;                                 \
        const char* _gb = (const char*)(wp + (size_t)_imgb * (32 * PN / 4));         \
        _Pragma("unroll")                                                            \
        for (int _i = 0; _i < 7; _i++) {                                             \
            int _idx = tid + _i * 256;                                               \
            if (_idx < 1664) CPA16(bwd + _soff + _idx * 16, _gb + (size_t)_idx * 16);\
        }                                                                            \
    } while (0)

    CONV_ISSUE(0, 0);
    CPA_COMMIT();

    for (int g = 0; g < ng; g++) {
        if (g + 1 < ng) CONV_ISSUE(g + 1, (g + 1) & 1);
        CPA_COMMIT();
        CPA_WAIT1();
        __syncthreads();

        const uint32_t* stg = dsm + (g & 1) * CSTGW;
        const uint32_t* Ah = stg;
        const uint32_t* Al = stg + 2304;
        const uint32_t* B0 = stg + 4608;
        const uint32_t* B1 = stg + 7936;

#pragma unroll
        for (int ks = 0; ks < 4; ks++) {
            uint32_t ah[2][4], al[2][4];
#pragma unroll
            for (int i = 0; i < 2; i++) {
                int r = wm * 32 + i * 16 + rA;
                int c = 8 * ks + cA;
                ah[i][0] = Ah[r * 36 + c];
                ah[i][1] = Ah[(r + 8) * 36 + c];
                ah[i][2] = Ah[r * 36 + c + 4];
                ah[i][3] = Ah[(r + 8) * 36 + c + 4];
                al[i][0] = Al[r * 36 + c];
                al[i][1] = Al[(r + 8) * 36 + c];
                al[i][2] = Al[r * 36 + c + 4];
                al[i][3] = Al[(r + 8) * 36 + c + 4];
            }
            uint32_t b0[3][2], b1[3][2];
#pragma unroll
            for (int j = 0; j < 3; j++) {
                int n = wn * 24 + j * 8 + rA;
                b0[j][0] = B0[(8 * ks + cA) * PN + n];
                b0[j][1] = B0[(8 * ks + 4 + cA) * PN + n];
                b1[j][0] = B1[(8 * ks + cA) * PN + n];
                b1[j][1] = B1[(8 * ks + 4 + cA) * PN + n];
            }
#pragma unroll
            for (int i = 0; i < 2; i++)
#pragma unroll
                for (int j = 0; j < 3; j++) {
                    MMA16816(acc[i][j], ah[i], b0[j][0], b0[j][1]);
                    MMA16816(acc[i][j], ah[i], b1[j][0], b1[j][1]);
                    MMA16816(acc[i][j], al[i], b0[j][0], b0[j][1]);
                }
        }
        __syncthreads();
    }

#pragma unroll
    for (int i = 0; i < 2; i++) {
        long long row0 = (long long)blockIdx.x * 64 + wm * 32 + i * 16 + rA;
#pragma unroll
        for (int j = 0; j < 3; j++) {
            int col = half * 96 + wn * 24 + j * 8 + 2 * cA;
            float b0 = bias[col], b1 = bias[col + 1];
            if (row0 < Bm) {
                float2 v = make_float2(acc[i][j][0] + b0, acc[i][j][1] + b1);
                *(float2*)&out[row0 * NC + col] = v;
            }
            if (row0 + 8 < Bm) {
                float2 v = make_float2(acc[i][j][2] + b0, acc[i][j][3] + b1);
                *(float2*)&out[(row0 + 8) * NC + col] = v;
            }
        }
    }
#undef CONV_ISSUE
}

// ---------------- prep q split ------------------------------------------------------
__global__ void prep_q_kernel(const float* __restrict__ q, __nv_bfloat16* __restrict__ qh,
                              __nv_bfloat16* __restrict__ ql, int h) {
    int i = blockIdx.x * 256 + threadIdx.x;
    if (i >= NB * NTOK * 64) return;
    int c = i & 63;
    int row = i >> 6;
    float f = q[(size_t)row * NC + h * 64 + c];
    __nv_bfloat16 hi = __float2bfloat16(f);
    qh[i] = hi;
    ql[i] = __float2bfloat16(f - __bfloat162float(hi));
}

// ---------------- pack k + v' into per-chunk MMA image blocks ------------------------
// chunk block (FSTGW words): [kh | kl | vh | vl], each 32 x 72 (pitch 72, zero pad).
// k image word (c2, n)  = {k[m=cb+n][d=2c2+1], k[cb+n][2c2]}        (transposed)
// v image word (c2, n)  = {v'[m=cb+2c2+1][d=n], v'[cb+2c2][n]}
__global__ void pack_kv_kernel(const float* __restrict__ kv, const float* __restrict__ vp,
                               uint32_t* __restrict__ img, int m, int nchunk) {
    int idx = blockIdx.x * 256 + threadIdx.x;
    int total = NB * nchunk * FSTGW;
    if (idx >= total) return;
    int b = idx / (nchunk * FSTGW);
    int rem = idx % (nchunk * FSTGW);
    int c = rem / FSTGW;
    int r2 = rem % FSTGW;
    int sect = r2 / 2304;
    int r3 = r2 % 2304;
    int c2 = r3 / 72, n = r3 % 72;
    if (n >= 64) { img[idx] = 0u; return; }
    float f0, f1;
    if (sect < 2) {
        int mi = c * 64 + n;
        if (mi < m) {
            const float* kr = kv + ((size_t)b * m + mi) * 128;
            f0 = kr[2 * c2];
            f1 = kr[2 * c2 + 1];
        } else { f0 = f1 = 0.f; }
    } else {
        int k0 = c * 64 + 2 * c2;
        f0 = (k0 < m) ? vp[((size_t)b * m + k0) * 64 + n] : 0.f;
        f1 = (k0 + 1 < m) ? vp[((size_t)b * m + k0 + 1) * 64 + n] : 0.f;
    }
    uint32_t hi, lo;
    split2(f0, f1, hi, lo);
    img[idx] = (sect & 1) ? lo : hi;
}

// ---------------- fused flash attention, cp.async double-buffered --------------------
// CTA: 128 q rows (grid 32 x NB), 8 warps, warp owns 16 rows x full m loop.
__global__ void __launch_bounds__(256) attn_flash_kernel(
    const __nv_bfloat16* __restrict__ qh, const __nv_bfloat16* __restrict__ ql,
    const uint32_t* __restrict__ kvimg,
    float* __restrict__ out, int m, int nchunk)
{
    extern __shared__ uint32_t fsm[];
    uint32_t* sQh = fsm;              // 128*36
    uint32_t* sQl = fsm + 4608;       // 128*36
    // stages at fsm + 9216 + s*FSTGW : [kh|kl|vh|vl] each 2304 words

    int tid = threadIdx.x, lane = tid & 31, w = tid >> 5;
    int rA = lane >> 2, cA = lane & 3;
    int b = blockIdx.y;
    int q0 = blockIdx.x * 128;

    uint32_t stg_b = smem_u32(fsm) + 9216u * 4;

    {   // q fill (once, regular stores)
        int arow = tid >> 1, ahalf = tid & 1;
        size_t off = ((size_t)b * NTOK + q0 + arow) * 64 + ahalf * 32;
        const uint4* sh = (const uint4*)(qh + off);
        const uint4* sl = (const uint4*)(ql + off);
        uint32_t* dh = sQh + arow * 36 + ahalf * 16;
        uint32_t* dl = sQl + arow * 36 + ahalf * 16;
#pragma unroll
        for (int j = 0; j < 4; j++) { *(uint4*)&dh[j * 4] = sh[j]; *(uint4*)&dl[j * 4] = sl[j]; }
    }

#define FL_ISSUE(c, s) do {                                                          \
        const char* _src = (const char*)(kvimg + ((size_t)b * nchunk + (c)) * FSTGW);\
        uint32_t _dst = stg_b + (uint32_t)(s) * (FSTGW * 4);                         \
        _Pragma("unroll")                                                            \
        for (int _t = 0; _t < 9; _t++) {                                             \
            int _idx = tid + _t * 256;                                               \
            CPA16(_dst + _idx * 16, _src + (size_t)_idx * 16);                       \
        }                                                                            \
    } while (0)

    float acc_o[8][4];
#pragma unroll
    for (int nn = 0; nn < 8; nn++)
#pragma unroll
        for (int q = 0; q < 4; q++) acc_o[nn][q] = 0.f;
    float mrun0 = -1e30f, mrun1 = -1e30f, l0 = 0.f, l1 = 0.f;

    FL_ISSUE(0, 0);
    CPA_COMMIT();

    for (int c = 0; c < nchunk; c++) {
        if (c + 1 < nchunk) FL_ISSUE(c + 1, (c + 1) & 1);
        CPA_COMMIT();
        CPA_WAIT1();
        __syncthreads();

        const uint32_t* stg = fsm + 9216 + (c & 1) * FSTGW;
        const uint32_t* sKh = stg;
        const uint32_t* sKl = stg + 2304;
        const uint32_t* sVh = stg + 4608;
        const uint32_t* sVl = stg + 6912;

        // ---- S = q @ k^T (warp: 16 rows x 64 cols), 3-term split ----
        float s[8][4];
#pragma unroll
        for (int j = 0; j < 8; j++)
#pragma unroll
            for (int q = 0; q < 4; q++) s[j][q] = 0.f;

#pragma unroll
        for (int ks = 0; ks < 4; ks++) {
            uint32_t ah[4], al[4];
            int r = w * 16 + rA;
            int cc = 8 * ks + cA;
            ah[0] = sQh[r * 36 + cc];
            ah[1] = sQh[(r + 8) * 36 + cc];
            ah[2] = sQh[r * 36 + cc + 4];
            ah[3] = sQh[(r + 8) * 36 + cc + 4];
            al[0] = sQl[r * 36 + cc];
            al[1] = sQl[(r + 8) * 36 + cc];
            al[2] = sQl[r * 36 + cc + 4];
            al[3] = sQl[(r + 8) * 36 + cc + 4];
#pragma unroll
            for (int j = 0; j < 8; j++) {
                int n = j * 8 + rA;
                uint32_t bh0 = sKh[(8 * ks + cA) * 72 + n];
                uint32_t bh1 = sKh[(8 * ks + 4 + cA) * 72 + n];
                uint32_t bl0 = sKl[(8 * ks + cA) * 72 + n];
                uint32_t bl1 = sKl[(8 * ks + 4 + cA) * 72 + n];
                MMA16816(s[j], ah, bh0, bh1);
                MMA16816(s[j], ah, bl0, bl1);
                MMA16816(s[j], al, bh0, bh1);
            }
        }

        // ---- scale + mask padded cols (last chunk only) ----
        int cbase = c * 64;
        bool lastc = (cbase + 64 > m);
#pragma unroll
        for (int j = 0; j < 8; j++)
#pragma unroll
            for (int q = 0; q < 4; q++) {
                float v = s[j][q] * ATT_SCALE;
                if (lastc && (cbase + j * 8 + 2 * cA + (q & 1)) >= m) v = -1e30f;
                s[j][q] = v;
            }

        // ---- online softmax (rows rA and rA+8; reduce over quad lanes) ----
        float mx0 = -1e30f, mx1 = -1e30f;
#pragma unroll
        for (int j = 0; j < 8; j++) {
            mx0 = fmaxf(mx0, fmaxf(s[j][0], s[j][1]));
            mx1 = fmaxf(mx1, fmaxf(s[j][2], s[j][3]));
        }
        mx0 = fmaxf(mx0, __shfl_xor_sync(0xffffffffu, mx0, 1));
        mx0 = fmaxf(mx0, __shfl_xor_sync(0xffffffffu, mx0, 2));
        mx1 = fmaxf(mx1, __shfl_xor_sync(0xffffffffu, mx1, 1));
        mx1 = fmaxf(mx1, __shfl_xor_sync(0xffffffffu, mx1, 2));
        float mn0 = fmaxf(mrun0, mx0), mn1 = fmaxf(mrun1, mx1);
        float sc0 = __expf(mrun0 - mn0), sc1 = __expf(mrun1 - mn1);
        mrun0 = mn0; mrun1 = mn1;

        float sum0 = 0.f, sum1 = 0.f;
#pragma unroll
        for (int j = 0; j < 8; j++) {
            s[j][0] = __expf(s[j][0] - mn0);
            s[j][1] = __expf(s[j][1] - mn0);
            s[j][2] = __expf(s[j][2] - mn1);
            s[j][3] = __expf(s[j][3] - mn1);
            sum0 += s[j][0] + s[j][1];
            sum1 += s[j][2] + s[j][3];
        }
        sum0 += __shfl_xor_sync(0xffffffffu, sum0, 1);
        sum0 += __shfl_xor_sync(0xffffffffu, sum0, 2);
        sum1 += __shfl_xor_sync(0xffffffffu, sum1, 1);
        sum1 += __shfl_xor_sync(0xffffffffu, sum1, 2);
        l0 = l0 * sc0 + sum0;
        l1 = l1 * sc1 + sum1;

#pragma unroll
        for (int nn = 0; nn < 8; nn++) {
            acc_o[nn][0] *= sc0; acc_o[nn][1] *= sc0;
            acc_o[nn][2] *= sc1; acc_o[nn][3] *= sc1;
        }

        // ---- pack P into A-fragments (hi/lo split), in registers ----
        uint32_t aph[4][4], apl[4][4];
#pragma unroll
        for (int kk = 0; kk < 4; kk++) {
            split2(s[2 * kk][0],     s[2 * kk][1],     aph[kk][0], apl[kk][0]);
            split2(s[2 * kk][2],     s[2 * kk][3],     aph[kk][1], apl[kk][1]);
            split2(s[2 * kk + 1][0], s[2 * kk + 1][1], aph[kk][2], apl[kk][2]);
            split2(s[2 * kk + 1][2], s[2 * kk + 1][3], aph[kk][3], apl[kk][3]);
        }

        // ---- PV accumulate ----
#pragma unroll
        for (int kk = 0; kk < 4; kk++) {
#pragma unroll
            for (int nn = 0; nn < 8; nn++) {
                int n = nn * 8 + rA;
                uint32_t vh0 = sVh[(8 * kk + cA) * 72 + n];
                uint32_t vh1 = sVh[(8 * kk + 4 + cA) * 72 + n];
                uint32_t vl0 = sVl[(8 * kk + cA) * 72 + n];
                uint32_t vl1 = sVl[(8 * kk + 4 + cA) * 72 + n];
                MMA16816(acc_o[nn], aph[kk], vh0, vh1);
                MMA16816(acc_o[nn], aph[kk], vl0, vl1);
                MMA16816(acc_o[nn], apl[kk], vh0, vh1);
            }
        }
        __syncthreads();
    }
#undef FL_ISSUE

    // ---- epilogue: normalize and store ----
    float inv0 = 1.f / l0, inv1 = 1.f / l1;
    size_t row0 = (size_t)b * NTOK + q0 + w * 16 + rA;
#pragma unroll
    for (int nn = 0; nn < 8; nn++) {
        int col = nn * 8 + 2 * cA;
        *(float2*)&out[row0 * NC + col] =
            make_float2(acc_o[nn][0] * inv0, acc_o[nn][1] * inv0);
        *(float2*)&out[(row0 + 8) * NC + col] =
            make_float2(acc_o[nn][2] * inv1, acc_o[nn][3] * inv1);
    }
}

// ---------------- LayerNorm + exact GELU --------------------------------------------
__device__ __forceinline__ float warpSum(float v) {
#pragma unroll
    for (int o = 16; o; o >>= 1) v += __shfl_xor_sync(0xffffffffu, v, o);
    return v;
}
__global__ void ln_gelu_kernel(float* __restrict__ t, const float* __restrict__ g,
                               const float* __restrict__ bb) {
    size_t row = blockIdx.x;
    int tid = threadIdx.x;
    float v = t[row * NC + tid];
    __shared__ float sm[6];
    int lane = tid & 31, w = tid >> 5;
    float s = warpSum(v);
    if (lane == 0) sm[w] = s;
    __syncthreads();
    float mean = 0.f;
#pragma unroll
    for (int i = 0; i < 6; i++) mean += sm[i];
    mean *= (1.0f / 192.0f);
    float d = v - mean;
    __syncthreads();
    s = warpSum(d * d);
    if (lane == 0) sm[w] = s;
    __syncthreads();
    float var = 0.f;
#pragma unroll
    for (int i = 0; i < 6; i++) var += sm[i];
    var *= (1.0f / 192.0f);
    float y = d * rsqrtf(var + 1e-5f) * g[tid] + bb[tid];
    t[row * NC + tid] = y * normcdff(y);
}

// ---------------- generic NT GEMM (projections) --------------------------------------
__global__ void __launch_bounds__(256) gemm_nt(
    const float* __restrict__ A, long long sA, int lda,
    const float* __restrict__ W, long long sW, int ldw,
    const float* __restrict__ bias,
    float* __restrict__ C, long long sC, int ldc,
    int M, int Nn, int K, float scale)
{
    __shared__ float As[16][132];
    __shared__ float Ws[16][68];
    int bz = blockIdx.z;
    const float* Ab = A + sA * bz;
    const float* Wb = W + sW * bz;
    float* Cb = C + sC * bz;
    int n0 = blockIdx.x * 64, m0 = blockIdx.y * 128;
    int tid = threadIdx.x;
    int tx = tid & 15, ty = tid >> 4;
    float acc[8][4];
#pragma unroll
    for (int i = 0; i < 8; i++)
#pragma unroll
        for (int j = 0; j < 4; j++) acc[i][j] = 0.f;

    for (int k0 = 0; k0 < K; k0 += 16) {
#pragma unroll
        for (int j = 0; j < 8; j++) {
            int idx = tid + j * 256;
            int kk = idx & 15, mm = idx >> 4;
            int gm = m0 + mm, gk = k0 + kk;
            As[kk][mm] = (gm < M && gk < K) ? Ab[(size_t)gm * lda + gk] : 0.f;
        }
#pragma unroll
        for (int j = 0; j < 4; j++) {
            int idx = tid + j * 256;
            int kk = idx & 15, nn = idx >> 4;
            int gn = n0 + nn, gk = k0 + kk;
            Ws[kk][nn] = (gn < Nn && gk < K) ? Wb[(size_t)gn * ldw + gk] : 0.f;
        }
        __syncthreads();
#pragma unroll
        for (int kk = 0; kk < 16; kk++) {
            float a[8], w[4];
#pragma unroll
            for (int i = 0; i < 8; i++) a[i] = As[kk][ty * 8 + i];
#pragma unroll
            for (int j = 0; j < 4; j++) w[j] = Ws[kk][tx * 4 + j];
#pragma unroll
            for (int i = 0; i < 8; i++)
#pragma unroll
                for (int j = 0; j < 4; j++) acc[i][j] = fmaf(a[i], w[j], acc[i][j]);
        }
        __syncthreads();
    }
#pragma unroll
    for (int i = 0; i < 8; i++) {
        int gm = m0 + ty * 8 + i;
        if (gm >= M) continue;
#pragma unroll
        for (int j = 0; j < 4; j++) {
            int gn = n0 + tx * 4 + j;
            if (gn < Nn) {
                float v = acc[i][j] * scale;
                if (bias) v += bias[gn];
                Cb[(size_t)gm * ldc + gn] = v;
            }
        }
    }
}

// ---------------- depthwise 3x3 on v, residual add -----------------------------------
__global__ void dwconv_kernel(const float* __restrict__ kv, const float* __restrict__ lw,
                              const float* __restrict__ lb, float* __restrict__ vp,
                              int side, int m)
{
    long long idx = (long long)blockIdx.x * 256 + threadIdx.x;
    long long total = (long long)NB * m * 64;
    if (idx >= total) return;
    int hd = (int)(idx & 63);
    long long pm = idx >> 6;
    int p = (int)(pm % m);
    int b = (int)(pm / m);
    int y = p / side, x = p % side;
    const float* vbase = kv + (size_t)b * m * 128 + 64 + hd;
    float s = lb[hd];
#pragma unroll
    for (int dy = 0; dy < 3; dy++) {
        int yy = y + dy - 1;
        if (yy < 0 || yy >= side) continue;
#pragma unroll
        for (int dx = 0; dx < 3; dx++) {
            int xx = x + dx - 1;
            if (xx < 0 || xx >= side) continue;
            s += lw[hd * 9 + dy * 3 + dx] * vbase[(size_t)(yy * side + xx) * 128];
        }
    }
    vp[idx] = vbase[(size_t)p * 128] + s;
}

// ---------------- host orchestration ---------------------------------------------------
extern "C" void kernel_launch(void* const* d_in, const int* in_sizes, int n_in,
                              void* d_out, int out_size)
{
    (void)in_sizes; (void)n_in; (void)out_size;
    const float* x    = (const float*)d_in[0];
    const float* q_w  = (const float*)d_in[1];
    const float* q_b  = (const float*)d_in[2];
    const float* kv_w = (const float*)d_in[3];
    const float* kv_b = (const float*)d_in[4];
    const float* sr_w[3] = {(const float*)d_in[5], (const float*)d_in[7], (const float*)d_in[9]};
    const float* sr_b[3] = {(const float*)d_in[6], (const float*)d_in[8], (const float*)d_in[10]};
    const float* ln_g[3] = {(const float*)d_in[11], (const float*)d_in[13], (const float*)d_in[15]};
    const float* ln_b[3] = {(const float*)d_in[12], (const float*)d_in[14], (const float*)d_in[16]};
    const float* lc_w[3] = {(const float*)d_in[17], (const float*)d_in[19], (const float*)d_in[21]};
    const float* lc_b[3] = {(const float*)d_in[18], (const float*)d_in[20], (const float*)d_in[22]};
    const float* nn1_w = (const float*)d_in[23];
    const float* nn1_b = (const float*)d_in[24];
    float* out = (float*)d_out;

    float *p_q, *p_t, *p_kv, *p_vp, *p_xcat;
    __nv_bfloat16 *p_xh, *p_xl, *p_qh, *p_ql;
    uint32_t *p_wp, *p_kvimg;
    cudaGetSymbolAddress((void**)&p_q,    g_q);
    cudaGetSymbolAddress((void**)&p_t,    g_t);
    cudaGetSymbolAddress((void**)&p_kv,   g_kv);
    cudaGetSymbolAddress((void**)&p_vp,   g_vp);
    cudaGetSymbolAddress((void**)&p_xcat, g_xcat);
    cudaGetSymbolAddress((void**)&p_xh,   g_xh);
    cudaGetSymbolAddress((void**)&p_xl,   g_xl);
    cudaGetSymbolAddress((void**)&p_wp,   g_wpack);
    cudaGetSymbolAddress((void**)&p_qh,   g_qh);
    cudaGetSymbolAddress((void**)&p_ql,   g_ql);
    cudaGetSymbolAddress((void**)&p_kvimg, g_kvimg);

    cudaFuncSetAttribute(conv_hmma_kernel, cudaFuncAttributeMaxDynamicSharedMemorySize,
                         2 * CSTGW * 4);
    cudaFuncSetAttribute(attn_flash_kernel, cudaFuncAttributeMaxDynamicSharedMemorySize,
                         (9216 + 2 * FSTGW) * 4);

    prep_x_kernel<<<(NB * NTOK * NC + 255) / 256, 256>>>(x, p_xh, p_xl);

    gemm_nt<<<dim3(3, 128, 1), 256>>>(x, 0, NC, q_w, 0, NC, q_b,
                                      p_q, 0, NC, NB * NTOK, NC, NC, 1.f);

    const int KS[3] = {8, 4, 2};
    for (int h = 0; h < 3; h++) {
        int k = KS[h];
        int side = 64 - k + 1;
        int m = side * side;
        int k2 = k * k;
        int nchunk = (m + 63) / 64;
        long long Bm = (long long)NB * m;

        prep_w_kernel<<<(k2 * 12 * 32 * PN + 255) / 256, 256>>>(sr_w[h], p_wp, k2);
        conv_hmma_kernel<<<dim3((int)((Bm + 63) / 64), 2), 256, 2 * CSTGW * 4>>>(
            p_xh, p_xl, (const uint4*)p_wp, sr_b[h], p_t, k, side, m);
        ln_gelu_kernel<<<NB * m, 192>>>(p_t, ln_g[h], ln_b[h]);

        gemm_nt<<<dim3(2, (NB * m + 127) / 128, 1), 256>>>(
            p_t, 0, NC, kv_w, 0, NC, kv_b, p_kv, 0, 128, NB * m, 128, NC, 1.f);

        prep_q_kernel<<<(NB * NTOK * 64 + 255) / 256, 256>>>(p_q, p_qh, p_ql, h);

        dwconv_kernel<<<(int)(((long long)NB * m * 64 + 255) / 256), 256>>>(
            p_kv, lc_w[h], lc_b[h], p_vp, side, m);
        pack_kv_kernel<<<(NB * nchunk * FSTGW + 255) / 256, 256>>>(
            p_kv, p_vp, p_kvimg, m, nchunk);

        attn_flash_kernel<<<dim3(NTOK / 128, NB), 256, (9216 + 2 * FSTGW) * 4>>>(
            p_qh, p_ql, p_kvimg, p_xcat + h * 64, m, nchunk);
    }

    gemm_nt<<<dim3(3, 128, 1), 256>>>(p_xcat, 0, NC, nn1_w, 0, NC, nn1_b,
                                      out, 0, NC, NB * NTOK, NC, NC, 1.f);
}

// round 12
// speedup vs baseline: 3.8266x; 1.0644x over previous
#include <cuda_runtime.h>
#include <cuda_bf16.h>
#include <math.h>
#include <stdint.h>

#define NB   4
#define NTOK 4096
#define NC   192
#define MAXM 3969
#define PN   104                         // B smem word pitch (conv + proj)
#define CSTGW 11264                      // stage words: Ah2304+Al2304+B6656
#define FSTGW 9216                       // flash stage words: kh/kl/vh/vl x 2304

static const float ATT_SCALE = 0.07216878364870323f; // 192^-0.5

// ---------------- scratch -------------------------------------------------------
__device__ float g_q[NB * NTOK * NC];
__device__ float g_t[(size_t)NB * MAXM * NC];
__device__ float g_kv[NB * MAXM * 128];
__device__ float g_vp[NB * MAXM * 64];
__device__ __nv_bfloat16 g_xh[NB * NTOK * NC];
__device__ __nv_bfloat16 g_xl[NB * NTOK * NC];
__device__ __nv_bfloat16 g_th[(size_t)NB * MAXM * NC];
__device__ __nv_bfloat16 g_tl[(size_t)NB * MAXM * NC];
__device__ uint32_t g_xch[NB * NTOK * 96];      // xcat split hi (word pairs)
__device__ uint32_t g_xcl[NB * NTOK * 96];      // xcat split lo
__device__ uint32_t g_wpack[768 * 32 * PN];     // conv W images
__device__ uint32_t g_wq[12 * 32 * PN];         // q proj W images
__device__ uint32_t g_wkv[12 * 32 * PN];        // kv proj W images
__device__ uint32_t g_wnn[12 * 32 * PN];        // final proj W images
__device__ __nv_bfloat16 g_qh[NB * NTOK * 64];
__device__ __nv_bfloat16 g_ql[NB * NTOK * 64];
__device__ uint32_t g_kvimg[NB * 63 * FSTGW];   // per-chunk [kh|kl|vh|vl] images

// ---------------- helpers ---------------------------------------------------------
__device__ __forceinline__ uint32_t smem_u32(const void* p) {
    uint32_t a;
    asm("{ .reg .u64 t; cvta.to.shared.u64 t, %1; cvt.u32.u64 %0, t; }" : "=r"(a) : "l"(p));
    return a;
}
#define MMA16816(acc, a, b0, b1)                                                    \
    asm volatile("mma.sync.aligned.m16n8k16.row.col.f32.bf16.bf16.f32 "             \
        "{%0,%1,%2,%3}, {%4,%5,%6,%7}, {%8,%9}, {%0,%1,%2,%3};"                     \
        : "+f"((acc)[0]), "+f"((acc)[1]), "+f"((acc)[2]), "+f"((acc)[3])            \
        : "r"((a)[0]), "r"((a)[1]), "r"((a)[2]), "r"((a)[3]), "r"(b0), "r"(b1))
#define CPA16(dst, src)                                                             \
    asm volatile("cp.async.cg.shared.global [%0], [%1], 16;"                        \
        :: "r"(dst), "l"(src))
#define CPA_COMMIT() asm volatile("cp.async.commit_group;" ::: "memory")
#define CPA_WAIT1()  asm volatile("cp.async.wait_group 1;" ::: "memory")

__device__ __forceinline__ void split2(float a, float b, uint32_t& hi, uint32_t& lo) {
    __nv_bfloat16 ha = __float2bfloat16(a), hb = __float2bfloat16(b);
    float ra = a - __bfloat162float(ha);
    float rb = b - __bfloat162float(hb);
    __nv_bfloat16 la = __float2bfloat16(ra), lb = __float2bfloat16(rb);
    hi = ((uint32_t)*(unsigned short*)&hb << 16) | *(unsigned short*)&ha;
    lo = ((uint32_t)*(unsigned short*)&lb << 16) | *(unsigned short*)&la;
}

// ---------------- prep: split x into bf16 hi/lo -----------------------------------
__global__ void prep_x_kernel(const float* __restrict__ x, __nv_bfloat16* __restrict__ xh,
                              __nv_bfloat16* __restrict__ xl) {
    int i = blockIdx.x * 256 + threadIdx.x;
    if (i >= NB * NTOK * NC) return;
    float f = x[i];
    __nv_bfloat16 h = __float2bfloat16(f);
    xh[i] = h;
    xl[i] = __float2bfloat16(f - __bfloat162float(h));
}

// ---------------- prep: W -> packed word images (conv taps or k2=1 projections) -----
__global__ void prep_w_kernel(const float* __restrict__ w, uint32_t* __restrict__ wp,
                              int k2) {
    int idx = blockIdx.x * 256 + threadIdx.x;
    int total = k2 * 12 * 32 * PN;
    if (idx >= total) return;
    int img = idx / (32 * PN), rem = idx % (32 * PN);
    int c2 = rem / PN, n = rem % PN;
    if (n >= 96) { wp[idx] = 0u; return; }
    int tap = img / 12, r = img % 12;
    int cb = r >> 2, r2 = r & 3;
    int cohalf = r2 >> 1, split = r2 & 1;
    int ci = cb * 64 + 2 * c2;
    int co = cohalf * 96 + n;
    float fe = w[((size_t)co * NC + ci) * k2 + tap];
    float fo = w[((size_t)co * NC + ci + 1) * k2 + tap];
    __nv_bfloat16 he = __float2bfloat16(fe), ho = __float2bfloat16(fo);
    __nv_bfloat16 ve = split ? __float2bfloat16(fe - __bfloat162float(he)) : he;
    __nv_bfloat16 vo = split ? __float2bfloat16(fo - __bfloat162float(ho)) : ho;
    uint32_t we = *(const unsigned short*)&ve;
    uint32_t wo = *(const unsigned short*)&vo;
    wp[idx] = (wo << 16) | we;
}

// ---------------- conv: implicit GEMM, HMMA, cp.async x2 (unchanged) ----------------
__global__ void __launch_bounds__(256, 2) conv_hmma_kernel(
    const __nv_bfloat16* __restrict__ xh, const __nv_bfloat16* __restrict__ xl,
    const uint4* __restrict__ wp, const float* __restrict__ bias,
    float* __restrict__ out, int k, int side, int m)
{
    extern __shared__ uint32_t dsm[];

    int tid = threadIdx.x;
    int lane = tid & 31, wid = tid >> 5;
    int wm = wid & 1, wn = wid >> 1;
    long long Bm = (long long)NB * m;

    int arow = tid >> 2, aq = tid & 3;
    long long apx = (long long)blockIdx.x * 64 + arow;
    long long apxc = apx < Bm - 1 ? apx : Bm - 1;
    int ab = (int)(apxc / m), app = (int)(apxc % m);
    int aoy = app / side, aox = app % side;
    size_t axbase = (size_t)ab * NTOK * NC;
    int half = blockIdx.y;
    int rA = lane >> 2, cA = lane & 3;

    uint32_t smbase = smem_u32(dsm);
    uint32_t awd = smbase + (uint32_t)(arow * 36 + aq * 8) * 4;
    uint32_t bwd = smbase + 4608u * 4;

    float acc[2][3][4];
#pragma unroll
    for (int i = 0; i < 2; i++)
#pragma unroll
        for (int j = 0; j < 3; j++)
#pragma unroll
            for (int q = 0; q < 4; q++) acc[i][j][q] = 0.f;

    int k2 = k * k;
    int ng = k2 * 3;

#define CONV_ISSUE(g, s) do {                                                        \
        int _tap = (g) / 3, _cb = (g) - _tap * 3;                                    \
        int _dy = _tap / k, _dx = _tap - _dy * k;                                    \
        size_t _aoff = axbase + (size_t)((aoy + _dy) * 64 + aox + _dx) * NC          \
                     + _cb * 64 + aq * 16;                                           \
        uint32_t _soff = (uint32_t)(s) * (CSTGW * 4);                                \
        const char* _gh = (const char*)(xh + _aoff);                                 \
        const char* _gl = (const char*)(xl + _aoff);                                 \
        CPA16(awd + _soff,      _gh);                                                \
        CPA16(awd + _soff + 16, _gh + 16);                                           \
        CPA16(awd + _soff + 2304u * 4,      _gl);                                    \
        CPA16(awd + _soff + 2304u * 4 + 16, _gl + 16);                               \
        int _imgb = (_tap * 3 + _cb) * 4 + half * 2;                                 \
        const char* _gb = (const char*)(wp + (size_t)_imgb * (32 * PN / 4));         \
        _Pragma("unroll")                                                            \
        for (int _i = 0; _i < 7; _i++) {                                             \
            int _idx = tid + _i * 256;                                               \
            if (_idx < 1664) CPA16(bwd + _soff + _idx * 16, _gb + (size_t)_idx * 16);\
        }                                                                            \
    } while (0)

    CONV_ISSUE(0, 0);
    CPA_COMMIT();

    for (int g = 0; g < ng; g++) {
        if (g + 1 < ng) CONV_ISSUE(g + 1, (g + 1) & 1);
        CPA_COMMIT();
        CPA_WAIT1();
        __syncthreads();

        const uint32_t* stg = dsm + (g & 1) * CSTGW;
        const uint32_t* Ah = stg;
        const uint32_t* Al = stg + 2304;
        const uint32_t* B0 = stg + 4608;
        const uint32_t* B1 = stg + 7936;

#pragma unroll
        for (int ks = 0; ks < 4; ks++) {
            uint32_t ah[2][4], al[2][4];
#pragma unroll
            for (int i = 0; i < 2; i++) {
                int r = wm * 32 + i * 16 + rA;
                int c = 8 * ks + cA;
                ah[i][0] = Ah[r * 36 + c];
                ah[i][1] = Ah[(r + 8) * 36 + c];
                ah[i][2] = Ah[r * 36 + c + 4];
                ah[i][3] = Ah[(r + 8) * 36 + c + 4];
                al[i][0] = Al[r * 36 + c];
                al[i][1] = Al[(r + 8) * 36 + c];
                al[i][2] = Al[r * 36 + c + 4];
                al[i][3] = Al[(r + 8) * 36 + c + 4];
            }
            uint32_t b0[3][2], b1[3][2];
#pragma unroll
            for (int j = 0; j < 3; j++) {
                int n = wn * 24 + j * 8 + rA;
                b0[j][0] = B0[(8 * ks + cA) * PN + n];
                b0[j][1] = B0[(8 * ks + 4 + cA) * PN + n];
                b1[j][0] = B1[(8 * ks + cA) * PN + n];
                b1[j][1] = B1[(8 * ks + 4 + cA) * PN + n];
            }
#pragma unroll
            for (int i = 0; i < 2; i++)
#pragma unroll
                for (int j = 0; j < 3; j++) {
                    MMA16816(acc[i][j], ah[i], b0[j][0], b0[j][1]);
                    MMA16816(acc[i][j], ah[i], b1[j][0], b1[j][1]);
                    MMA16816(acc[i][j], al[i], b0[j][0], b0[j][1]);
                }
        }
        __syncthreads();
    }

#pragma unroll
    for (int i = 0; i < 2; i++) {
        long long row0 = (long long)blockIdx.x * 64 + wm * 32 + i * 16 + rA;
#pragma unroll
        for (int j = 0; j < 3; j++) {
            int col = half * 96 + wn * 24 + j * 8 + 2 * cA;
            float b0 = bias[col], b1 = bias[col + 1];
            if (row0 < Bm) {
                float2 v = make_float2(acc[i][j][0] + b0, acc[i][j][1] + b1);
                *(float2*)&out[row0 * NC + col] = v;
            }
            if (row0 + 8 < Bm) {
                float2 v = make_float2(acc[i][j][2] + b0, acc[i][j][3] + b1);
                *(float2*)&out[(row0 + 8) * NC + col] = v;
            }
        }
    }
#undef CONV_ISSUE
}

// ---------------- projection GEMM on HMMA: out = A @ W^T + bias ----------------------
// A split (Ah/Al bf16, rows x 192 row-major). CTA 64 rows x 96 cols (grid.y = half).
__global__ void __launch_bounds__(256, 2) gemm_hmma_kernel(
    const __nv_bfloat16* __restrict__ Ah_g, const __nv_bfloat16* __restrict__ Al_g,
    const uint4* __restrict__ wimg, const float* __restrict__ bias,
    float* __restrict__ out, long long rows, int ldout, int Nout)
{
    extern __shared__ uint32_t dsm[];

    int tid = threadIdx.x;
    int lane = tid & 31, wid = tid >> 5;
    int wm = wid & 1, wn = wid >> 1;

    int arow = tid >> 2, aq = tid & 3;
    long long r = (long long)blockIdx.x * 64 + arow;
    long long rc = r < rows - 1 ? r : rows - 1;
    int half = blockIdx.y;
    int rA = lane >> 2, cA = lane & 3;

    uint32_t smbase = smem_u32(dsm);
    uint32_t awd = smbase + (uint32_t)(arow * 36 + aq * 8) * 4;
    uint32_t bwd = smbase + 4608u * 4;

    float acc[2][3][4];
#pragma unroll
    for (int i = 0; i < 2; i++)
#pragma unroll
        for (int j = 0; j < 3; j++)
#pragma unroll
            for (int q = 0; q < 4; q++) acc[i][j][q] = 0.f;

#define PROJ_ISSUE(g, s) do {                                                        \
        size_t _aoff = (size_t)rc * NC + (g) * 64 + aq * 16;                         \
        uint32_t _soff = (uint32_t)(s) * (CSTGW * 4);                                \
        const char* _gh = (const char*)(Ah_g + _aoff);                               \
        const char* _gl = (const char*)(Al_g + _aoff);                               \
        CPA16(awd + _soff,      _gh);                                                \
        CPA16(awd + _soff + 16, _gh + 16);                                           \
        CPA16(awd + _soff + 2304u * 4,      _gl);                                    \
        CPA16(awd + _soff + 2304u * 4 + 16, _gl + 16);                               \
        int _imgb = (g) * 4 + half * 2;                                              \
        const char* _gb = (const char*)(wimg + (size_t)_imgb * (32 * PN / 4));       \
        _Pragma("unroll")                                                            \
        for (int _i = 0; _i < 7; _i++) {                                             \
            int _idx = tid + _i * 256;                                               \
            if (_idx < 1664) CPA16(bwd + _soff + _idx * 16, _gb + (size_t)_idx * 16);\
        }                                                                            \
    } while (0)

    PROJ_ISSUE(0, 0);
    CPA_COMMIT();

    for (int g = 0; g < 3; g++) {
        if (g + 1 < 3) PROJ_ISSUE(g + 1, (g + 1) & 1);
        CPA_COMMIT();
        CPA_WAIT1();
        __syncthreads();

        const uint32_t* stg = dsm + (g & 1) * CSTGW;
        const uint32_t* Ah = stg;
        const uint32_t* Al = stg + 2304;
        const uint32_t* B0 = stg + 4608;
        const uint32_t* B1 = stg + 7936;

#pragma unroll
        for (int ks = 0; ks < 4; ks++) {
            uint32_t ah[2][4], al[2][4];
#pragma unroll
            for (int i = 0; i < 2; i++) {
                int rr = wm * 32 + i * 16 + rA;
                int c = 8 * ks + cA;
                ah[i][0] = Ah[rr * 36 + c];
                ah[i][1] = Ah[(rr + 8) * 36 + c];
                ah[i][2] = Ah[rr * 36 + c + 4];
                ah[i][3] = Ah[(rr + 8) * 36 + c + 4];
                al[i][0] = Al[rr * 36 + c];
                al[i][1] = Al[(rr + 8) * 36 + c];
                al[i][2] = Al[rr * 36 + c + 4];
                al[i][3] = Al[(rr + 8) * 36 + c + 4];
            }
            uint32_t b0[3][2], b1[3][2];
#pragma unroll
            for (int j = 0; j < 3; j++) {
                int n = wn * 24 + j * 8 + rA;
                b0[j][0] = B0[(8 * ks + cA) * PN + n];
                b0[j][1] = B0[(8 * ks + 4 + cA) * PN + n];
                b1[j][0] = B1[(8 * ks + cA) * PN + n];
                b1[j][1] = B1[(8 * ks + 4 + cA) * PN + n];
            }
#pragma unroll
            for (int i = 0; i < 2; i++)
#pragma unroll
                for (int j = 0; j < 3; j++) {
                    MMA16816(acc[i][j], ah[i], b0[j][0], b0[j][1]);
                    MMA16816(acc[i][j], ah[i], b1[j][0], b1[j][1]);
                    MMA16816(acc[i][j], al[i], b0[j][0], b0[j][1]);
                }
        }
        __syncthreads();
    }
#undef PROJ_ISSUE

#pragma unroll
    for (int i = 0; i < 2; i++) {
        long long row0 = (long long)blockIdx.x * 64 + wm * 32 + i * 16 + rA;
#pragma unroll
        for (int j = 0; j < 3; j++) {
            int col = half * 96 + wn * 24 + j * 8 + 2 * cA;
            if (col >= Nout) continue;
            float b0 = bias[col], b1 = bias[col + 1];
            if (row0 < rows) {
                float2 v = make_float2(acc[i][j][0] + b0, acc[i][j][1] + b1);
                *(float2*)&out[row0 * ldout + col] = v;
            }
            if (row0 + 8 < rows) {
                float2 v = make_float2(acc[i][j][2] + b0, acc[i][j][3] + b1);
                *(float2*)&out[(row0 + 8) * ldout + col] = v;
            }
        }
    }
}

// ---------------- prep q split ------------------------------------------------------
__global__ void prep_q_kernel(const float* __restrict__ q, __nv_bfloat16* __restrict__ qh,
                              __nv_bfloat16* __restrict__ ql, int h) {
    int i = blockIdx.x * 256 + threadIdx.x;
    if (i >= NB * NTOK * 64) return;
    int c = i & 63;
    int row = i >> 6;
    float f = q[(size_t)row * NC + h * 64 + c];
    __nv_bfloat16 hi = __float2bfloat16(f);
    qh[i] = hi;
    ql[i] = __float2bfloat16(f - __bfloat162float(hi));
}

// ---------------- pack k + v' into per-chunk MMA image blocks ------------------------
__global__ void pack_kv_kernel(const float* __restrict__ kv, const float* __restrict__ vp,
                               uint32_t* __restrict__ img, int m, int nchunk) {
    int idx = blockIdx.x * 256 + threadIdx.x;
    int total = NB * nchunk * FSTGW;
    if (idx >= total) return;
    int b = idx / (nchunk * FSTGW);
    int rem = idx % (nchunk * FSTGW);
    int c = rem / FSTGW;
    int r2 = rem % FSTGW;
    int sect = r2 / 2304;
    int r3 = r2 % 2304;
    int c2 = r3 / 72, n = r3 % 72;
    if (n >= 64) { img[idx] = 0u; return; }
    float f0, f1;
    if (sect < 2) {
        int mi = c * 64 + n;
        if (mi < m) {
            const float* kr = kv + ((size_t)b * m + mi) * 128;
            f0 = kr[2 * c2];
            f1 = kr[2 * c2 + 1];
        } else { f0 = f1 = 0.f; }
    } else {
        int k0 = c * 64 + 2 * c2;
        f0 = (k0 < m) ? vp[((size_t)b * m + k0) * 64 + n] : 0.f;
        f1 = (k0 + 1 < m) ? vp[((size_t)b * m + k0 + 1) * 64 + n] : 0.f;
    }
    uint32_t hi, lo;
    split2(f0, f1, hi, lo);
    img[idx] = (sect & 1) ? lo : hi;
}

// ---------------- fused flash attention (xcat written as split bf16 words) -----------
__global__ void __launch_bounds__(256) attn_flash_kernel(
    const __nv_bfloat16* __restrict__ qh, const __nv_bfloat16* __restrict__ ql,
    const uint32_t* __restrict__ kvimg,
    uint32_t* __restrict__ xch, uint32_t* __restrict__ xcl,
    int hoff, int m, int nchunk)
{
    extern __shared__ uint32_t fsm[];
    uint32_t* sQh = fsm;
    uint32_t* sQl = fsm + 4608;

    int tid = threadIdx.x, lane = tid & 31, w = tid >> 5;
    int rA = lane >> 2, cA = lane & 3;
    int b = blockIdx.y;
    int q0 = blockIdx.x * 128;

    uint32_t stg_b = smem_u32(fsm) + 9216u * 4;

    {   // q fill
        int arow = tid >> 1, ahalf = tid & 1;
        size_t off = ((size_t)b * NTOK + q0 + arow) * 64 + ahalf * 32;
        const uint4* sh = (const uint4*)(qh + off);
        const uint4* sl = (const uint4*)(ql + off);
        uint32_t* dh = sQh + arow * 36 + ahalf * 16;
        uint32_t* dl = sQl + arow * 36 + ahalf * 16;
#pragma unroll
        for (int j = 0; j < 4; j++) { *(uint4*)&dh[j * 4] = sh[j]; *(uint4*)&dl[j * 4] = sl[j]; }
    }

#define FL_ISSUE(c, s) do {                                                          \
        const char* _src = (const char*)(kvimg + ((size_t)b * nchunk + (c)) * FSTGW);\
        uint32_t _dst = stg_b + (uint32_t)(s) * (FSTGW * 4);                         \
        _Pragma("unroll")                                                            \
        for (int _t = 0; _t < 9; _t++) {                                             \
            int _idx = tid + _t * 256;                                               \
            CPA16(_dst + _idx * 16, _src + (size_t)_idx * 16);                       \
        }                                                                            \
    } while (0)

    float acc_o[8][4];
#pragma unroll
    for (int nn = 0; nn < 8; nn++)
#pragma unroll
        for (int q = 0; q < 4; q++) acc_o[nn][q] = 0.f;
    float mrun0 = -1e30f, mrun1 = -1e30f, l0 = 0.f, l1 = 0.f;

    FL_ISSUE(0, 0);
    CPA_COMMIT();

    for (int c = 0; c < nchunk; c++) {
        if (c + 1 < nchunk) FL_ISSUE(c + 1, (c + 1) & 1);
        CPA_COMMIT();
        CPA_WAIT1();
        __syncthreads();

        const uint32_t* stg = fsm + 9216 + (c & 1) * FSTGW;
        const uint32_t* sKh = stg;
        const uint32_t* sKl = stg + 2304;
        const uint32_t* sVh = stg + 4608;
        const uint32_t* sVl = stg + 6912;

        float s[8][4];
#pragma unroll
        for (int j = 0; j < 8; j++)
#pragma unroll
            for (int q = 0; q < 4; q++) s[j][q] = 0.f;

#pragma unroll
        for (int ks = 0; ks < 4; ks++) {
            uint32_t ah[4], al[4];
            int r = w * 16 + rA;
            int cc = 8 * ks + cA;
            ah[0] = sQh[r * 36 + cc];
            ah[1] = sQh[(r + 8) * 36 + cc];
            ah[2] = sQh[r * 36 + cc + 4];
            ah[3] = sQh[(r + 8) * 36 + cc + 4];
            al[0] = sQl[r * 36 + cc];
            al[1] = sQl[(r + 8) * 36 + cc];
            al[2] = sQl[r * 36 + cc + 4];
            al[3] = sQl[(r + 8) * 36 + cc + 4];
#pragma unroll
            for (int j = 0; j < 8; j++) {
                int n = j * 8 + rA;
                uint32_t bh0 = sKh[(8 * ks + cA) * 72 + n];
                uint32_t bh1 = sKh[(8 * ks + 4 + cA) * 72 + n];
                uint32_t bl0 = sKl[(8 * ks + cA) * 72 + n];
                uint32_t bl1 = sKl[(8 * ks + 4 + cA) * 72 + n];
                MMA16816(s[j], ah, bh0, bh1);
                MMA16816(s[j], ah, bl0, bl1);
                MMA16816(s[j], al, bh0, bh1);
            }
        }

        int cbase = c * 64;
        bool lastc = (cbase + 64 > m);
#pragma unroll
        for (int j = 0; j < 8; j++)
#pragma unroll
            for (int q = 0; q < 4; q++) {
                float v = s[j][q] * ATT_SCALE;
                if (lastc && (cbase + j * 8 + 2 * cA + (q & 1)) >= m) v = -1e30f;
                s[j][q] = v;
            }

        float mx0 = -1e30f, mx1 = -1e30f;
#pragma unroll
        for (int j = 0; j < 8; j++) {
            mx0 = fmaxf(mx0, fmaxf(s[j][0], s[j][1]));
            mx1 = fmaxf(mx1, fmaxf(s[j][2], s[j][3]));
        }
        mx0 = fmaxf(mx0, __shfl_xor_sync(0xffffffffu, mx0, 1));
        mx0 = fmaxf(mx0, __shfl_xor_sync(0xffffffffu, mx0, 2));
        mx1 = fmaxf(mx1, __shfl_xor_sync(0xffffffffu, mx1, 1));
        mx1 = fmaxf(mx1, __shfl_xor_sync(0xffffffffu, mx1, 2));
        float mn0 = fmaxf(mrun0, mx0), mn1 = fmaxf(mrun1, mx1);
        float sc0 = __expf(mrun0 - mn0), sc1 = __expf(mrun1 - mn1);
        mrun0 = mn0; mrun1 = mn1;

        float sum0 = 0.f, sum1 = 0.f;
#pragma unroll
        for (int j = 0; j < 8; j++) {
            s[j][0] = __expf(s[j][0] - mn0);
            s[j][1] = __expf(s[j][1] - mn0);
            s[j][2] = __expf(s[j][2] - mn1);
            s[j][3] = __expf(s[j][3] - mn1);
            sum0 += s[j][0] + s[j][1];
            sum1 += s[j][2] + s[j][3];
        }
        sum0 += __shfl_xor_sync(0xffffffffu, sum0, 1);
        sum0 += __shfl_xor_sync(0xffffffffu, sum0, 2);
        sum1 += __shfl_xor_sync(0xffffffffu, sum1, 1);
        sum1 += __shfl_xor_sync(0xffffffffu, sum1, 2);
        l0 = l0 * sc0 + sum0;
        l1 = l1 * sc1 + sum1;

#pragma unroll
        for (int nn = 0; nn < 8; nn++) {
            acc_o[nn][0] *= sc0; acc_o[nn][1] *= sc0;
            acc_o[nn][2] *= sc1; acc_o[nn][3] *= sc1;
        }

        uint32_t aph[4][4], apl[4][4];
#pragma unroll
        for (int kk = 0; kk < 4; kk++) {
            split2(s[2 * kk][0],     s[2 * kk][1],     aph[kk][0], apl[kk][0]);
            split2(s[2 * kk][2],     s[2 * kk][3],     aph[kk][1], apl[kk][1]);
            split2(s[2 * kk + 1][0], s[2 * kk + 1][1], aph[kk][2], apl[kk][2]);
            split2(s[2 * kk + 1][2], s[2 * kk + 1][3], aph[kk][3], apl[kk][3]);
        }

#pragma unroll
        for (int kk = 0; kk < 4; kk++) {
#pragma unroll
            for (int nn = 0; nn < 8; nn++) {
                int n = nn * 8 + rA;
                uint32_t vh0 = sVh[(8 * kk + cA) * 72 + n];
                uint32_t vh1 = sVh[(8 * kk + 4 + cA) * 72 + n];
                uint32_t vl0 = sVl[(8 * kk + cA) * 72 + n];
                uint32_t vl1 = sVl[(8 * kk + 4 + cA) * 72 + n];
                MMA16816(acc_o[nn], aph[kk], vh0, vh1);
                MMA16816(acc_o[nn], aph[kk], vl0, vl1);
                MMA16816(acc_o[nn], apl[kk], vh0, vh1);
            }
        }
        __syncthreads();
    }
#undef FL_ISSUE

    // epilogue: normalize and store as split bf16 word-pairs into xcat
    float inv0 = 1.f / l0, inv1 = 1.f / l1;
    size_t row0 = (size_t)b * NTOK + q0 + w * 16 + rA;
#pragma unroll
    for (int nn = 0; nn < 8; nn++) {
        int col = nn * 8 + 2 * cA;
        size_t w0 = row0 * 96 + (size_t)((hoff + col) >> 1);
        size_t w1 = (row0 + 8) * 96 + (size_t)((hoff + col) >> 1);
        uint32_t hi, lo;
        split2(acc_o[nn][0] * inv0, acc_o[nn][1] * inv0, hi, lo);
        xch[w0] = hi; xcl[w0] = lo;
        split2(acc_o[nn][2] * inv1, acc_o[nn][3] * inv1, hi, lo);
        xch[w1] = hi; xcl[w1] = lo;
    }
}

// ---------------- LayerNorm + exact GELU -> split bf16 -------------------------------
__device__ __forceinline__ float warpSum(float v) {
#pragma unroll
    for (int o = 16; o; o >>= 1) v += __shfl_xor_sync(0xffffffffu, v, o);
    return v;
}
__global__ void ln_gelu_kernel(const float* __restrict__ t, const float* __restrict__ g,
                               const float* __restrict__ bb,
                               __nv_bfloat16* __restrict__ th, __nv_bfloat16* __restrict__ tl) {
    size_t row = blockIdx.x;
    int tid = threadIdx.x;
    float v = t[row * NC + tid];
    __shared__ float sm[6];
    int lane = tid & 31, w = tid >> 5;
    float s = warpSum(v);
    if (lane == 0) sm[w] = s;
    __syncthreads();
    float mean = 0.f;
#pragma unroll
    for (int i = 0; i < 6; i++) mean += sm[i];
    mean *= (1.0f / 192.0f);
    float d = v - mean;
    __syncthreads();
    s = warpSum(d * d);
    if (lane == 0) sm[w] = s;
    __syncthreads();
    float var = 0.f;
#pragma unroll
    for (int i = 0; i < 6; i++) var += sm[i];
    var *= (1.0f / 192.0f);
    float y = d * rsqrtf(var + 1e-5f) * g[tid] + bb[tid];
    float r = y * normcdff(y);
    __nv_bfloat16 hi = __float2bfloat16(r);
    th[row * NC + tid] = hi;
    tl[row * NC + tid] = __float2bfloat16(r - __bfloat162float(hi));
}

// ---------------- depthwise 3x3 on v, residual add -----------------------------------
__global__ void dwconv_kernel(const float* __restrict__ kv, const float* __restrict__ lw,
                              const float* __restrict__ lb, float* __restrict__ vp,
                              int side, int m)
{
    long long idx = (long long)blockIdx.x * 256 + threadIdx.x;
    long long total = (long long)NB * m * 64;
    if (idx >= total) return;
    int hd = (int)(idx & 63);
    long long pm = idx >> 6;
    int p = (int)(pm % m);
    int b = (int)(pm / m);
    int y = p / side, x = p % side;
    const float* vbase = kv + (size_t)b * m * 128 + 64 + hd;
    float s = lb[hd];
#pragma unroll
    for (int dy = 0; dy < 3; dy++) {
        int yy = y + dy - 1;
        if (yy < 0 || yy >= side) continue;
#pragma unroll
        for (int dx = 0; dx < 3; dx++) {
            int xx = x + dx - 1;
            if (xx < 0 || xx >= side) continue;
            s += lw[hd * 9 + dy * 3 + dx] * vbase[(size_t)(yy * side + xx) * 128];
        }
    }
    vp[idx] = vbase[(size_t)p * 128] + s;
}

// ---------------- host orchestration ---------------------------------------------------
extern "C" void kernel_launch(void* const* d_in, const int* in_sizes, int n_in,
                              void* d_out, int out_size)
{
    (void)in_sizes; (void)n_in; (void)out_size;
    const float* x    = (const float*)d_in[0];
    const float* q_w  = (const float*)d_in[1];
    const float* q_b  = (const float*)d_in[2];
    const float* kv_w = (const float*)d_in[3];
    const float* kv_b = (const float*)d_in[4];
    const float* sr_w[3] = {(const float*)d_in[5], (const float*)d_in[7], (const float*)d_in[9]};
    const float* sr_b[3] = {(const float*)d_in[6], (const float*)d_in[8], (const float*)d_in[10]};
    const float* ln_g[3] = {(const float*)d_in[11], (const float*)d_in[13], (const float*)d_in[15]};
    const float* ln_b[3] = {(const float*)d_in[12], (const float*)d_in[14], (const float*)d_in[16]};
    const float* lc_w[3] = {(const float*)d_in[17], (const float*)d_in[19], (const float*)d_in[21]};
    const float* lc_b[3] = {(const float*)d_in[18], (const float*)d_in[20], (const float*)d_in[22]};
    const float* nn1_w = (const float*)d_in[23];
    const float* nn1_b = (const float*)d_in[24];
    float* out = (float*)d_out;

    float *p_q, *p_t, *p_kv, *p_vp;
    __nv_bfloat16 *p_xh, *p_xl, *p_th, *p_tl, *p_qh, *p_ql;
    uint32_t *p_wp, *p_wq, *p_wkv, *p_wnn, *p_kvimg, *p_xch, *p_xcl;
    cudaGetSymbolAddress((void**)&p_q,    g_q);
    cudaGetSymbolAddress((void**)&p_t,    g_t);
    cudaGetSymbolAddress((void**)&p_kv,   g_kv);
    cudaGetSymbolAddress((void**)&p_vp,   g_vp);
    cudaGetSymbolAddress((void**)&p_xh,   g_xh);
    cudaGetSymbolAddress((void**)&p_xl,   g_xl);
    cudaGetSymbolAddress((void**)&p_th,   g_th);
    cudaGetSymbolAddress((void**)&p_tl,   g_tl);
    cudaGetSymbolAddress((void**)&p_wp,   g_wpack);
    cudaGetSymbolAddress((void**)&p_wq,   g_wq);
    cudaGetSymbolAddress((void**)&p_wkv,  g_wkv);
    cudaGetSymbolAddress((void**)&p_wnn,  g_wnn);
    cudaGetSymbolAddress((void**)&p_qh,   g_qh);
    cudaGetSymbolAddress((void**)&p_ql,   g_ql);
    cudaGetSymbolAddress((void**)&p_kvimg, g_kvimg);
    cudaGetSymbolAddress((void**)&p_xch,  g_xch);
    cudaGetSymbolAddress((void**)&p_xcl,  g_xcl);

    cudaFuncSetAttribute(conv_hmma_kernel, cudaFuncAttributeMaxDynamicSharedMemorySize,
                         2 * CSTGW * 4);
    cudaFuncSetAttribute(gemm_hmma_kernel, cudaFuncAttributeMaxDynamicSharedMemorySize,
                         2 * CSTGW * 4);
    cudaFuncSetAttribute(attn_flash_kernel, cudaFuncAttributeMaxDynamicSharedMemorySize,
                         (9216 + 2 * FSTGW) * 4);

    const int WPROJ = 12 * 32 * PN;

    prep_x_kernel<<<(NB * NTOK * NC + 255) / 256, 256>>>(x, p_xh, p_xl);
    prep_w_kernel<<<(WPROJ + 255) / 256, 256>>>(q_w, p_wq, 1);
    prep_w_kernel<<<(WPROJ + 255) / 256, 256>>>(kv_w, p_wkv, 1);
    prep_w_kernel<<<(WPROJ + 255) / 256, 256>>>(nn1_w, p_wnn, 1);

    // q projection (HMMA)
    gemm_hmma_kernel<<<dim3((NB * NTOK + 63) / 64, 2), 256, 2 * CSTGW * 4>>>(
        p_xh, p_xl, (const uint4*)p_wq, q_b, p_q, (long long)NB * NTOK, NC, NC);

    const int KS[3] = {8, 4, 2};
    for (int h = 0; h < 3; h++) {
        int k = KS[h];
        int side = 64 - k + 1;
        int m = side * side;
        int k2 = k * k;
        int nchunk = (m + 63) / 64;
        long long Bm = (long long)NB * m;

        prep_w_kernel<<<(k2 * WPROJ + 255) / 256, 256>>>(sr_w[h], p_wp, k2);
        conv_hmma_kernel<<<dim3((int)((Bm + 63) / 64), 2), 256, 2 * CSTGW * 4>>>(
            p_xh, p_xl, (const uint4*)p_wp, sr_b[h], p_t, k, side, m);
        ln_gelu_kernel<<<NB * m, 192>>>(p_t, ln_g[h], ln_b[h], p_th, p_tl);

        // kv projection (HMMA, N=128)
        gemm_hmma_kernel<<<dim3((int)((Bm + 63) / 64), 2), 256, 2 * CSTGW * 4>>>(
            p_th, p_tl, (const uint4*)p_wkv, kv_b, p_kv, Bm, 128, 128);

        prep_q_kernel<<<(NB * NTOK * 64 + 255) / 256, 256>>>(p_q, p_qh, p_ql, h);

        dwconv_kernel<<<(int)(((long long)NB * m * 64 + 255) / 256), 256>>>(
            p_kv, lc_w[h], lc_b[h], p_vp, side, m);
        pack_kv_kernel<<<(NB * nchunk * FSTGW + 255) / 256, 256>>>(
            p_kv, p_vp, p_kvimg, m, nchunk);

        attn_flash_kernel<<<dim3(NTOK / 128, NB), 256, (9216 + 2 * FSTGW) * 4>>>(
            p_qh, p_ql, p_kvimg, p_xch, p_xcl, h * 64, m, nchunk);
    }

    // final projection (HMMA)
    gemm_hmma_kernel<<<dim3((NB * NTOK + 63) / 64, 2), 256, 2 * CSTGW * 4>>>(
        (const __nv_bfloat16*)p_xch, (const __nv_bfloat16*)p_xcl,
        (const uint4*)p_wnn, nn1_b, out, (long long)NB * NTOK, NC, NC);
}

// round 13
// speedup vs baseline: 3.9462x; 1.0313x over previous
#include <cuda_runtime.h>
#include <cuda_bf16.h>
#include <math.h>
#include <stdint.h>

#define NB   4
#define NTOK 4096
#define NC   192
#define MAXM 3969
#define BIMG 3456                        // B image words: 96 rows x 36 pitch
#define CSTGW 11520                      // stage words: Ah2304+Al2304+B0 3456+B1 3456
#define FSTGW 9216                       // flash stage words: kh/kl/vh/vl x 2304

static const float ATT_SCALE = 0.07216878364870323f; // 192^-0.5

// ---------------- scratch -------------------------------------------------------
__device__ float g_q[NB * NTOK * NC];
__device__ float g_t[(size_t)NB * MAXM * NC];
__device__ float g_kv[NB * MAXM * 128];
__device__ float g_vp[NB * MAXM * 64];
__device__ __nv_bfloat16 g_xh[NB * NTOK * NC];
__device__ __nv_bfloat16 g_xl[NB * NTOK * NC];
__device__ __nv_bfloat16 g_th[(size_t)NB * MAXM * NC];
__device__ __nv_bfloat16 g_tl[(size_t)NB * MAXM * NC];
__device__ uint32_t g_xch[NB * NTOK * 96];
__device__ uint32_t g_xcl[NB * NTOK * 96];
__device__ uint32_t g_wpack[768 * BIMG];        // conv W images (n-major)
__device__ uint32_t g_wq[12 * BIMG];
__device__ uint32_t g_wkv[12 * BIMG];
__device__ uint32_t g_wnn[12 * BIMG];
__device__ __nv_bfloat16 g_qh[NB * NTOK * 64];
__device__ __nv_bfloat16 g_ql[NB * NTOK * 64];
__device__ uint32_t g_kvimg[NB * 63 * FSTGW];

// ---------------- helpers ---------------------------------------------------------
__device__ __forceinline__ uint32_t smem_u32(const void* p) {
    uint32_t a;
    asm("{ .reg .u64 t; cvta.to.shared.u64 t, %1; cvt.u32.u64 %0, t; }" : "=r"(a) : "l"(p));
    return a;
}
#define MMA16816(acc, a, b0, b1)                                                    \
    asm volatile("mma.sync.aligned.m16n8k16.row.col.f32.bf16.bf16.f32 "             \
        "{%0,%1,%2,%3}, {%4,%5,%6,%7}, {%8,%9}, {%0,%1,%2,%3};"                     \
        : "+f"((acc)[0]), "+f"((acc)[1]), "+f"((acc)[2]), "+f"((acc)[3])            \
        : "r"((a)[0]), "r"((a)[1]), "r"((a)[2]), "r"((a)[3]), "r"(b0), "r"(b1))
#define LDSM4(r0, r1, r2, r3, addr)                                                 \
    asm volatile("ldmatrix.sync.aligned.m8n8.x4.shared.b16 {%0,%1,%2,%3}, [%4];"    \
        : "=r"(r0), "=r"(r1), "=r"(r2), "=r"(r3) : "r"(addr))
#define LDSM2(r0, r1, addr)                                                         \
    asm volatile("ldmatrix.sync.aligned.m8n8.x2.shared.b16 {%0,%1}, [%2];"          \
        : "=r"(r0), "=r"(r1) : "r"(addr))
#define CPA16(dst, src)                                                             \
    asm volatile("cp.async.cg.shared.global [%0], [%1], 16;"                        \
        :: "r"(dst), "l"(src))
#define CPA_COMMIT() asm volatile("cp.async.commit_group;" ::: "memory")
#define CPA_WAIT1()  asm volatile("cp.async.wait_group 1;" ::: "memory")

__device__ __forceinline__ void split2(float a, float b, uint32_t& hi, uint32_t& lo) {
    __nv_bfloat16 ha = __float2bfloat16(a), hb = __float2bfloat16(b);
    float ra = a - __bfloat162float(ha);
    float rb = b - __bfloat162float(hb);
    __nv_bfloat16 la = __float2bfloat16(ra), lb = __float2bfloat16(rb);
    hi = ((uint32_t)*(unsigned short*)&hb << 16) | *(unsigned short*)&ha;
    lo = ((uint32_t)*(unsigned short*)&lb << 16) | *(unsigned short*)&la;
}

// ---------------- prep: split x into bf16 hi/lo -----------------------------------
__global__ void prep_x_kernel(const float* __restrict__ x, __nv_bfloat16* __restrict__ xh,
                              __nv_bfloat16* __restrict__ xl) {
    int i = blockIdx.x * 256 + threadIdx.x;
    if (i >= NB * NTOK * NC) return;
    float f = x[i];
    __nv_bfloat16 h = __float2bfloat16(f);
    xh[i] = h;
    xl[i] = __float2bfloat16(f - __bfloat162float(h));
}

// ---------------- prep: W -> n-major packed word images -----------------------------
// img = ((tap*3 + cb)*2 + cohalf)*2 + split; image = 96 rows(n) x 36 words (32 used).
// word(n, c2) = {bf16 W[ci=cb*64+2c2+1, co], bf16 W[cb*64+2c2, co]}, co = cohalf*96+n.
__global__ void prep_w_kernel(const float* __restrict__ w, uint32_t* __restrict__ wp,
                              int k2) {
    int idx = blockIdx.x * 256 + threadIdx.x;
    int total = k2 * 12 * BIMG;
    if (idx >= total) return;
    int img = idx / BIMG, rem = idx % BIMG;
    int n = rem / 36, c2 = rem % 36;
    if (c2 >= 32) { wp[idx] = 0u; return; }
    int tap = img / 12, r = img % 12;
    int cb = r >> 2, r2 = r & 3;
    int cohalf = r2 >> 1, split = r2 & 1;
    int ci = cb * 64 + 2 * c2;
    int co = cohalf * 96 + n;
    float fe = w[((size_t)co * NC + ci) * k2 + tap];
    float fo = w[((size_t)co * NC + ci + 1) * k2 + tap];
    __nv_bfloat16 he = __float2bfloat16(fe), ho = __float2bfloat16(fo);
    __nv_bfloat16 ve = split ? __float2bfloat16(fe - __bfloat162float(he)) : he;
    __nv_bfloat16 vo = split ? __float2bfloat16(fo - __bfloat162float(ho)) : ho;
    uint32_t we = *(const unsigned short*)&ve;
    uint32_t wo = *(const unsigned short*)&vo;
    wp[idx] = (wo << 16) | we;
}

// ---------------- shared compute core (ldmatrix + MMA), used by conv & proj ---------
// acc[2][3][4]; addresses precomputed per thread.
#define HMMA_GROUP_COMPUTE(soff)                                                     \
    _Pragma("unroll")                                                                \
    for (int ks = 0; ks < 4; ks++) {                                                 \
        uint32_t kb = (uint32_t)(ks * 32);                                           \
        uint32_t ah[4], ah2[4], al[4], al2[4];                                       \
        LDSM4(ah[0], ah[1], ah[2], ah[3], aoff0 + (soff) + kb);                      \
        LDSM4(ah2[0], ah2[1], ah2[2], ah2[3], aoff1 + (soff) + kb);                  \
        LDSM4(al[0], al[1], al[2], al[3], aoff0 + (soff) + 9216u + kb);              \
        LDSM4(al2[0], al2[1], al2[2], al2[3], aoff1 + (soff) + 9216u + kb);          \
        uint32_t wh[3][2], wl[3][2];                                                 \
        LDSM4(wh[0][0], wh[0][1], wh[1][0], wh[1][1], boff01 + (soff) + kb);         \
        LDSM2(wh[2][0], wh[2][1], boff2 + (soff) + kb);                              \
        LDSM4(wl[0][0], wl[0][1], wl[1][0], wl[1][1], boff01 + (soff) + 13824u + kb);\
        LDSM2(wl[2][0], wl[2][1], boff2 + (soff) + 13824u + kb);                     \
        _Pragma("unroll")                                                            \
        for (int j = 0; j < 3; j++) {                                                \
            MMA16816(acc[0][j], ah, wh[j][0], wh[j][1]);                             \
            MMA16816(acc[0][j], ah, wl[j][0], wl[j][1]);                             \
            MMA16816(acc[0][j], al, wh[j][0], wh[j][1]);                             \
            MMA16816(acc[1][j], ah2, wh[j][0], wh[j][1]);                            \
            MMA16816(acc[1][j], ah2, wl[j][0], wl[j][1]);                            \
            MMA16816(acc[1][j], al2, wh[j][0], wh[j][1]);                            \
        }                                                                            \
    }

// ---------------- conv: implicit GEMM, HMMA + ldmatrix, cp.async x2 -----------------
__global__ void __launch_bounds__(256, 2) conv_hmma_kernel(
    const __nv_bfloat16* __restrict__ xh, const __nv_bfloat16* __restrict__ xl,
    const uint4* __restrict__ wp, const float* __restrict__ bias,
    float* __restrict__ out, int k, int side, int m)
{
    extern __shared__ uint32_t dsm[];

    int tid = threadIdx.x;
    int lane = tid & 31, wid = tid >> 5;
    int wm = wid & 1, wn = wid >> 1;
    long long Bm = (long long)NB * m;

    int arow = tid >> 2, aq = tid & 3;
    long long apx = (long long)blockIdx.x * 64 + arow;
    long long apxc = apx < Bm - 1 ? apx : Bm - 1;
    int ab = (int)(apxc / m), app = (int)(apxc % m);
    int aoy = app / side, aox = app % side;
    size_t axbase = (size_t)ab * NTOK * NC;
    int half = blockIdx.y;
    int rA = lane >> 2, cA = lane & 3;

    uint32_t smbase = smem_u32(dsm);
    uint32_t awd = smbase + (uint32_t)(arow * 36 + aq * 8) * 4;
    uint32_t bwd = smbase + 4608u * 4;

    // ldmatrix per-lane addresses (byte offsets from smbase)
    int lrow = lane & 15, lcol = lane >> 4;
    uint32_t aoff0 = smbase + (uint32_t)((wm * 32 + lrow) * 144 + lcol * 16);
    uint32_t aoff1 = aoff0 + 16 * 144;
    int brow = (lane & 7) + ((lane & 16) ? 8 : 0);
    int bcolb = ((lane >> 3) & 1) * 16;
    uint32_t boff01 = smbase + 4608u * 4 + (uint32_t)((wn * 24 + brow) * 144 + bcolb);
    uint32_t boff2  = smbase + 4608u * 4 + (uint32_t)((wn * 24 + 16 + (lane & 7)) * 144
                                                      + bcolb);

    float acc[2][3][4];
#pragma unroll
    for (int i = 0; i < 2; i++)
#pragma unroll
        for (int j = 0; j < 3; j++)
#pragma unroll
            for (int q = 0; q < 4; q++) acc[i][j][q] = 0.f;

    int k2 = k * k;
    int ng = k2 * 3;

#define CONV_ISSUE(g, s) do {                                                        \
        int _tap = (g) / 3, _cb = (g) - _tap * 3;                                    \
        int _dy = _tap / k, _dx = _tap - _dy * k;                                    \
        size_t _aoff = axbase + (size_t)((aoy + _dy) * 64 + aox + _dx) * NC          \
                     + _cb * 64 + aq * 16;                                           \
        uint32_t _soff = (uint32_t)(s) * (CSTGW * 4);                                \
        const char* _gh = (const char*)(xh + _aoff);                                 \
        const char* _gl = (const char*)(xl + _aoff);                                 \
        CPA16(awd + _soff,      _gh);                                                \
        CPA16(awd + _soff + 16, _gh + 16);                                           \
        CPA16(awd + _soff + 2304u * 4,      _gl);                                    \
        CPA16(awd + _soff + 2304u * 4 + 16, _gl + 16);                               \
        int _imgb = (_tap * 3 + _cb) * 4 + half * 2;                                 \
        const char* _gb = (const char*)(wp + (size_t)_imgb * (BIMG / 4));            \
        _Pragma("unroll")                                                            \
        for (int _i = 0; _i < 7; _i++) {                                             \
            int _idx = tid + _i * 256;                                               \
            if (_idx < 1728) CPA16(bwd + _soff + _idx * 16, _gb + (size_t)_idx * 16);\
        }                                                                            \
    } while (0)

    CONV_ISSUE(0, 0);
    CPA_COMMIT();

    for (int g = 0; g < ng; g++) {
        if (g + 1 < ng) CONV_ISSUE(g + 1, (g + 1) & 1);
        CPA_COMMIT();
        CPA_WAIT1();
        __syncthreads();

        uint32_t soff = (uint32_t)(g & 1) * (CSTGW * 4);
        HMMA_GROUP_COMPUTE(soff);
        __syncthreads();
    }
#undef CONV_ISSUE

#pragma unroll
    for (int i = 0; i < 2; i++) {
        long long row0 = (long long)blockIdx.x * 64 + wm * 32 + i * 16 + rA;
#pragma unroll
        for (int j = 0; j < 3; j++) {
            int col = half * 96 + wn * 24 + j * 8 + 2 * cA;
            float b0 = bias[col], b1 = bias[col + 1];
            if (row0 < Bm) {
                float2 v = make_float2(acc[i][j][0] + b0, acc[i][j][1] + b1);
                *(float2*)&out[row0 * NC + col] = v;
            }
            if (row0 + 8 < Bm) {
                float2 v = make_float2(acc[i][j][2] + b0, acc[i][j][3] + b1);
                *(float2*)&out[(row0 + 8) * NC + col] = v;
            }
        }
    }
}

// ---------------- projection GEMM on HMMA + ldmatrix --------------------------------
__global__ void __launch_bounds__(256, 2) gemm_hmma_kernel(
    const __nv_bfloat16* __restrict__ Ah_g, const __nv_bfloat16* __restrict__ Al_g,
    const uint4* __restrict__ wimg, const float* __restrict__ bias,
    float* __restrict__ out, long long rows, int ldout, int Nout)
{
    extern __shared__ uint32_t dsm[];

    int tid = threadIdx.x;
    int lane = tid & 31, wid = tid >> 5;
    int wm = wid & 1, wn = wid >> 1;

    int arow = tid >> 2, aq = tid & 3;
    long long r = (long long)blockIdx.x * 64 + arow;
    long long rc = r < rows - 1 ? r : rows - 1;
    int half = blockIdx.y;
    int rA = lane >> 2, cA = lane & 3;

    uint32_t smbase = smem_u32(dsm);
    uint32_t awd = smbase + (uint32_t)(arow * 36 + aq * 8) * 4;
    uint32_t bwd = smbase + 4608u * 4;

    int lrow = lane & 15, lcol = lane >> 4;
    uint32_t aoff0 = smbase + (uint32_t)((wm * 32 + lrow) * 144 + lcol * 16);
    uint32_t aoff1 = aoff0 + 16 * 144;
    int brow = (lane & 7) + ((lane & 16) ? 8 : 0);
    int bcolb = ((lane >> 3) & 1) * 16;
    uint32_t boff01 = smbase + 4608u * 4 + (uint32_t)((wn * 24 + brow) * 144 + bcolb);
    uint32_t boff2  = smbase + 4608u * 4 + (uint32_t)((wn * 24 + 16 + (lane & 7)) * 144
                                                      + bcolb);

    float acc[2][3][4];
#pragma unroll
    for (int i = 0; i < 2; i++)
#pragma unroll
        for (int j = 0; j < 3; j++)
#pragma unroll
            for (int q = 0; q < 4; q++) acc[i][j][q] = 0.f;

#define PROJ_ISSUE(g, s) do {                                                        \
        size_t _aoff = (size_t)rc * NC + (g) * 64 + aq * 16;                         \
        uint32_t _soff = (uint32_t)(s) * (CSTGW * 4);                                \
        const char* _gh = (const char*)(Ah_g + _aoff);                               \
        const char* _gl = (const char*)(Al_g + _aoff);                               \
        CPA16(awd + _soff,      _gh);                                                \
        CPA16(awd + _soff + 16, _gh + 16);                                           \
        CPA16(awd + _soff + 2304u * 4,      _gl);                                    \
        CPA16(awd + _soff + 2304u * 4 + 16, _gl + 16);                               \
        int _imgb = (g) * 4 + half * 2;                                              \
        const char* _gb = (const char*)(wimg + (size_t)_imgb * (BIMG / 4));          \
        _Pragma("unroll")                                                            \
        for (int _i = 0; _i < 7; _i++) {                                             \
            int _idx = tid + _i * 256;                                               \
            if (_idx < 1728) CPA16(bwd + _soff + _idx * 16, _gb + (size_t)_idx * 16);\
        }                                                                            \
    } while (0)

    PROJ_ISSUE(0, 0);
    CPA_COMMIT();

    for (int g = 0; g < 3; g++) {
        if (g + 1 < 3) PROJ_ISSUE(g + 1, (g + 1) & 1);
        CPA_COMMIT();
        CPA_WAIT1();
        __syncthreads();

        uint32_t soff = (uint32_t)(g & 1) * (CSTGW * 4);
        HMMA_GROUP_COMPUTE(soff);
        __syncthreads();
    }
#undef PROJ_ISSUE

#pragma unroll
    for (int i = 0; i < 2; i++) {
        long long row0 = (long long)blockIdx.x * 64 + wm * 32 + i * 16 + rA;
#pragma unroll
        for (int j = 0; j < 3; j++) {
            int col = half * 96 + wn * 24 + j * 8 + 2 * cA;
            if (col >= Nout) continue;
            float b0 = bias[col], b1 = bias[col + 1];
            if (row0 < rows) {
                float2 v = make_float2(acc[i][j][0] + b0, acc[i][j][1] + b1);
                *(float2*)&out[row0 * ldout + col] = v;
            }
            if (row0 + 8 < rows) {
                float2 v = make_float2(acc[i][j][2] + b0, acc[i][j][3] + b1);
                *(float2*)&out[(row0 + 8) * ldout + col] = v;
            }
        }
    }
}

// ---------------- prep q split ------------------------------------------------------
__global__ void prep_q_kernel(const float* __restrict__ q, __nv_bfloat16* __restrict__ qh,
                              __nv_bfloat16* __restrict__ ql, int h) {
    int i = blockIdx.x * 256 + threadIdx.x;
    if (i >= NB * NTOK * 64) return;
    int c = i & 63;
    int row = i >> 6;
    float f = q[(size_t)row * NC + h * 64 + c];
    __nv_bfloat16 hi = __float2bfloat16(f);
    qh[i] = hi;
    ql[i] = __float2bfloat16(f - __bfloat162float(hi));
}

// ---------------- pack k + v' into per-chunk MMA image blocks ------------------------
__global__ void pack_kv_kernel(const float* __restrict__ kv, const float* __restrict__ vp,
                               uint32_t* __restrict__ img, int m, int nchunk) {
    int idx = blockIdx.x * 256 + threadIdx.x;
    int total = NB * nchunk * FSTGW;
    if (idx >= total) return;
    int b = idx / (nchunk * FSTGW);
    int rem = idx % (nchunk * FSTGW);
    int c = rem / FSTGW;
    int r2 = rem % FSTGW;
    int sect = r2 / 2304;
    int r3 = r2 % 2304;
    int c2 = r3 / 72, n = r3 % 72;
    if (n >= 64) { img[idx] = 0u; return; }
    float f0, f1;
    if (sect < 2) {
        int mi = c * 64 + n;
        if (mi < m) {
            const float* kr = kv + ((size_t)b * m + mi) * 128;
            f0 = kr[2 * c2];
            f1 = kr[2 * c2 + 1];
        } else { f0 = f1 = 0.f; }
    } else {
        int k0 = c * 64 + 2 * c2;
        f0 = (k0 < m) ? vp[((size_t)b * m + k0) * 64 + n] : 0.f;
        f1 = (k0 + 1 < m) ? vp[((size_t)b * m + k0 + 1) * 64 + n] : 0.f;
    }
    uint32_t hi, lo;
    split2(f0, f1, hi, lo);
    img[idx] = (sect & 1) ? lo : hi;
}

// ---------------- fused flash attention (unchanged from R12) -------------------------
__global__ void __launch_bounds__(256) attn_flash_kernel(
    const __nv_bfloat16* __restrict__ qh, const __nv_bfloat16* __restrict__ ql,
    const uint32_t* __restrict__ kvimg,
    uint32_t* __restrict__ xch, uint32_t* __restrict__ xcl,
    int hoff, int m, int nchunk)
{
    extern __shared__ uint32_t fsm[];
    uint32_t* sQh = fsm;
    uint32_t* sQl = fsm + 4608;

    int tid = threadIdx.x, lane = tid & 31, w = tid >> 5;
    int rA = lane >> 2, cA = lane & 3;
    int b = blockIdx.y;
    int q0 = blockIdx.x * 128;

    uint32_t stg_b = smem_u32(fsm) + 9216u * 4;

    {
        int arow = tid >> 1, ahalf = tid & 1;
        size_t off = ((size_t)b * NTOK + q0 + arow) * 64 + ahalf * 32;
        const uint4* sh = (const uint4*)(qh + off);
        const uint4* sl = (const uint4*)(ql + off);
        uint32_t* dh = sQh + arow * 36 + ahalf * 16;
        uint32_t* dl = sQl + arow * 36 + ahalf * 16;
#pragma unroll
        for (int j = 0; j < 4; j++) { *(uint4*)&dh[j * 4] = sh[j]; *(uint4*)&dl[j * 4] = sl[j]; }
    }

#define FL_ISSUE(c, s) do {                                                          \
        const char* _src = (const char*)(kvimg + ((size_t)b * nchunk + (c)) * FSTGW);\
        uint32_t _dst = stg_b + (uint32_t)(s) * (FSTGW * 4);                         \
        _Pragma("unroll")                                                            \
        for (int _t = 0; _t < 9; _t++) {                                             \
            int _idx = tid + _t * 256;                                               \
            CPA16(_dst + _idx * 16, _src + (size_t)_idx * 16);                       \
        }                                                                            \
    } while (0)

    float acc_o[8][4];
#pragma unroll
    for (int nn = 0; nn < 8; nn++)
#pragma unroll
        for (int q = 0; q < 4; q++) acc_o[nn][q] = 0.f;
    float mrun0 = -1e30f, mrun1 = -1e30f, l0 = 0.f, l1 = 0.f;

    FL_ISSUE(0, 0);
    CPA_COMMIT();

    for (int c = 0; c < nchunk; c++) {
        if (c + 1 < nchunk) FL_ISSUE(c + 1, (c + 1) & 1);
        CPA_COMMIT();
        CPA_WAIT1();
        __syncthreads();

        const uint32_t* stg = fsm + 9216 + (c & 1) * FSTGW;
        const uint32_t* sKh = stg;
        const uint32_t* sKl = stg + 2304;
        const uint32_t* sVh = stg + 4608;
        const uint32_t* sVl = stg + 6912;

        float s[8][4];
#pragma unroll
        for (int j = 0; j < 8; j++)
#pragma unroll
            for (int q = 0; q < 4; q++) s[j][q] = 0.f;

#pragma unroll
        for (int ks = 0; ks < 4; ks++) {
            uint32_t ah[4], al[4];
            int r = w * 16 + rA;
            int cc = 8 * ks + cA;
            ah[0] = sQh[r * 36 + cc];
            ah[1] = sQh[(r + 8) * 36 + cc];
            ah[2] = sQh[r * 36 + cc + 4];
            ah[3] = sQh[(r + 8) * 36 + cc + 4];
            al[0] = sQl[r * 36 + cc];
            al[1] = sQl[(r + 8) * 36 + cc];
            al[2] = sQl[r * 36 + cc + 4];
            al[3] = sQl[(r + 8) * 36 + cc + 4];
#pragma unroll
            for (int j = 0; j < 8; j++) {
                int n = j * 8 + rA;
                uint32_t bh0 = sKh[(8 * ks + cA) * 72 + n];
                uint32_t bh1 = sKh[(8 * ks + 4 + cA) * 72 + n];
                uint32_t bl0 = sKl[(8 * ks + cA) * 72 + n];
                uint32_t bl1 = sKl[(8 * ks + 4 + cA) * 72 + n];
                MMA16816(s[j], ah, bh0, bh1);
                MMA16816(s[j], ah, bl0, bl1);
                MMA16816(s[j], al, bh0, bh1);
            }
        }

        int cbase = c * 64;
        bool lastc = (cbase + 64 > m);
#pragma unroll
        for (int j = 0; j < 8; j++)
#pragma unroll
            for (int q = 0; q < 4; q++) {
                float v = s[j][q] * ATT_SCALE;
                if (lastc && (cbase + j * 8 + 2 * cA + (q & 1)) >= m) v = -1e30f;
                s[j][q] = v;
            }

        float mx0 = -1e30f, mx1 = -1e30f;
#pragma unroll
        for (int j = 0; j < 8; j++) {
            mx0 = fmaxf(mx0, fmaxf(s[j][0], s[j][1]));
            mx1 = fmaxf(mx1, fmaxf(s[j][2], s[j][3]));
        }
        mx0 = fmaxf(mx0, __shfl_xor_sync(0xffffffffu, mx0, 1));
        mx0 = fmaxf(mx0, __shfl_xor_sync(0xffffffffu, mx0, 2));
        mx1 = fmaxf(mx1, __shfl_xor_sync(0xffffffffu, mx1, 1));
        mx1 = fmaxf(mx1, __shfl_xor_sync(0xffffffffu, mx1, 2));
        float mn0 = fmaxf(mrun0, mx0), mn1 = fmaxf(mrun1, mx1);
        float sc0 = __expf(mrun0 - mn0), sc1 = __expf(mrun1 - mn1);
        mrun0 = mn0; mrun1 = mn1;

        float sum0 = 0.f, sum1 = 0.f;
#pragma unroll
        for (int j = 0; j < 8; j++) {
            s[j][0] = __expf(s[j][0] - mn0);
            s[j][1] = __expf(s[j][1] - mn0);
            s[j][2] = __expf(s[j][2] - mn1);
            s[j][3] = __expf(s[j][3] - mn1);
            sum0 += s[j][0] + s[j][1];
            sum1 += s[j][2] + s[j][3];
        }
        sum0 += __shfl_xor_sync(0xffffffffu, sum0, 1);
        sum0 += __shfl_xor_sync(0xffffffffu, sum0, 2);
        sum1 += __shfl_xor_sync(0xffffffffu, sum1, 1);
        sum1 += __shfl_xor_sync(0xffffffffu, sum1, 2);
        l0 = l0 * sc0 + sum0;
        l1 = l1 * sc1 + sum1;

#pragma unroll
        for (int nn = 0; nn < 8; nn++) {
            acc_o[nn][0] *= sc0; acc_o[nn][1] *= sc0;
            acc_o[nn][2] *= sc1; acc_o[nn][3] *= sc1;
        }

        uint32_t aph[4][4], apl[4][4];
#pragma unroll
        for (int kk = 0; kk < 4; kk++) {
            split2(s[2 * kk][0],     s[2 * kk][1],     aph[kk][0], apl[kk][0]);
            split2(s[2 * kk][2],     s[2 * kk][3],     aph[kk][1], apl[kk][1]);
            split2(s[2 * kk + 1][0], s[2 * kk + 1][1], aph[kk][2], apl[kk][2]);
            split2(s[2 * kk + 1][2], s[2 * kk + 1][3], aph[kk][3], apl[kk][3]);
        }

#pragma unroll
        for (int kk = 0; kk < 4; kk++) {
#pragma unroll
            for (int nn = 0; nn < 8; nn++) {
                int n = nn * 8 + rA;
                uint32_t vh0 = sVh[(8 * kk + cA) * 72 + n];
                uint32_t vh1 = sVh[(8 * kk + 4 + cA) * 72 + n];
                uint32_t vl0 = sVl[(8 * kk + cA) * 72 + n];
                uint32_t vl1 = sVl[(8 * kk + 4 + cA) * 72 + n];
                MMA16816(acc_o[nn], aph[kk], vh0, vh1);
                MMA16816(acc_o[nn], aph[kk], vl0, vl1);
                MMA16816(acc_o[nn], apl[kk], vh0, vh1);
            }
        }
        __syncthreads();
    }
#undef FL_ISSUE

    float inv0 = 1.f / l0, inv1 = 1.f / l1;
    size_t row0 = (size_t)b * NTOK + q0 + w * 16 + rA;
#pragma unroll
    for (int nn = 0; nn < 8; nn++) {
        int col = nn * 8 + 2 * cA;
        size_t w0 = row0 * 96 + (size_t)((hoff + col) >> 1);
        size_t w1 = (row0 + 8) * 96 + (size_t)((hoff + col) >> 1);
        uint32_t hi, lo;
        split2(acc_o[nn][0] * inv0, acc_o[nn][1] * inv0, hi, lo);
        xch[w0] = hi; xcl[w0] = lo;
        split2(acc_o[nn][2] * inv1, acc_o[nn][3] * inv1, hi, lo);
        xch[w1] = hi; xcl[w1] = lo;
    }
}

// ---------------- LayerNorm + exact GELU -> split bf16 -------------------------------
__device__ __forceinline__ float warpSum(float v) {
#pragma unroll
    for (int o = 16; o; o >>= 1) v += __shfl_xor_sync(0xffffffffu, v, o);
    return v;
}
__global__ void ln_gelu_kernel(const float* __restrict__ t, const float* __restrict__ g,
                               const float* __restrict__ bb,
                               __nv_bfloat16* __restrict__ th, __nv_bfloat16* __restrict__ tl) {
    size_t row = blockIdx.x;
    int tid = threadIdx.x;
    float v = t[row * NC + tid];
    __shared__ float sm[6];
    int lane = tid & 31, w = tid >> 5;
    float s = warpSum(v);
    if (lane == 0) sm[w] = s;
    __syncthreads();
    float mean = 0.f;
#pragma unroll
    for (int i = 0; i < 6; i++) mean += sm[i];
    mean *= (1.0f / 192.0f);
    float d = v - mean;
    __syncthreads();
    s = warpSum(d * d);
    if (lane == 0) sm[w] = s;
    __syncthreads();
    float var = 0.f;
#pragma unroll
    for (int i = 0; i < 6; i++) var += sm[i];
    var *= (1.0f / 192.0f);
    float y = d * rsqrtf(var + 1e-5f) * g[tid] + bb[tid];
    float r = y * normcdff(y);
    __nv_bfloat16 hi = __float2bfloat16(r);
    th[row * NC + tid] = hi;
    tl[row * NC + tid] = __float2bfloat16(r - __bfloat162float(hi));
}

// ---------------- depthwise 3x3 on v, residual add -----------------------------------
__global__ void dwconv_kernel(const float* __restrict__ kv, const float* __restrict__ lw,
                              const float* __restrict__ lb, float* __restrict__ vp,
                              int side, int m)
{
    long long idx = (long long)blockIdx.x * 256 + threadIdx.x;
    long long total = (long long)NB * m * 64;
    if (idx >= total) return;
    int hd = (int)(idx & 63);
    long long pm = idx >> 6;
    int p = (int)(pm % m);
    int b = (int)(pm / m);
    int y = p / side, x = p % side;
    const float* vbase = kv + (size_t)b * m * 128 + 64 + hd;
    float s = lb[hd];
#pragma unroll
    for (int dy = 0; dy < 3; dy++) {
        int yy = y + dy - 1;
        if (yy < 0 || yy >= side) continue;
#pragma unroll
        for (int dx = 0; dx < 3; dx++) {
            int xx = x + dx - 1;
            if (xx < 0 || xx >= side) continue;
            s += lw[hd * 9 + dy * 3 + dx] * vbase[(size_t)(yy * side + xx) * 128];
        }
    }
    vp[idx] = vbase[(size_t)p * 128] + s;
}

// ---------------- host orchestration ---------------------------------------------------
extern "C" void kernel_launch(void* const* d_in, const int* in_sizes, int n_in,
                              void* d_out, int out_size)
{
    (void)in_sizes; (void)n_in; (void)out_size;
    const float* x    = (const float*)d_in[0];
    const float* q_w  = (const float*)d_in[1];
    const float* q_b  = (const float*)d_in[2];
    const float* kv_w = (const float*)d_in[3];
    const float* kv_b = (const float*)d_in[4];
    const float* sr_w[3] = {(const float*)d_in[5], (const float*)d_in[7], (const float*)d_in[9]};
    const float* sr_b[3] = {(const float*)d_in[6], (const float*)d_in[8], (const float*)d_in[10]};
    const float* ln_g[3] = {(const float*)d_in[11], (const float*)d_in[13], (const float*)d_in[15]};
    const float* ln_b[3] = {(const float*)d_in[12], (const float*)d_in[14], (const float*)d_in[16]};
    const float* lc_w[3] = {(const float*)d_in[17], (const float*)d_in[19], (const float*)d_in[21]};
    const float* lc_b[3] = {(const float*)d_in[18], (const float*)d_in[20], (const float*)d_in[22]};
    const float* nn1_w = (const float*)d_in[23];
    const float* nn1_b = (const float*)d_in[24];
    float* out = (float*)d_out;

    float *p_q, *p_t, *p_kv, *p_vp;
    __nv_bfloat16 *p_xh, *p_xl, *p_th, *p_tl, *p_qh, *p_ql;
    uint32_t *p_wp, *p_wq, *p_wkv, *p_wnn, *p_kvimg, *p_xch, *p_xcl;
    cudaGetSymbolAddress((void**)&p_q,    g_q);
    cudaGetSymbolAddress((void**)&p_t,    g_t);
    cudaGetSymbolAddress((void**)&p_kv,   g_kv);
    cudaGetSymbolAddress((void**)&p_vp,   g_vp);
    cudaGetSymbolAddress((void**)&p_xh,   g_xh);
    cudaGetSymbolAddress((void**)&p_xl,   g_xl);
    cudaGetSymbolAddress((void**)&p_th,   g_th);
    cudaGetSymbolAddress((void**)&p_tl,   g_tl);
    cudaGetSymbolAddress((void**)&p_wp,   g_wpack);
    cudaGetSymbolAddress((void**)&p_wq,   g_wq);
    cudaGetSymbolAddress((void**)&p_wkv,  g_wkv);
    cudaGetSymbolAddress((void**)&p_wnn,  g_wnn);
    cudaGetSymbolAddress((void**)&p_qh,   g_qh);
    cudaGetSymbolAddress((void**)&p_ql,   g_ql);
    cudaGetSymbolAddress((void**)&p_kvimg, g_kvimg);
    cudaGetSymbolAddress((void**)&p_xch,  g_xch);
    cudaGetSymbolAddress((void**)&p_xcl,  g_xcl);

    cudaFuncSetAttribute(conv_hmma_kernel, cudaFuncAttributeMaxDynamicSharedMemorySize,
                         2 * CSTGW * 4);
    cudaFuncSetAttribute(gemm_hmma_kernel, cudaFuncAttributeMaxDynamicSharedMemorySize,
                         2 * CSTGW * 4);
    cudaFuncSetAttribute(attn_flash_kernel, cudaFuncAttributeMaxDynamicSharedMemorySize,
                         (9216 + 2 * FSTGW) * 4);

    const int WPROJ = 12 * BIMG;

    prep_x_kernel<<<(NB * NTOK * NC + 255) / 256, 256>>>(x, p_xh, p_xl);
    prep_w_kernel<<<(WPROJ + 255) / 256, 256>>>(q_w, p_wq, 1);
    prep_w_kernel<<<(WPROJ + 255) / 256, 256>>>(kv_w, p_wkv, 1);
    prep_w_kernel<<<(WPROJ + 255) / 256, 256>>>(nn1_w, p_wnn, 1);

    gemm_hmma_kernel<<<dim3((NB * NTOK + 63) / 64, 2), 256, 2 * CSTGW * 4>>>(
        p_xh, p_xl, (const uint4*)p_wq, q_b, p_q, (long long)NB * NTOK, NC, NC);

    const int KS[3] = {8, 4, 2};
    for (int h = 0; h < 3; h++) {
        int k = KS[h];
        int side = 64 - k + 1;
        int m = side * side;
        int k2 = k * k;
        int nchunk = (m + 63) / 64;
        long long Bm = (long long)NB * m;

        prep_w_kernel<<<(k2 * WPROJ + 255) / 256, 256>>>(sr_w[h], p_wp, k2);
        conv_hmma_kernel<<<dim3((int)((Bm + 63) / 64), 2), 256, 2 * CSTGW * 4>>>(
            p_xh, p_xl, (const uint4*)p_wp, sr_b[h], p_t, k, side, m);
        ln_gelu_kernel<<<NB * m, 192>>>(p_t, ln_g[h], ln_b[h], p_th, p_tl);

        gemm_hmma_kernel<<<dim3((int)((Bm + 63) / 64), 2), 256, 2 * CSTGW * 4>>>(
            p_th, p_tl, (const uint4*)p_wkv, kv_b, p_kv, Bm, 128, 128);

        prep_q_kernel<<<(NB * NTOK * 64 + 255) / 256, 256>>>(p_q, p_qh, p_ql, h);

        dwconv_kernel<<<(int)(((long long)NB * m * 64 + 255) / 256), 256>>>(
            p_kv, lc_w[h], lc_b[h], p_vp, side, m);
        pack_kv_kernel<<<(NB * nchunk * FSTGW + 255) / 256, 256>>>(
            p_kv, p_vp, p_kvimg, m, nchunk);

        attn_flash_kernel<<<dim3(NTOK / 128, NB), 256, (9216 + 2 * FSTGW) * 4>>>(
            p_qh, p_ql, p_kvimg, p_xch, p_xcl, h * 64, m, nchunk);
    }

    gemm_hmma_kernel<<<dim3((NB * NTOK + 63) / 64, 2), 256, 2 * CSTGW * 4>>>(
        (const __nv_bfloat16*)p_xch, (const __nv_bfloat16*)p_xcl,
        (const uint4*)p_wnn, nn1_b, out, (long long)NB * NTOK, NC, NC);
}